// round 9
// baseline (speedup 1.0000x reference)
#include <cuda_runtime.h>
#include <cuda_fp16.h>
#include <cstdint>

#define HID 1024
#define HEADS 16
#define HD 64
#define BATCH 8
#define SEQ 1024
#define MROWS (BATCH * SEQ)

// ---------------- scratch (device globals; no allocation allowed) ----------
__device__ __half g_Qh[MROWS * HID];
__device__ __half g_Ql[MROWS * HID];
__device__ __half g_Kh[MROWS * HID];
__device__ __half g_Vh[MROWS * HID];
__device__ __half g_Ahi[MROWS * HID];
__device__ __half g_Alo[MROWS * HID];
__device__ __half g_Wqh[HID * HID];
__device__ __half g_Wkh[HID * HID];
__device__ __half g_Wvh[HID * HID];
__device__ __half g_Woh[HID * HID];
__device__ float g_invf[HID / 2];
__device__ float4 g_tab[SEQ * (HID / 2)];

// ---------------- helpers ----------------------------------------
__device__ __forceinline__ uint32_t smem_u32(const void* p) {
    uint32_t a;
    asm("{ .reg .u64 t; cvta.to.shared.u64 t, %1; cvt.u32.u64 %0, t; }"
        : "=r"(a) : "l"(p));
    return a;
}
__device__ __forceinline__ void cp16(uint32_t dst, const void* src) {
    asm volatile("cp.async.cg.shared.global [%0], [%1], 16;" :: "r"(dst), "l"(src));
}
#define CP_COMMIT() asm volatile("cp.async.commit_group;" ::: "memory")
#define CP_WAIT1()  asm volatile("cp.async.wait_group 1;" ::: "memory")

__device__ __forceinline__ void ldm4(uint32_t* r, uint32_t addr) {
    asm volatile("ldmatrix.sync.aligned.m8n8.x4.shared.b16 {%0,%1,%2,%3}, [%4];"
                 : "=r"(r[0]), "=r"(r[1]), "=r"(r[2]), "=r"(r[3]) : "r"(addr));
}
__device__ __forceinline__ void ldm4t(uint32_t* r, uint32_t addr) {
    asm volatile("ldmatrix.sync.aligned.m8n8.x4.trans.shared.b16 {%0,%1,%2,%3}, [%4];"
                 : "=r"(r[0]), "=r"(r[1]), "=r"(r[2]), "=r"(r[3]) : "r"(addr));
}
__device__ __forceinline__ void mma16816(float* d, const uint32_t* a,
                                         uint32_t b0, uint32_t b1) {
    asm volatile(
        "mma.sync.aligned.m16n8k16.row.col.f32.f16.f16.f32 "
        "{%0,%1,%2,%3}, {%4,%5,%6,%7}, {%8,%9}, {%0,%1,%2,%3};"
        : "+f"(d[0]), "+f"(d[1]), "+f"(d[2]), "+f"(d[3])
        : "r"(a[0]), "r"(a[1]), "r"(a[2]), "r"(a[3]), "r"(b0), "r"(b1));
}
// fp16 split: pair of floats -> half2 hi + half2 lo (packed u32)
__device__ __forceinline__ void split2h(float x, float y, uint32_t& hi, uint32_t& lo) {
    __half2 h = __floats2half2_rn(x, y);
    float2 f = __half22float2(h);
    __half2 l2 = __floats2half2_rn(x - f.x, y - f.y);
    hi = *reinterpret_cast<uint32_t*>(&h);
    lo = *reinterpret_cast<uint32_t*>(&l2);
}
// 8 fp32 -> uint4 of 8 rn-rounded fp16 (no residual)
__device__ __forceinline__ uint4 cvt8h(const float4& u, const float4& v) {
    __half2 h0 = __floats2half2_rn(u.x, u.y);
    __half2 h1 = __floats2half2_rn(u.z, u.w);
    __half2 h2 = __floats2half2_rn(v.x, v.y);
    __half2 h3 = __floats2half2_rn(v.z, v.w);
    return make_uint4(*(uint32_t*)&h0, *(uint32_t*)&h1, *(uint32_t*)&h2, *(uint32_t*)&h3);
}
// permutation: n' = 128p + 64s + i  ->  orig = 64p + 512s + i
__device__ __forceinline__ int perm_orig(int n) {
    int p = n >> 7, s = (n >> 6) & 1, i = n & 63;
    return 64 * p + 512 * s + i;
}

// ============================================================================
// weight prep: single fp16 (rn-rounded), row-permuted / col-permuted
// ============================================================================
__global__ __launch_bounds__(256) void prep_w_rowperm(
    const float* __restrict__ W, __half* __restrict__ Wh)
{
    int idx = blockIdx.x * 256 + threadIdx.x;   // HID*HID/8
    int n = idx >> 7;
    int c8 = (idx & 127) * 8;
    int orig = perm_orig(n);
    float4 u = *(const float4*)(W + (size_t)orig * HID + c8);
    float4 v = *(const float4*)(W + (size_t)orig * HID + c8 + 4);
    *(uint4*)(Wh + (size_t)n * HID + c8) = cvt8h(u, v);
}

__global__ __launch_bounds__(256) void prep_w_colperm(
    const float* __restrict__ W, __half* __restrict__ Wh)
{
    int idx = blockIdx.x * 256 + threadIdx.x;
    int n = idx >> 7;
    int k8 = (idx & 127) * 8;
    int orig = perm_orig(k8);
    float4 u = *(const float4*)(W + (size_t)n * HID + orig);
    float4 v = *(const float4*)(W + (size_t)n * HID + orig + 4);
    *(uint4*)(Wh + (size_t)n * HID + k8) = cvt8h(u, v);
}

__global__ void make_invf_kernel() {
    int j = threadIdx.x;
    if (j < HID / 2) {
        double e = exp(-((double)(2 * j) / (double)HID) * log(10000.0));
        g_invf[j] = (float)e;
    }
}
__global__ __launch_bounds__(256) void rope_table_kernel() {
    int idx = blockIdx.x * 256 + threadIdx.x;
    int s = idx >> 9;
    int j = idx & 511;
    float t = (float)s * g_invf[j];
    float st, ct;
    sincosf(t, &st, &ct);
    float s1, c1, s2, c2;
    sincosf(st, &s1, &c1);
    sincosf(ct, &s2, &c2);
    g_tab[idx] = make_float4(c1, s1, c2, s2);
}

// ============================================================================
// fused QKV projection, 1-term pure fp16: Y = X*W'^T (+bias +RoPE +scale).
// A = fp32 converted inline to single fp16; B = single fp16 weights.
// CTA 128x128, warp 64x32, K-chunk 32, 2-stage double buffer.
// ============================================================================
#define RSTRIDE 80
#define TILE_B (128 * RSTRIDE)      // 10240
#define STAGE1 (2 * TILE_B)         // 20480 (A, B) for 1-term proj
#define STAGE2 (3 * TILE_B)         // 30720 (Ah, Al, B) for 2-term out
#define GEMM_SMEM 67584             // epilogue fp32 tile 128x132
#define SROW 132

template <bool WANT_LO>
__global__ __launch_bounds__(256, 2)
void gemm_qkv(const float* __restrict__ X, const __half* __restrict__ Bw,
              const float* __restrict__ bias,
              __half* __restrict__ outh, __half* __restrict__ outl, float scale)
{
    extern __shared__ __align__(128) char smem[];

    const int tid  = threadIdx.x;
    const int wid  = tid >> 5;
    const int lane = tid & 31;
    const int wm   = wid & 1;
    const int wn   = wid >> 1;
    const int brow = blockIdx.y * 128;
    const int bcol = blockIdx.x * 128;

    const uint32_t sbase = smem_u32(smem);
    const uint32_t aoff = (uint32_t)(((lane & 7) + ((lane >> 3) & 1) * 8) * RSTRIDE
                                     + ((lane >> 4) & 1) * 16);
    const uint32_t boff = (uint32_t)(((lane & 7) + ((lane >> 4) & 1) * 8) * RSTRIDE
                                     + ((lane >> 3) & 1) * 16);

    const int r0i = tid >> 2;          // rows r0i, r0i+64
    const int ch  = tid & 3;

    const float* Xp = X + (size_t)brow * HID;
    const __half* Bp = Bw + (size_t)bcol * HID;

    float acc[4][4][4];
#pragma unroll
    for (int i = 0; i < 4; i++)
#pragma unroll
        for (int j = 0; j < 4; j++)
#pragma unroll
            for (int r = 0; r < 4; r++) acc[i][j][r] = 0.0f;

    // prologue: chunk 0 -> stage 0
    {
        const size_t ke = (size_t)ch * 8;
        float4 a0 = *(const float4*)(Xp + (size_t)r0i * HID + ke);
        float4 a1 = *(const float4*)(Xp + (size_t)r0i * HID + ke + 4);
        float4 a2 = *(const float4*)(Xp + (size_t)(r0i + 64) * HID + ke);
        float4 a3 = *(const float4*)(Xp + (size_t)(r0i + 64) * HID + ke + 4);
        uint4 b0 = *(const uint4*)(Bp + (size_t)r0i * HID + ke);
        uint4 b1 = *(const uint4*)(Bp + (size_t)(r0i + 64) * HID + ke);
        *(uint4*)(smem + 0 * TILE_B + r0i * RSTRIDE + ch * 16)        = cvt8h(a0, a1);
        *(uint4*)(smem + 0 * TILE_B + (r0i + 64) * RSTRIDE + ch * 16) = cvt8h(a2, a3);
        *(uint4*)(smem + 1 * TILE_B + r0i * RSTRIDE + ch * 16)        = b0;
        *(uint4*)(smem + 1 * TILE_B + (r0i + 64) * RSTRIDE + ch * 16) = b1;
    }
    __syncthreads();

    for (int kc = 0; kc < 32; kc++) {
        const int s = kc & 1;
        const bool has = (kc + 1) < 32;

        float4 pa[4];
        uint4 pb[2];
        if (has) {
            const size_t ke = (size_t)(kc + 1) * 32 + (size_t)ch * 8;
            pa[0] = *(const float4*)(Xp + (size_t)r0i * HID + ke);
            pa[1] = *(const float4*)(Xp + (size_t)r0i * HID + ke + 4);
            pa[2] = *(const float4*)(Xp + (size_t)(r0i + 64) * HID + ke);
            pa[3] = *(const float4*)(Xp + (size_t)(r0i + 64) * HID + ke + 4);
            pb[0] = *(const uint4*)(Bp + (size_t)r0i * HID + ke);
            pb[1] = *(const uint4*)(Bp + (size_t)(r0i + 64) * HID + ke);
        }

        const uint32_t base = sbase + s * STAGE1;
#pragma unroll
        for (int ks = 0; ks < 2; ks++) {
            const uint32_t kb = ks * 32;
            uint32_t ah[4][4];
#pragma unroll
            for (int mf = 0; mf < 4; mf++) {
                uint32_t ro = (uint32_t)((wm * 64 + mf * 16) * RSTRIDE) + kb;
                ldm4(ah[mf], base + ro + aoff);
            }
            uint32_t bh[2][4];
#pragma unroll
            for (int p = 0; p < 2; p++) {
                uint32_t ro = (uint32_t)((wn * 32 + p * 16) * RSTRIDE) + kb;
                ldm4(bh[p], base + TILE_B + ro + boff);
            }
#pragma unroll
            for (int mf = 0; mf < 4; mf++) {
#pragma unroll
                for (int nf = 0; nf < 4; nf++) {
                    const int p = nf >> 1, q = nf & 1;
                    mma16816(acc[mf][nf], ah[mf], bh[p][2 * q], bh[p][2 * q + 1]);
                }
            }
        }

        if (has) {
            char* st = smem + (s ^ 1) * STAGE1;
            *(uint4*)(st + 0 * TILE_B + r0i * RSTRIDE + ch * 16)        = cvt8h(pa[0], pa[1]);
            *(uint4*)(st + 0 * TILE_B + (r0i + 64) * RSTRIDE + ch * 16) = cvt8h(pa[2], pa[3]);
            *(uint4*)(st + 1 * TILE_B + r0i * RSTRIDE + ch * 16)        = pb[0];
            *(uint4*)(st + 1 * TILE_B + (r0i + 64) * RSTRIDE + ch * 16) = pb[1];
        }
        __syncthreads();
    }

    // epilogue: stage fp32 tile, apply bias + RoPE + scale, write fp16 hi(/lo)
    float* sm = (float*)smem;
    const int g  = lane >> 2;
    const int t2 = (lane & 3) * 2;
#pragma unroll
    for (int mf = 0; mf < 4; mf++) {
        const int lr = wm * 64 + mf * 16 + g;
#pragma unroll
        for (int nf = 0; nf < 4; nf++) {
            const int lc = wn * 32 + nf * 8 + t2;
            *(float2*)(sm + lr * SROW + lc)       = make_float2(acc[mf][nf][0], acc[mf][nf][1]);
            *(float2*)(sm + (lr + 8) * SROW + lc) = make_float2(acc[mf][nf][2], acc[mf][nf][3]);
        }
    }
    __syncthreads();

    const int pblk = bcol >> 7;
#pragma unroll
    for (int it = 0; it < 16; it++) {
        int idx = it * 256 + tid;
        int r  = idx >> 5;
        int c0 = (idx & 31) * 2;
        int srow = (brow + r) & (SEQ - 1);
        int j0 = 64 * pblk + c0;
        float4 t0 = g_tab[(srow << 9) | j0];
        float4 t1 = g_tab[(srow << 9) | (j0 + 1)];
        float x1a = sm[r * SROW + c0]      + bias[j0];
        float x1b = sm[r * SROW + c0 + 1]  + bias[j0 + 1];
        float x2a = sm[r * SROW + c0 + 64] + bias[j0 + 512];
        float x2b = sm[r * SROW + c0 + 65] + bias[j0 + 513];
        float y1a = (x1a * t0.x + x2a * t0.y) * scale;
        float y2a = (x2a * t0.z - x1a * t0.w) * scale;
        float y1b = (x1b * t1.x + x2b * t1.y) * scale;
        float y2b = (x2b * t1.z - x1b * t1.w) * scale;
        size_t gb = (size_t)(brow + r) * HID + bcol;
        uint32_t hi, lo;
        split2h(y1a, y1b, hi, lo);
        *(uint32_t*)(outh + gb + c0) = hi;
        if (WANT_LO) *(uint32_t*)(outl + gb + c0) = lo;
        split2h(y2a, y2b, hi, lo);
        *(uint32_t*)(outh + gb + 64 + c0) = hi;
        if (WANT_LO) *(uint32_t*)(outl + gb + 64 + c0) = lo;
    }
}

// ============================================================================
// output projection: out = Ctx*Wo'^T + bo (fp32). Ctx = fp16 hi/lo splits.
// ============================================================================
__global__ __launch_bounds__(256)
void gemm_out(const __half* __restrict__ Ahi, const __half* __restrict__ Alo,
              const __half* __restrict__ Bw,
              const float* __restrict__ bias, float* __restrict__ Y)
{
    extern __shared__ __align__(128) char smem[];

    const int tid  = threadIdx.x;
    const int wid  = tid >> 5;
    const int lane = tid & 31;
    const int wm   = wid & 1;
    const int wn   = wid >> 1;
    const int brow = blockIdx.y * 128;
    const int bcol = blockIdx.x * 128;

    const uint32_t sbase = smem_u32(smem);
    const uint32_t aoff = (uint32_t)(((lane & 7) + ((lane >> 3) & 1) * 8) * RSTRIDE
                                     + ((lane >> 4) & 1) * 16);
    const uint32_t boff = (uint32_t)(((lane & 7) + ((lane >> 4) & 1) * 8) * RSTRIDE
                                     + ((lane >> 3) & 1) * 16);

    const int r0i = tid >> 2;
    const int ch  = tid & 3;

    const __half* gptr[3];
    gptr[0] = Ahi + (size_t)brow * HID;
    gptr[1] = Alo + (size_t)brow * HID;
    gptr[2] = Bw  + (size_t)bcol * HID;

    float acc[4][4][4];
#pragma unroll
    for (int i = 0; i < 4; i++)
#pragma unroll
        for (int j = 0; j < 4; j++)
#pragma unroll
            for (int r = 0; r < 4; r++) acc[i][j][r] = 0.0f;

    {
        const size_t ke = (size_t)ch * 8;
#pragma unroll
        for (int t = 0; t < 3; t++) {
            uint4 v0 = *(const uint4*)(gptr[t] + (size_t)r0i * HID + ke);
            uint4 v1 = *(const uint4*)(gptr[t] + (size_t)(r0i + 64) * HID + ke);
            *(uint4*)(smem + t * TILE_B + r0i * RSTRIDE + ch * 16) = v0;
            *(uint4*)(smem + t * TILE_B + (r0i + 64) * RSTRIDE + ch * 16) = v1;
        }
    }
    __syncthreads();

    for (int kc = 0; kc < 32; kc++) {
        const int s = kc & 1;
        const bool has = (kc + 1) < 32;

        uint4 pf[3][2];
        if (has) {
            const size_t ke = (size_t)(kc + 1) * 32 + (size_t)ch * 8;
#pragma unroll
            for (int t = 0; t < 3; t++) {
                pf[t][0] = *(const uint4*)(gptr[t] + (size_t)r0i * HID + ke);
                pf[t][1] = *(const uint4*)(gptr[t] + (size_t)(r0i + 64) * HID + ke);
            }
        }

        const uint32_t base = sbase + s * STAGE2;
#pragma unroll
        for (int ks = 0; ks < 2; ks++) {
            const uint32_t kb = ks * 32;
            uint32_t ah[4][4], al[4][4];
#pragma unroll
            for (int mf = 0; mf < 4; mf++) {
                uint32_t ro = (uint32_t)((wm * 64 + mf * 16) * RSTRIDE) + kb;
                ldm4(ah[mf], base + ro + aoff);
                ldm4(al[mf], base + TILE_B + ro + aoff);
            }
            uint32_t bh[2][4];
#pragma unroll
            for (int p = 0; p < 2; p++) {
                uint32_t ro = (uint32_t)((wn * 32 + p * 16) * RSTRIDE) + kb;
                ldm4(bh[p], base + 2 * TILE_B + ro + boff);
            }
#pragma unroll
            for (int mf = 0; mf < 4; mf++) {
#pragma unroll
                for (int nf = 0; nf < 4; nf++) {
                    const int p = nf >> 1, q = nf & 1;
                    mma16816(acc[mf][nf], ah[mf], bh[p][2 * q], bh[p][2 * q + 1]);
                    mma16816(acc[mf][nf], al[mf], bh[p][2 * q], bh[p][2 * q + 1]);
                }
            }
        }

        if (has) {
            char* st = smem + (s ^ 1) * STAGE2;
#pragma unroll
            for (int t = 0; t < 3; t++) {
                *(uint4*)(st + t * TILE_B + r0i * RSTRIDE + ch * 16) = pf[t][0];
                *(uint4*)(st + t * TILE_B + (r0i + 64) * RSTRIDE + ch * 16) = pf[t][1];
            }
        }
        __syncthreads();
    }

    const int g = lane >> 2;
    const int t2 = (lane & 3) * 2;
#pragma unroll
    for (int mf = 0; mf < 4; mf++) {
        const int row0 = brow + wm * 64 + mf * 16 + g;
#pragma unroll
        for (int nf = 0; nf < 4; nf++) {
            const int col = bcol + wn * 32 + nf * 8 + t2;
            float2 bv = *(const float2*)(bias + col);
            *(float2*)(Y + (size_t)row0 * HID + col) =
                make_float2(acc[mf][nf][0] + bv.x, acc[mf][nf][1] + bv.y);
            *(float2*)(Y + (size_t)(row0 + 8) * HID + col) =
                make_float2(acc[mf][nf][2] + bv.x, acc[mf][nf][3] + bv.y);
        }
    }
}

// ============================================================================
// tensor-core flash attention, fp16 2-term. Q split hi/lo; K,V single fp16.
// cp.async double-buffered K/V stages. Ctx written as fp16 hi/lo splits.
// ============================================================================
#define AST 144
#define AQ_H 0
#define AQ_L (128 * AST)              // 18432
#define AKV0 (2 * 128 * AST)          // 36864
#define KVSTG (2 * 64 * AST)          // 18432 (K, V)
#define ATTN_SMEM (AKV0 + 2 * KVSTG)  // 73728

__device__ __forceinline__ void attn_issue_kv(
    int krow0, size_t colbase, uint32_t kvbase, int tid)
{
#pragma unroll
    for (int i = 0; i < 4; i++) {
        const __half* g = (i < 2) ? g_Kh : g_Vh;
        const int arr = i >> 1;
        const int rem = ((i & 1) << 8) + tid;
        const int row = rem >> 3;
        const int c = rem & 7;
        cp16(kvbase + arr * (64 * AST) + row * AST + c * 16,
             g + (size_t)(krow0 + row) * HID + colbase + c * 8);
    }
}

__global__ __launch_bounds__(256, 2) void attn_mma() {
    extern __shared__ __align__(128) char smem[];

    const int tid  = threadIdx.x;
    const int wid  = tid >> 5;
    const int lane = tid & 31;
    const int qt   = blockIdx.x;
    const int bh   = blockIdx.y;
    const int b    = bh >> 4;
    const int h    = bh & 15;
    const int qbase = b * SEQ + qt * 128;
    const size_t colbase = (size_t)h * HD;
    const int krow_base = b * SEQ;

    const uint32_t sb = smem_u32(smem);

    const uint32_t aoff = (uint32_t)(((lane & 7) + ((lane >> 3) & 1) * 8) * AST
                                     + ((lane >> 4) & 1) * 16);
    const uint32_t boff = (uint32_t)(((lane & 7) + ((lane >> 4) & 1) * 8) * AST
                                     + ((lane >> 3) & 1) * 16);
    const uint32_t voff = (uint32_t)(((lane & 7) + ((lane >> 3) & 1) * 8) * AST
                                     + ((lane >> 4) & 1) * 16);

    // group 0: Q hi/lo + KV stage 0
#pragma unroll
    for (int i = 0; i < 8; i++) {
        const __half* g = (i < 4) ? g_Qh : g_Ql;
        const int t = i >> 2;
        const int rem = ((i & 3) << 8) + tid;
        const int row = rem >> 3;
        const int c = rem & 7;
        cp16(sb + t * (128 * AST) + row * AST + c * 16,
             g + (size_t)(qbase + row) * HID + colbase + c * 8);
    }
    attn_issue_kv(krow_base, colbase, sb + AKV0, tid);
    CP_COMMIT();
    attn_issue_kv(krow_base + 64, colbase, sb + AKV0 + KVSTG, tid);
    CP_COMMIT();

    float o[8][4];
#pragma unroll
    for (int nf = 0; nf < 8; nf++)
#pragma unroll
        for (int r = 0; r < 4; r++) o[nf][r] = 0.0f;
    float m0 = -1e30f, m1 = -1e30f, l0 = 0.0f, l1 = 0.0f;

    const uint32_t qrow_off = (uint32_t)(wid * 16 * AST);

    for (int kt = 0; kt < 16; kt++) {
        const int s = kt & 1;
        CP_WAIT1();
        __syncthreads();

        const uint32_t kvb = sb + AKV0 + s * KVSTG;
        const uint32_t akh = kvb;
        const uint32_t avh = kvb + 64 * AST;

        float sfr[8][4];
#pragma unroll
        for (int nf = 0; nf < 8; nf++)
#pragma unroll
            for (int r = 0; r < 4; r++) sfr[nf][r] = 0.0f;

#pragma unroll
        for (int kq = 0; kq < 4; kq++) {
            uint32_t qh[4], ql[4];
            ldm4(qh, sb + AQ_H + qrow_off + kq * 32 + aoff);
            ldm4(ql, sb + AQ_L + qrow_off + kq * 32 + aoff);
            uint32_t kh[4][4];
#pragma unroll
            for (int p = 0; p < 4; p++)
                ldm4(kh[p], akh + (uint32_t)(p * 16 * AST) + kq * 32 + boff);
#pragma unroll
            for (int nf = 0; nf < 8; nf++) {
                const int p = nf >> 1, q = nf & 1;
                mma16816(sfr[nf], qh, kh[p][2 * q], kh[p][2 * q + 1]);
                mma16816(sfr[nf], ql, kh[p][2 * q], kh[p][2 * q + 1]);
            }
        }

        float mx0 = -1e30f, mx1 = -1e30f;
#pragma unroll
        for (int nf = 0; nf < 8; nf++) {
            mx0 = fmaxf(mx0, fmaxf(sfr[nf][0], sfr[nf][1]));
            mx1 = fmaxf(mx1, fmaxf(sfr[nf][2], sfr[nf][3]));
        }
        mx0 = fmaxf(mx0, __shfl_xor_sync(0xFFFFFFFF, mx0, 1));
        mx0 = fmaxf(mx0, __shfl_xor_sync(0xFFFFFFFF, mx0, 2));
        mx1 = fmaxf(mx1, __shfl_xor_sync(0xFFFFFFFF, mx1, 1));
        mx1 = fmaxf(mx1, __shfl_xor_sync(0xFFFFFFFF, mx1, 2));

        float mn0 = fmaxf(m0, mx0), mn1 = fmaxf(m1, mx1);
        float c0 = __expf(m0 - mn0), c1 = __expf(m1 - mn1);
        l0 *= c0; l1 *= c1;
#pragma unroll
        for (int nf = 0; nf < 8; nf++) {
            o[nf][0] *= c0; o[nf][1] *= c0;
            o[nf][2] *= c1; o[nf][3] *= c1;
        }
#pragma unroll
        for (int nf = 0; nf < 8; nf++) {
            sfr[nf][0] = __expf(sfr[nf][0] - mn0);
            sfr[nf][1] = __expf(sfr[nf][1] - mn0);
            sfr[nf][2] = __expf(sfr[nf][2] - mn1);
            sfr[nf][3] = __expf(sfr[nf][3] - mn1);
            l0 += sfr[nf][0] + sfr[nf][1];
            l1 += sfr[nf][2] + sfr[nf][3];
        }
        m0 = mn0; m1 = mn1;

#pragma unroll
        for (int kk = 0; kk < 4; kk++) {
            uint32_t ah[4], al[4];
            split2h(sfr[2 * kk][0],     sfr[2 * kk][1],     ah[0], al[0]);
            split2h(sfr[2 * kk][2],     sfr[2 * kk][3],     ah[1], al[1]);
            split2h(sfr[2 * kk + 1][0], sfr[2 * kk + 1][1], ah[2], al[2]);
            split2h(sfr[2 * kk + 1][2], sfr[2 * kk + 1][3], ah[3], al[3]);

            uint32_t vh[4][4];
#pragma unroll
            for (int p = 0; p < 4; p++) {
                uint32_t ro = (uint32_t)(kk * 16 * AST) + (uint32_t)(p * 32);
                ldm4t(vh[p], avh + ro + voff);
            }
#pragma unroll
            for (int nf = 0; nf < 8; nf++) {
                const int p = nf >> 1, q = nf & 1;
                mma16816(o[nf], ah, vh[p][2 * q], vh[p][2 * q + 1]);
                mma16816(o[nf], al, vh[p][2 * q], vh[p][2 * q + 1]);
            }
        }

        __syncthreads();
        if (kt + 2 < 16)
            attn_issue_kv(krow_base + (kt + 2) * 64, colbase,
                          sb + AKV0 + s * KVSTG, tid);
        CP_COMMIT();
    }

    l0 += __shfl_xor_sync(0xFFFFFFFF, l0, 1);
    l0 += __shfl_xor_sync(0xFFFFFFFF, l0, 2);
    l1 += __shfl_xor_sync(0xFFFFFFFF, l1, 1);
    l1 += __shfl_xor_sync(0xFFFFFFFF, l1, 2);
    float inv0 = 1.0f / l0, inv1 = 1.0f / l1;

    const int g  = lane >> 2;
    const int t2 = (lane & 3) * 2;
    const int row0 = qbase + wid * 16 + g;
#pragma unroll
    for (int nf = 0; nf < 8; nf++) {
        size_t col = colbase + nf * 8 + t2;
        uint32_t hi, lo;
        split2h(o[nf][0] * inv0, o[nf][1] * inv0, hi, lo);
        *(uint32_t*)(g_Ahi + (size_t)row0 * HID + col) = hi;
        *(uint32_t*)(g_Alo + (size_t)row0 * HID + col) = lo;
        split2h(o[nf][2] * inv1, o[nf][3] * inv1, hi, lo);
        *(uint32_t*)(g_Ahi + (size_t)(row0 + 8) * HID + col) = hi;
        *(uint32_t*)(g_Alo + (size_t)(row0 + 8) * HID + col) = lo;
    }
}

// ============================================================================
// launch
// ============================================================================
extern "C" void kernel_launch(void* const* d_in, const int* in_sizes, int n_in,
                              void* d_out, int out_size) {
    (void)in_sizes; (void)n_in; (void)out_size;
    const float* query = (const float*)d_in[0];
    const float* key   = (const float*)d_in[1];
    const float* value = (const float*)d_in[2];
    const float* Wq    = (const float*)d_in[3];
    const float* bq    = (const float*)d_in[4];
    const float* Wk    = (const float*)d_in[5];
    const float* bk    = (const float*)d_in[6];
    const float* Wv    = (const float*)d_in[7];
    const float* bv    = (const float*)d_in[8];
    const float* Wo    = (const float*)d_in[9];
    const float* bo    = (const float*)d_in[10];
    float* out = (float*)d_out;

    __half *Qh, *Ql, *Kh, *Vh, *Ahi, *Alo, *Wqh, *Wkh, *Wvh, *Woh;
    cudaGetSymbolAddress((void**)&Qh, g_Qh);   cudaGetSymbolAddress((void**)&Ql, g_Ql);
    cudaGetSymbolAddress((void**)&Kh, g_Kh);   cudaGetSymbolAddress((void**)&Vh, g_Vh);
    cudaGetSymbolAddress((void**)&Ahi, g_Ahi); cudaGetSymbolAddress((void**)&Alo, g_Alo);
    cudaGetSymbolAddress((void**)&Wqh, g_Wqh); cudaGetSymbolAddress((void**)&Wkh, g_Wkh);
    cudaGetSymbolAddress((void**)&Wvh, g_Wvh); cudaGetSymbolAddress((void**)&Woh, g_Woh);

    cudaFuncSetAttribute(gemm_qkv<true>,  cudaFuncAttributeMaxDynamicSharedMemorySize, GEMM_SMEM);
    cudaFuncSetAttribute(gemm_qkv<false>, cudaFuncAttributeMaxDynamicSharedMemorySize, GEMM_SMEM);
    cudaFuncSetAttribute(gemm_out, cudaFuncAttributeMaxDynamicSharedMemorySize, GEMM_SMEM);
    cudaFuncSetAttribute(attn_mma, cudaFuncAttributeMaxDynamicSharedMemorySize, ATTN_SMEM);

    dim3 ggrid(HID / 128, MROWS / 128);
    const int wblocks = (HID * HID / 8) / 256;   // 512

    make_invf_kernel<<<1, 512>>>();
    rope_table_kernel<<<(SEQ * 512) / 256, 256>>>();

    prep_w_rowperm<<<wblocks, 256>>>(Wq, Wqh);
    prep_w_rowperm<<<wblocks, 256>>>(Wk, Wkh);
    prep_w_rowperm<<<wblocks, 256>>>(Wv, Wvh);
    prep_w_colperm<<<wblocks, 256>>>(Wo, Woh);

    gemm_qkv<true> <<<ggrid, 256, GEMM_SMEM>>>(query, Wqh, bq, Qh, Ql, 0.125f);
    gemm_qkv<false><<<ggrid, 256, GEMM_SMEM>>>(key,   Wkh, bk, Kh, nullptr, 1.0f);
    gemm_qkv<false><<<ggrid, 256, GEMM_SMEM>>>(value, Wvh, bv, Vh, nullptr, 1.0f);

    attn_mma<<<dim3(8, 128), 256, ATTN_SMEM>>>();

    gemm_out<<<ggrid, 256, GEMM_SMEM>>>(Ahi, Alo, Woh, bo, out);
}

// round 10
// speedup vs baseline: 1.5276x; 1.5276x over previous
#include <cuda_runtime.h>
#include <cuda_fp16.h>
#include <cstdint>

#define HID 1024
#define HEADS 16
#define HD 64
#define BATCH 8
#define SEQ 1024
#define MROWS (BATCH * SEQ)

// ---------------- scratch (device globals; no allocation allowed) ----------
__device__ __half g_Qh[MROWS * HID];
__device__ __half g_Ql[MROWS * HID];
__device__ __half g_Kh[MROWS * HID];
__device__ __half g_Vh[MROWS * HID];
__device__ __half g_Ahi[MROWS * HID];
__device__ __half g_Alo[MROWS * HID];
__device__ __half g_Wqh[HID * HID];
__device__ __half g_Wkh[HID * HID];
__device__ __half g_Wvh[HID * HID];
__device__ __half g_Woh[HID * HID];
__device__ float g_invf[HID / 2];
__device__ float4 g_tab[SEQ * (HID / 2)];

// ---------------- helpers ----------------------------------------
__device__ __forceinline__ uint32_t smem_u32(const void* p) {
    uint32_t a;
    asm("{ .reg .u64 t; cvta.to.shared.u64 t, %1; cvt.u32.u64 %0, t; }"
        : "=r"(a) : "l"(p));
    return a;
}
__device__ __forceinline__ void cp16(uint32_t dst, const void* src) {
    asm volatile("cp.async.cg.shared.global [%0], [%1], 16;" :: "r"(dst), "l"(src));
}
#define CP_COMMIT() asm volatile("cp.async.commit_group;" ::: "memory")
#define CP_WAIT1()  asm volatile("cp.async.wait_group 1;" ::: "memory")

__device__ __forceinline__ void ldm4(uint32_t* r, uint32_t addr) {
    asm volatile("ldmatrix.sync.aligned.m8n8.x4.shared.b16 {%0,%1,%2,%3}, [%4];"
                 : "=r"(r[0]), "=r"(r[1]), "=r"(r[2]), "=r"(r[3]) : "r"(addr));
}
__device__ __forceinline__ void ldm4t(uint32_t* r, uint32_t addr) {
    asm volatile("ldmatrix.sync.aligned.m8n8.x4.trans.shared.b16 {%0,%1,%2,%3}, [%4];"
                 : "=r"(r[0]), "=r"(r[1]), "=r"(r[2]), "=r"(r[3]) : "r"(addr));
}
__device__ __forceinline__ void mma16816(float* d, const uint32_t* a,
                                         uint32_t b0, uint32_t b1) {
    asm volatile(
        "mma.sync.aligned.m16n8k16.row.col.f32.f16.f16.f32 "
        "{%0,%1,%2,%3}, {%4,%5,%6,%7}, {%8,%9}, {%0,%1,%2,%3};"
        : "+f"(d[0]), "+f"(d[1]), "+f"(d[2]), "+f"(d[3])
        : "r"(a[0]), "r"(a[1]), "r"(a[2]), "r"(a[3]), "r"(b0), "r"(b1));
}
// fp16 split: pair of floats -> half2 hi + half2 lo (packed u32)
__device__ __forceinline__ void split2h(float x, float y, uint32_t& hi, uint32_t& lo) {
    __half2 h = __floats2half2_rn(x, y);
    float2 f = __half22float2(h);
    __half2 l2 = __floats2half2_rn(x - f.x, y - f.y);
    hi = *reinterpret_cast<uint32_t*>(&h);
    lo = *reinterpret_cast<uint32_t*>(&l2);
}
// 8 fp32 -> uint4 of 8 rn-rounded fp16 (no residual)
__device__ __forceinline__ uint4 cvt8h(const float4& u, const float4& v) {
    __half2 h0 = __floats2half2_rn(u.x, u.y);
    __half2 h1 = __floats2half2_rn(u.z, u.w);
    __half2 h2 = __floats2half2_rn(v.x, v.y);
    __half2 h3 = __floats2half2_rn(v.z, v.w);
    return make_uint4(*(uint32_t*)&h0, *(uint32_t*)&h1, *(uint32_t*)&h2, *(uint32_t*)&h3);
}
// permutation: n' = 128p + 64s + i  ->  orig = 64p + 512s + i
__device__ __forceinline__ int perm_orig(int n) {
    int p = n >> 7, s = (n >> 6) & 1, i = n & 63;
    return 64 * p + 512 * s + i;
}

// ============================================================================
// weight prep: single fp16 (rn-rounded), row-permuted / col-permuted
// ============================================================================
__global__ __launch_bounds__(256) void prep_w_rowperm(
    const float* __restrict__ W, __half* __restrict__ Wh)
{
    int idx = blockIdx.x * 256 + threadIdx.x;   // HID*HID/8
    int n = idx >> 7;
    int c8 = (idx & 127) * 8;
    int orig = perm_orig(n);
    float4 u = *(const float4*)(W + (size_t)orig * HID + c8);
    float4 v = *(const float4*)(W + (size_t)orig * HID + c8 + 4);
    *(uint4*)(Wh + (size_t)n * HID + c8) = cvt8h(u, v);
}

__global__ __launch_bounds__(256) void prep_w_colperm(
    const float* __restrict__ W, __half* __restrict__ Wh)
{
    int idx = blockIdx.x * 256 + threadIdx.x;
    int n = idx >> 7;
    int k8 = (idx & 127) * 8;
    int orig = perm_orig(k8);
    float4 u = *(const float4*)(W + (size_t)n * HID + orig);
    float4 v = *(const float4*)(W + (size_t)n * HID + orig + 4);
    *(uint4*)(Wh + (size_t)n * HID + k8) = cvt8h(u, v);
}

__global__ void make_invf_kernel() {
    int j = threadIdx.x;
    if (j < HID / 2) {
        double e = exp(-((double)(2 * j) / (double)HID) * log(10000.0));
        g_invf[j] = (float)e;
    }
}
__global__ __launch_bounds__(256) void rope_table_kernel() {
    int idx = blockIdx.x * 256 + threadIdx.x;
    int s = idx >> 9;
    int j = idx & 511;
    float t = (float)s * g_invf[j];
    float st, ct;
    sincosf(t, &st, &ct);
    float s1, c1, s2, c2;
    sincosf(st, &s1, &c1);
    sincosf(ct, &s2, &c2);
    g_tab[idx] = make_float4(c1, s1, c2, s2);
}

// ============================================================================
// fused QKV projection, 1-term pure fp16: Y = X*W'^T (+bias +RoPE +scale).
// A = fp32 converted inline to single fp16; B = single fp16 weights.
// CTA 128x128, warp 64x32, K-chunk 32, 2-stage double buffer.
// NOTE: no min-blocks hint — forcing 2 CTAs/SM caps regs at 128 and spills
// (R9 regression). Let ptxas allocate freely.
// ============================================================================
#define RSTRIDE 80
#define TILE_B (128 * RSTRIDE)      // 10240
#define STAGE1 (2 * TILE_B)         // 20480 (A, B) for 1-term proj
#define STAGE2 (3 * TILE_B)         // 30720 (Ah, Al, B) for 2-term out
#define GEMM_SMEM 67584             // epilogue fp32 tile 128x132
#define SROW 132

template <bool WANT_LO>
__global__ __launch_bounds__(256)
void gemm_qkv(const float* __restrict__ X, const __half* __restrict__ Bw,
              const float* __restrict__ bias,
              __half* __restrict__ outh, __half* __restrict__ outl, float scale)
{
    extern __shared__ __align__(128) char smem[];

    const int tid  = threadIdx.x;
    const int wid  = tid >> 5;
    const int lane = tid & 31;
    const int wm   = wid & 1;
    const int wn   = wid >> 1;
    const int brow = blockIdx.y * 128;
    const int bcol = blockIdx.x * 128;

    const uint32_t sbase = smem_u32(smem);
    const uint32_t aoff = (uint32_t)(((lane & 7) + ((lane >> 3) & 1) * 8) * RSTRIDE
                                     + ((lane >> 4) & 1) * 16);
    const uint32_t boff = (uint32_t)(((lane & 7) + ((lane >> 4) & 1) * 8) * RSTRIDE
                                     + ((lane >> 3) & 1) * 16);

    const int r0i = tid >> 2;          // rows r0i, r0i+64
    const int ch  = tid & 3;

    const float* Xp = X + (size_t)brow * HID;
    const __half* Bp = Bw + (size_t)bcol * HID;

    float acc[4][4][4];
#pragma unroll
    for (int i = 0; i < 4; i++)
#pragma unroll
        for (int j = 0; j < 4; j++)
#pragma unroll
            for (int r = 0; r < 4; r++) acc[i][j][r] = 0.0f;

    // prologue: chunk 0 -> stage 0
    {
        const size_t ke = (size_t)ch * 8;
        float4 a0 = *(const float4*)(Xp + (size_t)r0i * HID + ke);
        float4 a1 = *(const float4*)(Xp + (size_t)r0i * HID + ke + 4);
        float4 a2 = *(const float4*)(Xp + (size_t)(r0i + 64) * HID + ke);
        float4 a3 = *(const float4*)(Xp + (size_t)(r0i + 64) * HID + ke + 4);
        uint4 b0 = *(const uint4*)(Bp + (size_t)r0i * HID + ke);
        uint4 b1 = *(const uint4*)(Bp + (size_t)(r0i + 64) * HID + ke);
        *(uint4*)(smem + 0 * TILE_B + r0i * RSTRIDE + ch * 16)        = cvt8h(a0, a1);
        *(uint4*)(smem + 0 * TILE_B + (r0i + 64) * RSTRIDE + ch * 16) = cvt8h(a2, a3);
        *(uint4*)(smem + 1 * TILE_B + r0i * RSTRIDE + ch * 16)        = b0;
        *(uint4*)(smem + 1 * TILE_B + (r0i + 64) * RSTRIDE + ch * 16) = b1;
    }
    __syncthreads();

    for (int kc = 0; kc < 32; kc++) {
        const int s = kc & 1;
        const bool has = (kc + 1) < 32;

        float4 pa[4];
        uint4 pb[2];
        if (has) {
            const size_t ke = (size_t)(kc + 1) * 32 + (size_t)ch * 8;
            pa[0] = *(const float4*)(Xp + (size_t)r0i * HID + ke);
            pa[1] = *(const float4*)(Xp + (size_t)r0i * HID + ke + 4);
            pa[2] = *(const float4*)(Xp + (size_t)(r0i + 64) * HID + ke);
            pa[3] = *(const float4*)(Xp + (size_t)(r0i + 64) * HID + ke + 4);
            pb[0] = *(const uint4*)(Bp + (size_t)r0i * HID + ke);
            pb[1] = *(const uint4*)(Bp + (size_t)(r0i + 64) * HID + ke);
        }

        const uint32_t base = sbase + s * STAGE1;
#pragma unroll
        for (int ks = 0; ks < 2; ks++) {
            const uint32_t kb = ks * 32;
            uint32_t ah[4][4];
#pragma unroll
            for (int mf = 0; mf < 4; mf++) {
                uint32_t ro = (uint32_t)((wm * 64 + mf * 16) * RSTRIDE) + kb;
                ldm4(ah[mf], base + ro + aoff);
            }
            uint32_t bh[2][4];
#pragma unroll
            for (int p = 0; p < 2; p++) {
                uint32_t ro = (uint32_t)((wn * 32 + p * 16) * RSTRIDE) + kb;
                ldm4(bh[p], base + TILE_B + ro + boff);
            }
#pragma unroll
            for (int mf = 0; mf < 4; mf++) {
#pragma unroll
                for (int nf = 0; nf < 4; nf++) {
                    const int p = nf >> 1, q = nf & 1;
                    mma16816(acc[mf][nf], ah[mf], bh[p][2 * q], bh[p][2 * q + 1]);
                }
            }
        }

        if (has) {
            char* st = smem + (s ^ 1) * STAGE1;
            *(uint4*)(st + 0 * TILE_B + r0i * RSTRIDE + ch * 16)        = cvt8h(pa[0], pa[1]);
            *(uint4*)(st + 0 * TILE_B + (r0i + 64) * RSTRIDE + ch * 16) = cvt8h(pa[2], pa[3]);
            *(uint4*)(st + 1 * TILE_B + r0i * RSTRIDE + ch * 16)        = pb[0];
            *(uint4*)(st + 1 * TILE_B + (r0i + 64) * RSTRIDE + ch * 16) = pb[1];
        }
        __syncthreads();
    }

    // epilogue: stage fp32 tile, apply bias + RoPE + scale, write fp16 hi(/lo)
    float* sm = (float*)smem;
    const int g  = lane >> 2;
    const int t2 = (lane & 3) * 2;
#pragma unroll
    for (int mf = 0; mf < 4; mf++) {
        const int lr = wm * 64 + mf * 16 + g;
#pragma unroll
        for (int nf = 0; nf < 4; nf++) {
            const int lc = wn * 32 + nf * 8 + t2;
            *(float2*)(sm + lr * SROW + lc)       = make_float2(acc[mf][nf][0], acc[mf][nf][1]);
            *(float2*)(sm + (lr + 8) * SROW + lc) = make_float2(acc[mf][nf][2], acc[mf][nf][3]);
        }
    }
    __syncthreads();

    const int pblk = bcol >> 7;
#pragma unroll
    for (int it = 0; it < 16; it++) {
        int idx = it * 256 + tid;
        int r  = idx >> 5;
        int c0 = (idx & 31) * 2;
        int srow = (brow + r) & (SEQ - 1);
        int j0 = 64 * pblk + c0;
        float4 t0 = g_tab[(srow << 9) | j0];
        float4 t1 = g_tab[(srow << 9) | (j0 + 1)];
        float x1a = sm[r * SROW + c0]      + bias[j0];
        float x1b = sm[r * SROW + c0 + 1]  + bias[j0 + 1];
        float x2a = sm[r * SROW + c0 + 64] + bias[j0 + 512];
        float x2b = sm[r * SROW + c0 + 65] + bias[j0 + 513];
        float y1a = (x1a * t0.x + x2a * t0.y) * scale;
        float y2a = (x2a * t0.z - x1a * t0.w) * scale;
        float y1b = (x1b * t1.x + x2b * t1.y) * scale;
        float y2b = (x2b * t1.z - x1b * t1.w) * scale;
        size_t gb = (size_t)(brow + r) * HID + bcol;
        uint32_t hi, lo;
        split2h(y1a, y1b, hi, lo);
        *(uint32_t*)(outh + gb + c0) = hi;
        if (WANT_LO) *(uint32_t*)(outl + gb + c0) = lo;
        split2h(y2a, y2b, hi, lo);
        *(uint32_t*)(outh + gb + 64 + c0) = hi;
        if (WANT_LO) *(uint32_t*)(outl + gb + 64 + c0) = lo;
    }
}

// ============================================================================
// output projection: out = Ctx*Wo'^T + bo (fp32). Ctx = fp16 hi/lo splits.
// ============================================================================
__global__ __launch_bounds__(256)
void gemm_out(const __half* __restrict__ Ahi, const __half* __restrict__ Alo,
              const __half* __restrict__ Bw,
              const float* __restrict__ bias, float* __restrict__ Y)
{
    extern __shared__ __align__(128) char smem[];

    const int tid  = threadIdx.x;
    const int wid  = tid >> 5;
    const int lane = tid & 31;
    const int wm   = wid & 1;
    const int wn   = wid >> 1;
    const int brow = blockIdx.y * 128;
    const int bcol = blockIdx.x * 128;

    const uint32_t sbase = smem_u32(smem);
    const uint32_t aoff = (uint32_t)(((lane & 7) + ((lane >> 3) & 1) * 8) * RSTRIDE
                                     + ((lane >> 4) & 1) * 16);
    const uint32_t boff = (uint32_t)(((lane & 7) + ((lane >> 4) & 1) * 8) * RSTRIDE
                                     + ((lane >> 3) & 1) * 16);

    const int r0i = tid >> 2;
    const int ch  = tid & 3;

    const __half* gptr[3];
    gptr[0] = Ahi + (size_t)brow * HID;
    gptr[1] = Alo + (size_t)brow * HID;
    gptr[2] = Bw  + (size_t)bcol * HID;

    float acc[4][4][4];
#pragma unroll
    for (int i = 0; i < 4; i++)
#pragma unroll
        for (int j = 0; j < 4; j++)
#pragma unroll
            for (int r = 0; r < 4; r++) acc[i][j][r] = 0.0f;

    {
        const size_t ke = (size_t)ch * 8;
#pragma unroll
        for (int t = 0; t < 3; t++) {
            uint4 v0 = *(const uint4*)(gptr[t] + (size_t)r0i * HID + ke);
            uint4 v1 = *(const uint4*)(gptr[t] + (size_t)(r0i + 64) * HID + ke);
            *(uint4*)(smem + t * TILE_B + r0i * RSTRIDE + ch * 16) = v0;
            *(uint4*)(smem + t * TILE_B + (r0i + 64) * RSTRIDE + ch * 16) = v1;
        }
    }
    __syncthreads();

    for (int kc = 0; kc < 32; kc++) {
        const int s = kc & 1;
        const bool has = (kc + 1) < 32;

        uint4 pf[3][2];
        if (has) {
            const size_t ke = (size_t)(kc + 1) * 32 + (size_t)ch * 8;
#pragma unroll
            for (int t = 0; t < 3; t++) {
                pf[t][0] = *(const uint4*)(gptr[t] + (size_t)r0i * HID + ke);
                pf[t][1] = *(const uint4*)(gptr[t] + (size_t)(r0i + 64) * HID + ke);
            }
        }

        const uint32_t base = sbase + s * STAGE2;
#pragma unroll
        for (int ks = 0; ks < 2; ks++) {
            const uint32_t kb = ks * 32;
            uint32_t ah[4][4], al[4][4];
#pragma unroll
            for (int mf = 0; mf < 4; mf++) {
                uint32_t ro = (uint32_t)((wm * 64 + mf * 16) * RSTRIDE) + kb;
                ldm4(ah[mf], base + ro + aoff);
                ldm4(al[mf], base + TILE_B + ro + aoff);
            }
            uint32_t bh[2][4];
#pragma unroll
            for (int p = 0; p < 2; p++) {
                uint32_t ro = (uint32_t)((wn * 32 + p * 16) * RSTRIDE) + kb;
                ldm4(bh[p], base + 2 * TILE_B + ro + boff);
            }
#pragma unroll
            for (int mf = 0; mf < 4; mf++) {
#pragma unroll
                for (int nf = 0; nf < 4; nf++) {
                    const int p = nf >> 1, q = nf & 1;
                    mma16816(acc[mf][nf], ah[mf], bh[p][2 * q], bh[p][2 * q + 1]);
                    mma16816(acc[mf][nf], al[mf], bh[p][2 * q], bh[p][2 * q + 1]);
                }
            }
        }

        if (has) {
            char* st = smem + (s ^ 1) * STAGE2;
#pragma unroll
            for (int t = 0; t < 3; t++) {
                *(uint4*)(st + t * TILE_B + r0i * RSTRIDE + ch * 16) = pf[t][0];
                *(uint4*)(st + t * TILE_B + (r0i + 64) * RSTRIDE + ch * 16) = pf[t][1];
            }
        }
        __syncthreads();
    }

    const int g = lane >> 2;
    const int t2 = (lane & 3) * 2;
#pragma unroll
    for (int mf = 0; mf < 4; mf++) {
        const int row0 = brow + wm * 64 + mf * 16 + g;
#pragma unroll
        for (int nf = 0; nf < 4; nf++) {
            const int col = bcol + wn * 32 + nf * 8 + t2;
            float2 bv = *(const float2*)(bias + col);
            *(float2*)(Y + (size_t)row0 * HID + col) =
                make_float2(acc[mf][nf][0] + bv.x, acc[mf][nf][1] + bv.y);
            *(float2*)(Y + (size_t)(row0 + 8) * HID + col) =
                make_float2(acc[mf][nf][2] + bv.x, acc[mf][nf][3] + bv.y);
        }
    }
}

// ============================================================================
// tensor-core flash attention, fp16 2-term. Q split hi/lo; K,V single fp16.
// cp.async double-buffered K/V stages. Ctx written as fp16 hi/lo splits.
// ============================================================================
#define AST 144
#define AQ_H 0
#define AQ_L (128 * AST)              // 18432
#define AKV0 (2 * 128 * AST)          // 36864
#define KVSTG (2 * 64 * AST)          // 18432 (K, V)
#define ATTN_SMEM (AKV0 + 2 * KVSTG)  // 73728

__device__ __forceinline__ void attn_issue_kv(
    int krow0, size_t colbase, uint32_t kvbase, int tid)
{
#pragma unroll
    for (int i = 0; i < 4; i++) {
        const __half* g = (i < 2) ? g_Kh : g_Vh;
        const int arr = i >> 1;
        const int rem = ((i & 1) << 8) + tid;
        const int row = rem >> 3;
        const int c = rem & 7;
        cp16(kvbase + arr * (64 * AST) + row * AST + c * 16,
             g + (size_t)(krow0 + row) * HID + colbase + c * 8);
    }
}

__global__ __launch_bounds__(256, 2) void attn_mma() {
    extern __shared__ __align__(128) char smem[];

    const int tid  = threadIdx.x;
    const int wid  = tid >> 5;
    const int lane = tid & 31;
    const int qt   = blockIdx.x;
    const int bh   = blockIdx.y;
    const int b    = bh >> 4;
    const int h    = bh & 15;
    const int qbase = b * SEQ + qt * 128;
    const size_t colbase = (size_t)h * HD;
    const int krow_base = b * SEQ;

    const uint32_t sb = smem_u32(smem);

    const uint32_t aoff = (uint32_t)(((lane & 7) + ((lane >> 3) & 1) * 8) * AST
                                     + ((lane >> 4) & 1) * 16);
    const uint32_t boff = (uint32_t)(((lane & 7) + ((lane >> 4) & 1) * 8) * AST
                                     + ((lane >> 3) & 1) * 16);
    const uint32_t voff = (uint32_t)(((lane & 7) + ((lane >> 3) & 1) * 8) * AST
                                     + ((lane >> 4) & 1) * 16);

    // group 0: Q hi/lo + KV stage 0
#pragma unroll
    for (int i = 0; i < 8; i++) {
        const __half* g = (i < 4) ? g_Qh : g_Ql;
        const int t = i >> 2;
        const int rem = ((i & 3) << 8) + tid;
        const int row = rem >> 3;
        const int c = rem & 7;
        cp16(sb + t * (128 * AST) + row * AST + c * 16,
             g + (size_t)(qbase + row) * HID + colbase + c * 8);
    }
    attn_issue_kv(krow_base, colbase, sb + AKV0, tid);
    CP_COMMIT();
    attn_issue_kv(krow_base + 64, colbase, sb + AKV0 + KVSTG, tid);
    CP_COMMIT();

    float o[8][4];
#pragma unroll
    for (int nf = 0; nf < 8; nf++)
#pragma unroll
        for (int r = 0; r < 4; r++) o[nf][r] = 0.0f;
    float m0 = -1e30f, m1 = -1e30f, l0 = 0.0f, l1 = 0.0f;

    const uint32_t qrow_off = (uint32_t)(wid * 16 * AST);

    for (int kt = 0; kt < 16; kt++) {
        const int s = kt & 1;
        CP_WAIT1();
        __syncthreads();

        const uint32_t kvb = sb + AKV0 + s * KVSTG;
        const uint32_t akh = kvb;
        const uint32_t avh = kvb + 64 * AST;

        float sfr[8][4];
#pragma unroll
        for (int nf = 0; nf < 8; nf++)
#pragma unroll
            for (int r = 0; r < 4; r++) sfr[nf][r] = 0.0f;

#pragma unroll
        for (int kq = 0; kq < 4; kq++) {
            uint32_t qh[4], ql[4];
            ldm4(qh, sb + AQ_H + qrow_off + kq * 32 + aoff);
            ldm4(ql, sb + AQ_L + qrow_off + kq * 32 + aoff);
            uint32_t kh[4][4];
#pragma unroll
            for (int p = 0; p < 4; p++)
                ldm4(kh[p], akh + (uint32_t)(p * 16 * AST) + kq * 32 + boff);
#pragma unroll
            for (int nf = 0; nf < 8; nf++) {
                const int p = nf >> 1, q = nf & 1;
                mma16816(sfr[nf], qh, kh[p][2 * q], kh[p][2 * q + 1]);
                mma16816(sfr[nf], ql, kh[p][2 * q], kh[p][2 * q + 1]);
            }
        }

        float mx0 = -1e30f, mx1 = -1e30f;
#pragma unroll
        for (int nf = 0; nf < 8; nf++) {
            mx0 = fmaxf(mx0, fmaxf(sfr[nf][0], sfr[nf][1]));
            mx1 = fmaxf(mx1, fmaxf(sfr[nf][2], sfr[nf][3]));
        }
        mx0 = fmaxf(mx0, __shfl_xor_sync(0xFFFFFFFF, mx0, 1));
        mx0 = fmaxf(mx0, __shfl_xor_sync(0xFFFFFFFF, mx0, 2));
        mx1 = fmaxf(mx1, __shfl_xor_sync(0xFFFFFFFF, mx1, 1));
        mx1 = fmaxf(mx1, __shfl_xor_sync(0xFFFFFFFF, mx1, 2));

        float mn0 = fmaxf(m0, mx0), mn1 = fmaxf(m1, mx1);
        float c0 = __expf(m0 - mn0), c1 = __expf(m1 - mn1);
        l0 *= c0; l1 *= c1;
#pragma unroll
        for (int nf = 0; nf < 8; nf++) {
            o[nf][0] *= c0; o[nf][1] *= c0;
            o[nf][2] *= c1; o[nf][3] *= c1;
        }
#pragma unroll
        for (int nf = 0; nf < 8; nf++) {
            sfr[nf][0] = __expf(sfr[nf][0] - mn0);
            sfr[nf][1] = __expf(sfr[nf][1] - mn0);
            sfr[nf][2] = __expf(sfr[nf][2] - mn1);
            sfr[nf][3] = __expf(sfr[nf][3] - mn1);
            l0 += sfr[nf][0] + sfr[nf][1];
            l1 += sfr[nf][2] + sfr[nf][3];
        }
        m0 = mn0; m1 = mn1;

#pragma unroll
        for (int kk = 0; kk < 4; kk++) {
            uint32_t ah[4], al[4];
            split2h(sfr[2 * kk][0],     sfr[2 * kk][1],     ah[0], al[0]);
            split2h(sfr[2 * kk][2],     sfr[2 * kk][3],     ah[1], al[1]);
            split2h(sfr[2 * kk + 1][0], sfr[2 * kk + 1][1], ah[2], al[2]);
            split2h(sfr[2 * kk + 1][2], sfr[2 * kk + 1][3], ah[3], al[3]);

            uint32_t vh[4][4];
#pragma unroll
            for (int p = 0; p < 4; p++) {
                uint32_t ro = (uint32_t)(kk * 16 * AST) + (uint32_t)(p * 32);
                ldm4t(vh[p], avh + ro + voff);
            }
#pragma unroll
            for (int nf = 0; nf < 8; nf++) {
                const int p = nf >> 1, q = nf & 1;
                mma16816(o[nf], ah, vh[p][2 * q], vh[p][2 * q + 1]);
                mma16816(o[nf], al, vh[p][2 * q], vh[p][2 * q + 1]);
            }
        }

        __syncthreads();
        if (kt + 2 < 16)
            attn_issue_kv(krow_base + (kt + 2) * 64, colbase,
                          sb + AKV0 + s * KVSTG, tid);
        CP_COMMIT();
    }

    l0 += __shfl_xor_sync(0xFFFFFFFF, l0, 1);
    l0 += __shfl_xor_sync(0xFFFFFFFF, l0, 2);
    l1 += __shfl_xor_sync(0xFFFFFFFF, l1, 1);
    l1 += __shfl_xor_sync(0xFFFFFFFF, l1, 2);
    float inv0 = 1.0f / l0, inv1 = 1.0f / l1;

    const int g  = lane >> 2;
    const int t2 = (lane & 3) * 2;
    const int row0 = qbase + wid * 16 + g;
#pragma unroll
    for (int nf = 0; nf < 8; nf++) {
        size_t col = colbase + nf * 8 + t2;
        uint32_t hi, lo;
        split2h(o[nf][0] * inv0, o[nf][1] * inv0, hi, lo);
        *(uint32_t*)(g_Ahi + (size_t)row0 * HID + col) = hi;
        *(uint32_t*)(g_Alo + (size_t)row0 * HID + col) = lo;
        split2h(o[nf][2] * inv1, o[nf][3] * inv1, hi, lo);
        *(uint32_t*)(g_Ahi + (size_t)(row0 + 8) * HID + col) = hi;
        *(uint32_t*)(g_Alo + (size_t)(row0 + 8) * HID + col) = lo;
    }
}

// ============================================================================
// launch
// ============================================================================
extern "C" void kernel_launch(void* const* d_in, const int* in_sizes, int n_in,
                              void* d_out, int out_size) {
    (void)in_sizes; (void)n_in; (void)out_size;
    const float* query = (const float*)d_in[0];
    const float* key   = (const float*)d_in[1];
    const float* value = (const float*)d_in[2];
    const float* Wq    = (const float*)d_in[3];
    const float* bq    = (const float*)d_in[4];
    const float* Wk    = (const float*)d_in[5];
    const float* bk    = (const float*)d_in[6];
    const float* Wv    = (const float*)d_in[7];
    const float* bv    = (const float*)d_in[8];
    const float* Wo    = (const float*)d_in[9];
    const float* bo    = (const float*)d_in[10];
    float* out = (float*)d_out;

    __half *Qh, *Ql, *Kh, *Vh, *Ahi, *Alo, *Wqh, *Wkh, *Wvh, *Woh;
    cudaGetSymbolAddress((void**)&Qh, g_Qh);   cudaGetSymbolAddress((void**)&Ql, g_Ql);
    cudaGetSymbolAddress((void**)&Kh, g_Kh);   cudaGetSymbolAddress((void**)&Vh, g_Vh);
    cudaGetSymbolAddress((void**)&Ahi, g_Ahi); cudaGetSymbolAddress((void**)&Alo, g_Alo);
    cudaGetSymbolAddress((void**)&Wqh, g_Wqh); cudaGetSymbolAddress((void**)&Wkh, g_Wkh);
    cudaGetSymbolAddress((void**)&Wvh, g_Wvh); cudaGetSymbolAddress((void**)&Woh, g_Woh);

    cudaFuncSetAttribute(gemm_qkv<true>,  cudaFuncAttributeMaxDynamicSharedMemorySize, GEMM_SMEM);
    cudaFuncSetAttribute(gemm_qkv<false>, cudaFuncAttributeMaxDynamicSharedMemorySize, GEMM_SMEM);
    cudaFuncSetAttribute(gemm_out, cudaFuncAttributeMaxDynamicSharedMemorySize, GEMM_SMEM);
    cudaFuncSetAttribute(attn_mma, cudaFuncAttributeMaxDynamicSharedMemorySize, ATTN_SMEM);

    dim3 ggrid(HID / 128, MROWS / 128);
    const int wblocks = (HID * HID / 8) / 256;   // 512

    make_invf_kernel<<<1, 512>>>();
    rope_table_kernel<<<(SEQ * 512) / 256, 256>>>();

    prep_w_rowperm<<<wblocks, 256>>>(Wq, Wqh);
    prep_w_rowperm<<<wblocks, 256>>>(Wk, Wkh);
    prep_w_rowperm<<<wblocks, 256>>>(Wv, Wvh);
    prep_w_colperm<<<wblocks, 256>>>(Wo, Woh);

    gemm_qkv<true> <<<ggrid, 256, GEMM_SMEM>>>(query, Wqh, bq, Qh, Ql, 0.125f);
    gemm_qkv<false><<<ggrid, 256, GEMM_SMEM>>>(key,   Wkh, bk, Kh, nullptr, 1.0f);
    gemm_qkv<false><<<ggrid, 256, GEMM_SMEM>>>(value, Wvh, bv, Vh, nullptr, 1.0f);

    attn_mma<<<dim3(8, 128), 256, ATTN_SMEM>>>();

    gemm_out<<<ggrid, 256, GEMM_SMEM>>>(Ahi, Alo, Woh, bo, out);
}

// round 11
// speedup vs baseline: 1.7000x; 1.1129x over previous
#include <cuda_runtime.h>
#include <cuda_fp16.h>
#include <cstdint>

#define HID 1024
#define HEADS 16
#define HD 64
#define BATCH 8
#define SEQ 1024
#define MROWS (BATCH * SEQ)

// ---------------- scratch (device globals; no allocation allowed) ----------
__device__ __half g_Qh[MROWS * HID];
__device__ __half g_Kh[MROWS * HID];
__device__ __half g_Vh[MROWS * HID];
__device__ __half g_Ahi[MROWS * HID];
__device__ __half g_Alo[MROWS * HID];
__device__ __half g_Wqh[HID * HID];
__device__ __half g_Wkh[HID * HID];
__device__ __half g_Wvh[HID * HID];
__device__ __half g_Woh[HID * HID];
__device__ float g_invf[HID / 2];
__device__ float4 g_tab[SEQ * (HID / 2)];

// ---------------- helpers ----------------------------------------
__device__ __forceinline__ uint32_t smem_u32(const void* p) {
    uint32_t a;
    asm("{ .reg .u64 t; cvta.to.shared.u64 t, %1; cvt.u32.u64 %0, t; }"
        : "=r"(a) : "l"(p));
    return a;
}
__device__ __forceinline__ void cp16(uint32_t dst, const void* src) {
    asm volatile("cp.async.cg.shared.global [%0], [%1], 16;" :: "r"(dst), "l"(src));
}
#define CP_COMMIT() asm volatile("cp.async.commit_group;" ::: "memory")
#define CP_WAIT1()  asm volatile("cp.async.wait_group 1;" ::: "memory")

__device__ __forceinline__ void ldm4(uint32_t* r, uint32_t addr) {
    asm volatile("ldmatrix.sync.aligned.m8n8.x4.shared.b16 {%0,%1,%2,%3}, [%4];"
                 : "=r"(r[0]), "=r"(r[1]), "=r"(r[2]), "=r"(r[3]) : "r"(addr));
}
__device__ __forceinline__ void ldm4t(uint32_t* r, uint32_t addr) {
    asm volatile("ldmatrix.sync.aligned.m8n8.x4.trans.shared.b16 {%0,%1,%2,%3}, [%4];"
                 : "=r"(r[0]), "=r"(r[1]), "=r"(r[2]), "=r"(r[3]) : "r"(addr));
}
__device__ __forceinline__ void mma16816(float* d, const uint32_t* a,
                                         uint32_t b0, uint32_t b1) {
    asm volatile(
        "mma.sync.aligned.m16n8k16.row.col.f32.f16.f16.f32 "
        "{%0,%1,%2,%3}, {%4,%5,%6,%7}, {%8,%9}, {%0,%1,%2,%3};"
        : "+f"(d[0]), "+f"(d[1]), "+f"(d[2]), "+f"(d[3])
        : "r"(a[0]), "r"(a[1]), "r"(a[2]), "r"(a[3]), "r"(b0), "r"(b1));
}
// fp16 split: pair of floats -> half2 hi + half2 lo (packed u32)
__device__ __forceinline__ void split2h(float x, float y, uint32_t& hi, uint32_t& lo) {
    __half2 h = __floats2half2_rn(x, y);
    float2 f = __half22float2(h);
    __half2 l2 = __floats2half2_rn(x - f.x, y - f.y);
    hi = *reinterpret_cast<uint32_t*>(&h);
    lo = *reinterpret_cast<uint32_t*>(&l2);
}
// pack two floats into one half2 u32 (rn)
__device__ __forceinline__ uint32_t pk2h(float x, float y) {
    __half2 h = __floats2half2_rn(x, y);
    return *reinterpret_cast<uint32_t*>(&h);
}
// 8 fp32 -> uint4 of 8 rn-rounded fp16 (no residual)
__device__ __forceinline__ uint4 cvt8h(const float4& u, const float4& v) {
    __half2 h0 = __floats2half2_rn(u.x, u.y);
    __half2 h1 = __floats2half2_rn(u.z, u.w);
    __half2 h2 = __floats2half2_rn(v.x, v.y);
    __half2 h3 = __floats2half2_rn(v.z, v.w);
    return make_uint4(*(uint32_t*)&h0, *(uint32_t*)&h1, *(uint32_t*)&h2, *(uint32_t*)&h3);
}
// permutation: n' = 128p + 64s + i  ->  orig = 64p + 512s + i
__device__ __forceinline__ int perm_orig(int n) {
    int p = n >> 7, s = (n >> 6) & 1, i = n & 63;
    return 64 * p + 512 * s + i;
}

// ============================================================================
// weight prep: single fp16 (rn-rounded), row-permuted / col-permuted
// ============================================================================
__global__ __launch_bounds__(256) void prep_w_rowperm(
    const float* __restrict__ W, __half* __restrict__ Wh)
{
    int idx = blockIdx.x * 256 + threadIdx.x;   // HID*HID/8
    int n = idx >> 7;
    int c8 = (idx & 127) * 8;
    int orig = perm_orig(n);
    float4 u = *(const float4*)(W + (size_t)orig * HID + c8);
    float4 v = *(const float4*)(W + (size_t)orig * HID + c8 + 4);
    *(uint4*)(Wh + (size_t)n * HID + c8) = cvt8h(u, v);
}

__global__ __launch_bounds__(256) void prep_w_colperm(
    const float* __restrict__ W, __half* __restrict__ Wh)
{
    int idx = blockIdx.x * 256 + threadIdx.x;
    int n = idx >> 7;
    int k8 = (idx & 127) * 8;
    int orig = perm_orig(k8);
    float4 u = *(const float4*)(W + (size_t)n * HID + orig);
    float4 v = *(const float4*)(W + (size_t)n * HID + orig + 4);
    *(uint4*)(Wh + (size_t)n * HID + k8) = cvt8h(u, v);
}

__global__ void make_invf_kernel() {
    int j = threadIdx.x;
    if (j < HID / 2) {
        double e = exp(-((double)(2 * j) / (double)HID) * log(10000.0));
        g_invf[j] = (float)e;
    }
}
__global__ __launch_bounds__(256) void rope_table_kernel() {
    int idx = blockIdx.x * 256 + threadIdx.x;
    int s = idx >> 9;
    int j = idx & 511;
    float t = (float)s * g_invf[j];
    float st, ct;
    sincosf(t, &st, &ct);
    float s1, c1, s2, c2;
    sincosf(st, &s1, &c1);
    sincosf(ct, &s2, &c2);
    g_tab[idx] = make_float4(c1, s1, c2, s2);
}

// ============================================================================
// fused QKV projection, 1-term pure fp16: Y = X*W'^T (+bias +RoPE +scale).
// A = fp32 converted inline to single fp16; B = single fp16 weights.
// CTA 128x128, warp 64x32, K-chunk 32, 2-stage double buffer.
// NOTE: no min-blocks hint (R9 spill regression). Let ptxas allocate freely.
// ============================================================================
#define RSTRIDE 80
#define TILE_B (128 * RSTRIDE)      // 10240
#define STAGE1 (2 * TILE_B)         // 20480 (A, B) for 1-term proj
#define STAGE2 (3 * TILE_B)         // 30720 (Ah, Al, B) for 2-term out
#define GEMM_SMEM 67584             // epilogue fp32 tile 128x132
#define SROW 132

__global__ __launch_bounds__(256)
void gemm_qkv(const float* __restrict__ X, const __half* __restrict__ Bw,
              const float* __restrict__ bias,
              __half* __restrict__ outh, float scale)
{
    extern __shared__ __align__(128) char smem[];

    const int tid  = threadIdx.x;
    const int wid  = tid >> 5;
    const int lane = tid & 31;
    const int wm   = wid & 1;
    const int wn   = wid >> 1;
    const int brow = blockIdx.y * 128;
    const int bcol = blockIdx.x * 128;

    const uint32_t sbase = smem_u32(smem);
    const uint32_t aoff = (uint32_t)(((lane & 7) + ((lane >> 3) & 1) * 8) * RSTRIDE
                                     + ((lane >> 4) & 1) * 16);
    const uint32_t boff = (uint32_t)(((lane & 7) + ((lane >> 4) & 1) * 8) * RSTRIDE
                                     + ((lane >> 3) & 1) * 16);

    const int r0i = tid >> 2;          // rows r0i, r0i+64
    const int ch  = tid & 3;

    const float* Xp = X + (size_t)brow * HID;
    const __half* Bp = Bw + (size_t)bcol * HID;

    float acc[4][4][4];
#pragma unroll
    for (int i = 0; i < 4; i++)
#pragma unroll
        for (int j = 0; j < 4; j++)
#pragma unroll
            for (int r = 0; r < 4; r++) acc[i][j][r] = 0.0f;

    // prologue: chunk 0 -> stage 0
    {
        const size_t ke = (size_t)ch * 8;
        float4 a0 = *(const float4*)(Xp + (size_t)r0i * HID + ke);
        float4 a1 = *(const float4*)(Xp + (size_t)r0i * HID + ke + 4);
        float4 a2 = *(const float4*)(Xp + (size_t)(r0i + 64) * HID + ke);
        float4 a3 = *(const float4*)(Xp + (size_t)(r0i + 64) * HID + ke + 4);
        uint4 b0 = *(const uint4*)(Bp + (size_t)r0i * HID + ke);
        uint4 b1 = *(const uint4*)(Bp + (size_t)(r0i + 64) * HID + ke);
        *(uint4*)(smem + 0 * TILE_B + r0i * RSTRIDE + ch * 16)        = cvt8h(a0, a1);
        *(uint4*)(smem + 0 * TILE_B + (r0i + 64) * RSTRIDE + ch * 16) = cvt8h(a2, a3);
        *(uint4*)(smem + 1 * TILE_B + r0i * RSTRIDE + ch * 16)        = b0;
        *(uint4*)(smem + 1 * TILE_B + (r0i + 64) * RSTRIDE + ch * 16) = b1;
    }
    __syncthreads();

    for (int kc = 0; kc < 32; kc++) {
        const int s = kc & 1;
        const bool has = (kc + 1) < 32;

        float4 pa[4];
        uint4 pb[2];
        if (has) {
            const size_t ke = (size_t)(kc + 1) * 32 + (size_t)ch * 8;
            pa[0] = *(const float4*)(Xp + (size_t)r0i * HID + ke);
            pa[1] = *(const float4*)(Xp + (size_t)r0i * HID + ke + 4);
            pa[2] = *(const float4*)(Xp + (size_t)(r0i + 64) * HID + ke);
            pa[3] = *(const float4*)(Xp + (size_t)(r0i + 64) * HID + ke + 4);
            pb[0] = *(const uint4*)(Bp + (size_t)r0i * HID + ke);
            pb[1] = *(const uint4*)(Bp + (size_t)(r0i + 64) * HID + ke);
        }

        const uint32_t base = sbase + s * STAGE1;
#pragma unroll
        for (int ks = 0; ks < 2; ks++) {
            const uint32_t kb = ks * 32;
            uint32_t ah[4][4];
#pragma unroll
            for (int mf = 0; mf < 4; mf++) {
                uint32_t ro = (uint32_t)((wm * 64 + mf * 16) * RSTRIDE) + kb;
                ldm4(ah[mf], base + ro + aoff);
            }
            uint32_t bh[2][4];
#pragma unroll
            for (int p = 0; p < 2; p++) {
                uint32_t ro = (uint32_t)((wn * 32 + p * 16) * RSTRIDE) + kb;
                ldm4(bh[p], base + TILE_B + ro + boff);
            }
#pragma unroll
            for (int mf = 0; mf < 4; mf++) {
#pragma unroll
                for (int nf = 0; nf < 4; nf++) {
                    const int p = nf >> 1, q = nf & 1;
                    mma16816(acc[mf][nf], ah[mf], bh[p][2 * q], bh[p][2 * q + 1]);
                }
            }
        }

        if (has) {
            char* st = smem + (s ^ 1) * STAGE1;
            *(uint4*)(st + 0 * TILE_B + r0i * RSTRIDE + ch * 16)        = cvt8h(pa[0], pa[1]);
            *(uint4*)(st + 0 * TILE_B + (r0i + 64) * RSTRIDE + ch * 16) = cvt8h(pa[2], pa[3]);
            *(uint4*)(st + 1 * TILE_B + r0i * RSTRIDE + ch * 16)        = pb[0];
            *(uint4*)(st + 1 * TILE_B + (r0i + 64) * RSTRIDE + ch * 16) = pb[1];
        }
        __syncthreads();
    }

    // epilogue: stage fp32 tile, apply bias + RoPE + scale, write fp16
    float* sm = (float*)smem;
    const int g  = lane >> 2;
    const int t2 = (lane & 3) * 2;
#pragma unroll
    for (int mf = 0; mf < 4; mf++) {
        const int lr = wm * 64 + mf * 16 + g;
#pragma unroll
        for (int nf = 0; nf < 4; nf++) {
            const int lc = wn * 32 + nf * 8 + t2;
            *(float2*)(sm + lr * SROW + lc)       = make_float2(acc[mf][nf][0], acc[mf][nf][1]);
            *(float2*)(sm + (lr + 8) * SROW + lc) = make_float2(acc[mf][nf][2], acc[mf][nf][3]);
        }
    }
    __syncthreads();

    const int pblk = bcol >> 7;
#pragma unroll
    for (int it = 0; it < 16; it++) {
        int idx = it * 256 + tid;
        int r  = idx >> 5;
        int c0 = (idx & 31) * 2;
        int srow = (brow + r) & (SEQ - 1);
        int j0 = 64 * pblk + c0;
        float4 t0 = g_tab[(srow << 9) | j0];
        float4 t1 = g_tab[(srow << 9) | (j0 + 1)];
        float x1a = sm[r * SROW + c0]      + bias[j0];
        float x1b = sm[r * SROW + c0 + 1]  + bias[j0 + 1];
        float x2a = sm[r * SROW + c0 + 64] + bias[j0 + 512];
        float x2b = sm[r * SROW + c0 + 65] + bias[j0 + 513];
        float y1a = (x1a * t0.x + x2a * t0.y) * scale;
        float y2a = (x2a * t0.z - x1a * t0.w) * scale;
        float y1b = (x1b * t1.x + x2b * t1.y) * scale;
        float y2b = (x2b * t1.z - x1b * t1.w) * scale;
        size_t gb = (size_t)(brow + r) * HID + bcol;
        *(uint32_t*)(outh + gb + c0)      = pk2h(y1a, y1b);
        *(uint32_t*)(outh + gb + 64 + c0) = pk2h(y2a, y2b);
    }
}

// ============================================================================
// output projection: out = Ctx*Wo'^T + bo (fp32). Ctx = fp16 hi/lo splits.
// ============================================================================
__global__ __launch_bounds__(256)
void gemm_out(const __half* __restrict__ Ahi, const __half* __restrict__ Alo,
              const __half* __restrict__ Bw,
              const float* __restrict__ bias, float* __restrict__ Y)
{
    extern __shared__ __align__(128) char smem[];

    const int tid  = threadIdx.x;
    const int wid  = tid >> 5;
    const int lane = tid & 31;
    const int wm   = wid & 1;
    const int wn   = wid >> 1;
    const int brow = blockIdx.y * 128;
    const int bcol = blockIdx.x * 128;

    const uint32_t sbase = smem_u32(smem);
    const uint32_t aoff = (uint32_t)(((lane & 7) + ((lane >> 3) & 1) * 8) * RSTRIDE
                                     + ((lane >> 4) & 1) * 16);
    const uint32_t boff = (uint32_t)(((lane & 7) + ((lane >> 4) & 1) * 8) * RSTRIDE
                                     + ((lane >> 3) & 1) * 16);

    const int r0i = tid >> 2;
    const int ch  = tid & 3;

    const __half* gptr[3];
    gptr[0] = Ahi + (size_t)brow * HID;
    gptr[1] = Alo + (size_t)brow * HID;
    gptr[2] = Bw  + (size_t)bcol * HID;

    float acc[4][4][4];
#pragma unroll
    for (int i = 0; i < 4; i++)
#pragma unroll
        for (int j = 0; j < 4; j++)
#pragma unroll
            for (int r = 0; r < 4; r++) acc[i][j][r] = 0.0f;

    {
        const size_t ke = (size_t)ch * 8;
#pragma unroll
        for (int t = 0; t < 3; t++) {
            uint4 v0 = *(const uint4*)(gptr[t] + (size_t)r0i * HID + ke);
            uint4 v1 = *(const uint4*)(gptr[t] + (size_t)(r0i + 64) * HID + ke);
            *(uint4*)(smem + t * TILE_B + r0i * RSTRIDE + ch * 16) = v0;
            *(uint4*)(smem + t * TILE_B + (r0i + 64) * RSTRIDE + ch * 16) = v1;
        }
    }
    __syncthreads();

    for (int kc = 0; kc < 32; kc++) {
        const int s = kc & 1;
        const bool has = (kc + 1) < 32;

        uint4 pf[3][2];
        if (has) {
            const size_t ke = (size_t)(kc + 1) * 32 + (size_t)ch * 8;
#pragma unroll
            for (int t = 0; t < 3; t++) {
                pf[t][0] = *(const uint4*)(gptr[t] + (size_t)r0i * HID + ke);
                pf[t][1] = *(const uint4*)(gptr[t] + (size_t)(r0i + 64) * HID + ke);
            }
        }

        const uint32_t base = sbase + s * STAGE2;
#pragma unroll
        for (int ks = 0; ks < 2; ks++) {
            const uint32_t kb = ks * 32;
            uint32_t ah[4][4], al[4][4];
#pragma unroll
            for (int mf = 0; mf < 4; mf++) {
                uint32_t ro = (uint32_t)((wm * 64 + mf * 16) * RSTRIDE) + kb;
                ldm4(ah[mf], base + ro + aoff);
                ldm4(al[mf], base + TILE_B + ro + aoff);
            }
            uint32_t bh[2][4];
#pragma unroll
            for (int p = 0; p < 2; p++) {
                uint32_t ro = (uint32_t)((wn * 32 + p * 16) * RSTRIDE) + kb;
                ldm4(bh[p], base + 2 * TILE_B + ro + boff);
            }
#pragma unroll
            for (int mf = 0; mf < 4; mf++) {
#pragma unroll
                for (int nf = 0; nf < 4; nf++) {
                    const int p = nf >> 1, q = nf & 1;
                    mma16816(acc[mf][nf], ah[mf], bh[p][2 * q], bh[p][2 * q + 1]);
                    mma16816(acc[mf][nf], al[mf], bh[p][2 * q], bh[p][2 * q + 1]);
                }
            }
        }

        if (has) {
            char* st = smem + (s ^ 1) * STAGE2;
#pragma unroll
            for (int t = 0; t < 3; t++) {
                *(uint4*)(st + t * TILE_B + r0i * RSTRIDE + ch * 16) = pf[t][0];
                *(uint4*)(st + t * TILE_B + (r0i + 64) * RSTRIDE + ch * 16) = pf[t][1];
            }
        }
        __syncthreads();
    }

    const int g = lane >> 2;
    const int t2 = (lane & 3) * 2;
#pragma unroll
    for (int mf = 0; mf < 4; mf++) {
        const int row0 = brow + wm * 64 + mf * 16 + g;
#pragma unroll
        for (int nf = 0; nf < 4; nf++) {
            const int col = bcol + wn * 32 + nf * 8 + t2;
            float2 bv = *(const float2*)(bias + col);
            *(float2*)(Y + (size_t)row0 * HID + col) =
                make_float2(acc[mf][nf][0] + bv.x, acc[mf][nf][1] + bv.y);
            *(float2*)(Y + (size_t)(row0 + 8) * HID + col) =
                make_float2(acc[mf][nf][2] + bv.x, acc[mf][nf][3] + bv.y);
        }
    }
}

// ============================================================================
// tensor-core flash attention, pure fp16 operands (Q, K, V, P single fp16).
// cp.async double-buffered K/V stages. Ctx written as fp16 hi/lo splits
// (the kept precision guard for the 2-term output projection).
// ============================================================================
#define AST 144
#define AQ 0
#define AKV0 (128 * AST)              // 18432
#define KVSTG (2 * 64 * AST)          // 18432 (K, V)
#define ATTN_SMEM (AKV0 + 2 * KVSTG)  // 55296

__device__ __forceinline__ void attn_issue_kv(
    int krow0, size_t colbase, uint32_t kvbase, int tid)
{
#pragma unroll
    for (int i = 0; i < 4; i++) {
        const __half* g = (i < 2) ? g_Kh : g_Vh;
        const int arr = i >> 1;
        const int rem = ((i & 1) << 8) + tid;
        const int row = rem >> 3;
        const int c = rem & 7;
        cp16(kvbase + arr * (64 * AST) + row * AST + c * 16,
             g + (size_t)(krow0 + row) * HID + colbase + c * 8);
    }
}

__global__ __launch_bounds__(256, 2) void attn_mma() {
    extern __shared__ __align__(128) char smem[];

    const int tid  = threadIdx.x;
    const int wid  = tid >> 5;
    const int lane = tid & 31;
    const int qt   = blockIdx.x;
    const int bh   = blockIdx.y;
    const int b    = bh >> 4;
    const int h    = bh & 15;
    const int qbase = b * SEQ + qt * 128;
    const size_t colbase = (size_t)h * HD;
    const int krow_base = b * SEQ;

    const uint32_t sb = smem_u32(smem);

    const uint32_t aoff = (uint32_t)(((lane & 7) + ((lane >> 3) & 1) * 8) * AST
                                     + ((lane >> 4) & 1) * 16);
    const uint32_t boff = (uint32_t)(((lane & 7) + ((lane >> 4) & 1) * 8) * AST
                                     + ((lane >> 3) & 1) * 16);
    const uint32_t voff = (uint32_t)(((lane & 7) + ((lane >> 3) & 1) * 8) * AST
                                     + ((lane >> 4) & 1) * 16);

    // group 0: Q + KV stage 0
#pragma unroll
    for (int i = 0; i < 4; i++) {
        const int rem = (i << 8) + tid;
        const int row = rem >> 3;
        const int c = rem & 7;
        cp16(sb + AQ + row * AST + c * 16,
             g_Qh + (size_t)(qbase + row) * HID + colbase + c * 8);
    }
    attn_issue_kv(krow_base, colbase, sb + AKV0, tid);
    CP_COMMIT();
    attn_issue_kv(krow_base + 64, colbase, sb + AKV0 + KVSTG, tid);
    CP_COMMIT();

    float o[8][4];
#pragma unroll
    for (int nf = 0; nf < 8; nf++)
#pragma unroll
        for (int r = 0; r < 4; r++) o[nf][r] = 0.0f;
    float m0 = -1e30f, m1 = -1e30f, l0 = 0.0f, l1 = 0.0f;

    const uint32_t qrow_off = (uint32_t)(wid * 16 * AST);

    for (int kt = 0; kt < 16; kt++) {
        const int s = kt & 1;
        CP_WAIT1();
        __syncthreads();

        const uint32_t kvb = sb + AKV0 + s * KVSTG;
        const uint32_t akh = kvb;
        const uint32_t avh = kvb + 64 * AST;

        float sfr[8][4];
#pragma unroll
        for (int nf = 0; nf < 8; nf++)
#pragma unroll
            for (int r = 0; r < 4; r++) sfr[nf][r] = 0.0f;

#pragma unroll
        for (int kq = 0; kq < 4; kq++) {
            uint32_t qh[4];
            ldm4(qh, sb + AQ + qrow_off + kq * 32 + aoff);
            uint32_t kh[4][4];
#pragma unroll
            for (int p = 0; p < 4; p++)
                ldm4(kh[p], akh + (uint32_t)(p * 16 * AST) + kq * 32 + boff);
#pragma unroll
            for (int nf = 0; nf < 8; nf++) {
                const int p = nf >> 1, q = nf & 1;
                mma16816(sfr[nf], qh, kh[p][2 * q], kh[p][2 * q + 1]);
            }
        }

        float mx0 = -1e30f, mx1 = -1e30f;
#pragma unroll
        for (int nf = 0; nf < 8; nf++) {
            mx0 = fmaxf(mx0, fmaxf(sfr[nf][0], sfr[nf][1]));
            mx1 = fmaxf(mx1, fmaxf(sfr[nf][2], sfr[nf][3]));
        }
        mx0 = fmaxf(mx0, __shfl_xor_sync(0xFFFFFFFF, mx0, 1));
        mx0 = fmaxf(mx0, __shfl_xor_sync(0xFFFFFFFF, mx0, 2));
        mx1 = fmaxf(mx1, __shfl_xor_sync(0xFFFFFFFF, mx1, 1));
        mx1 = fmaxf(mx1, __shfl_xor_sync(0xFFFFFFFF, mx1, 2));

        float mn0 = fmaxf(m0, mx0), mn1 = fmaxf(m1, mx1);
        float c0 = __expf(m0 - mn0), c1 = __expf(m1 - mn1);
        l0 *= c0; l1 *= c1;
#pragma unroll
        for (int nf = 0; nf < 8; nf++) {
            o[nf][0] *= c0; o[nf][1] *= c0;
            o[nf][2] *= c1; o[nf][3] *= c1;
        }
#pragma unroll
        for (int nf = 0; nf < 8; nf++) {
            sfr[nf][0] = __expf(sfr[nf][0] - mn0);
            sfr[nf][1] = __expf(sfr[nf][1] - mn0);
            sfr[nf][2] = __expf(sfr[nf][2] - mn1);
            sfr[nf][3] = __expf(sfr[nf][3] - mn1);
            l0 += sfr[nf][0] + sfr[nf][1];
            l1 += sfr[nf][2] + sfr[nf][3];
        }
        m0 = mn0; m1 = mn1;

#pragma unroll
        for (int kk = 0; kk < 4; kk++) {
            uint32_t ah[4];
            ah[0] = pk2h(sfr[2 * kk][0],     sfr[2 * kk][1]);
            ah[1] = pk2h(sfr[2 * kk][2],     sfr[2 * kk][3]);
            ah[2] = pk2h(sfr[2 * kk + 1][0], sfr[2 * kk + 1][1]);
            ah[3] = pk2h(sfr[2 * kk + 1][2], sfr[2 * kk + 1][3]);

            uint32_t vh[4][4];
#pragma unroll
            for (int p = 0; p < 4; p++) {
                uint32_t ro = (uint32_t)(kk * 16 * AST) + (uint32_t)(p * 32);
                ldm4t(vh[p], avh + ro + voff);
            }
#pragma unroll
            for (int nf = 0; nf < 8; nf++) {
                const int p = nf >> 1, q = nf & 1;
                mma16816(o[nf], ah, vh[p][2 * q], vh[p][2 * q + 1]);
            }
        }

        __syncthreads();
        if (kt + 2 < 16)
            attn_issue_kv(krow_base + (kt + 2) * 64, colbase,
                          sb + AKV0 + s * KVSTG, tid);
        CP_COMMIT();
    }

    l0 += __shfl_xor_sync(0xFFFFFFFF, l0, 1);
    l0 += __shfl_xor_sync(0xFFFFFFFF, l0, 2);
    l1 += __shfl_xor_sync(0xFFFFFFFF, l1, 1);
    l1 += __shfl_xor_sync(0xFFFFFFFF, l1, 2);
    float inv0 = 1.0f / l0, inv1 = 1.0f / l1;

    const int g  = lane >> 2;
    const int t2 = (lane & 3) * 2;
    const int row0 = qbase + wid * 16 + g;
#pragma unroll
    for (int nf = 0; nf < 8; nf++) {
        size_t col = colbase + nf * 8 + t2;
        uint32_t hi, lo;
        split2h(o[nf][0] * inv0, o[nf][1] * inv0, hi, lo);
        *(uint32_t*)(g_Ahi + (size_t)row0 * HID + col) = hi;
        *(uint32_t*)(g_Alo + (size_t)row0 * HID + col) = lo;
        split2h(o[nf][2] * inv1, o[nf][3] * inv1, hi, lo);
        *(uint32_t*)(g_Ahi + (size_t)(row0 + 8) * HID + col) = hi;
        *(uint32_t*)(g_Alo + (size_t)(row0 + 8) * HID + col) = lo;
    }
}

// ============================================================================
// launch
// ============================================================================
extern "C" void kernel_launch(void* const* d_in, const int* in_sizes, int n_in,
                              void* d_out, int out_size) {
    (void)in_sizes; (void)n_in; (void)out_size;
    const float* query = (const float*)d_in[0];
    const float* key   = (const float*)d_in[1];
    const float* value = (const float*)d_in[2];
    const float* Wq    = (const float*)d_in[3];
    const float* bq    = (const float*)d_in[4];
    const float* Wk    = (const float*)d_in[5];
    const float* bk    = (const float*)d_in[6];
    const float* Wv    = (const float*)d_in[7];
    const float* bv    = (const float*)d_in[8];
    const float* Wo    = (const float*)d_in[9];
    const float* bo    = (const float*)d_in[10];
    float* out = (float*)d_out;

    __half *Qh, *Kh, *Vh, *Ahi, *Alo, *Wqh, *Wkh, *Wvh, *Woh;
    cudaGetSymbolAddress((void**)&Qh, g_Qh);
    cudaGetSymbolAddress((void**)&Kh, g_Kh);   cudaGetSymbolAddress((void**)&Vh, g_Vh);
    cudaGetSymbolAddress((void**)&Ahi, g_Ahi); cudaGetSymbolAddress((void**)&Alo, g_Alo);
    cudaGetSymbolAddress((void**)&Wqh, g_Wqh); cudaGetSymbolAddress((void**)&Wkh, g_Wkh);
    cudaGetSymbolAddress((void**)&Wvh, g_Wvh); cudaGetSymbolAddress((void**)&Woh, g_Woh);

    cudaFuncSetAttribute(gemm_qkv, cudaFuncAttributeMaxDynamicSharedMemorySize, GEMM_SMEM);
    cudaFuncSetAttribute(gemm_out, cudaFuncAttributeMaxDynamicSharedMemorySize, GEMM_SMEM);
    cudaFuncSetAttribute(attn_mma, cudaFuncAttributeMaxDynamicSharedMemorySize, ATTN_SMEM);

    dim3 ggrid(HID / 128, MROWS / 128);
    const int wblocks = (HID * HID / 8) / 256;   // 512

    make_invf_kernel<<<1, 512>>>();
    rope_table_kernel<<<(SEQ * 512) / 256, 256>>>();

    prep_w_rowperm<<<wblocks, 256>>>(Wq, Wqh);
    prep_w_rowperm<<<wblocks, 256>>>(Wk, Wkh);
    prep_w_rowperm<<<wblocks, 256>>>(Wv, Wvh);
    prep_w_colperm<<<wblocks, 256>>>(Wo, Woh);

    gemm_qkv<<<ggrid, 256, GEMM_SMEM>>>(query, Wqh, bq, Qh, 0.125f);
    gemm_qkv<<<ggrid, 256, GEMM_SMEM>>>(key,   Wkh, bk, Kh, 1.0f);
    gemm_qkv<<<ggrid, 256, GEMM_SMEM>>>(value, Wvh, bv, Vh, 1.0f);

    attn_mma<<<dim3(8, 128), 256, ATTN_SMEM>>>();

    gemm_out<<<ggrid, 256, GEMM_SMEM>>>(Ahi, Alo, Woh, bo, out);
}

// round 12
// speedup vs baseline: 1.8728x; 1.1017x over previous
#include <cuda_runtime.h>
#include <cuda_fp16.h>
#include <cstdint>

#define HID 1024
#define HEADS 16
#define HD 64
#define BATCH 8
#define SEQ 1024
#define MROWS (BATCH * SEQ)

// ---------------- scratch (device globals; no allocation allowed) ----------
__device__ __half g_Qh[MROWS * HID];
__device__ __half g_Kh[MROWS * HID];
__device__ __half g_Vh[MROWS * HID];
__device__ __half g_Ctx[MROWS * HID];
__device__ __half g_Wqh[HID * HID];
__device__ __half g_Wkh[HID * HID];
__device__ __half g_Wvh[HID * HID];
__device__ __half g_Woh[HID * HID];
__device__ float g_invf[HID / 2];
__device__ float4 g_tab[SEQ * (HID / 2)];

// ---------------- helpers ----------------------------------------
__device__ __forceinline__ uint32_t smem_u32(const void* p) {
    uint32_t a;
    asm("{ .reg .u64 t; cvta.to.shared.u64 t, %1; cvt.u32.u64 %0, t; }"
        : "=r"(a) : "l"(p));
    return a;
}
__device__ __forceinline__ void cp16(uint32_t dst, const void* src) {
    asm volatile("cp.async.cg.shared.global [%0], [%1], 16;" :: "r"(dst), "l"(src));
}
#define CP_COMMIT() asm volatile("cp.async.commit_group;" ::: "memory")
#define CP_WAIT1()  asm volatile("cp.async.wait_group 1;" ::: "memory")

__device__ __forceinline__ void ldm4(uint32_t* r, uint32_t addr) {
    asm volatile("ldmatrix.sync.aligned.m8n8.x4.shared.b16 {%0,%1,%2,%3}, [%4];"
                 : "=r"(r[0]), "=r"(r[1]), "=r"(r[2]), "=r"(r[3]) : "r"(addr));
}
__device__ __forceinline__ void ldm4t(uint32_t* r, uint32_t addr) {
    asm volatile("ldmatrix.sync.aligned.m8n8.x4.trans.shared.b16 {%0,%1,%2,%3}, [%4];"
                 : "=r"(r[0]), "=r"(r[1]), "=r"(r[2]), "=r"(r[3]) : "r"(addr));
}
__device__ __forceinline__ void mma16816(float* d, const uint32_t* a,
                                         uint32_t b0, uint32_t b1) {
    asm volatile(
        "mma.sync.aligned.m16n8k16.row.col.f32.f16.f16.f32 "
        "{%0,%1,%2,%3}, {%4,%5,%6,%7}, {%8,%9}, {%0,%1,%2,%3};"
        : "+f"(d[0]), "+f"(d[1]), "+f"(d[2]), "+f"(d[3])
        : "r"(a[0]), "r"(a[1]), "r"(a[2]), "r"(a[3]), "r"(b0), "r"(b1));
}
// pack two floats into one half2 u32 (rn)
__device__ __forceinline__ uint32_t pk2h(float x, float y) {
    __half2 h = __floats2half2_rn(x, y);
    return *reinterpret_cast<uint32_t*>(&h);
}
// 8 fp32 -> uint4 of 8 rn-rounded fp16
__device__ __forceinline__ uint4 cvt8h(const float4& u, const float4& v) {
    __half2 h0 = __floats2half2_rn(u.x, u.y);
    __half2 h1 = __floats2half2_rn(u.z, u.w);
    __half2 h2 = __floats2half2_rn(v.x, v.y);
    __half2 h3 = __floats2half2_rn(v.z, v.w);
    return make_uint4(*(uint32_t*)&h0, *(uint32_t*)&h1, *(uint32_t*)&h2, *(uint32_t*)&h3);
}
// permutation: n' = 128p + 64s + i  ->  orig = 64p + 512s + i
__device__ __forceinline__ int perm_orig(int n) {
    int p = n >> 7, s = (n >> 6) & 1, i = n & 63;
    return 64 * p + 512 * s + i;
}

// ============================================================================
// weight prep: all three QKV weights in one launch (row-permuted fp16)
// ============================================================================
__global__ __launch_bounds__(256) void prep_w_qkv(
    const float* __restrict__ Wq, const float* __restrict__ Wk,
    const float* __restrict__ Wv)
{
    const float* W = (blockIdx.y == 0) ? Wq : (blockIdx.y == 1) ? Wk : Wv;
    __half* Wh = (blockIdx.y == 0) ? g_Wqh : (blockIdx.y == 1) ? g_Wkh : g_Wvh;
    int idx = blockIdx.x * 256 + threadIdx.x;   // HID*HID/8
    int n = idx >> 7;
    int c8 = (idx & 127) * 8;
    int orig = perm_orig(n);
    float4 u = *(const float4*)(W + (size_t)orig * HID + c8);
    float4 v = *(const float4*)(W + (size_t)orig * HID + c8 + 4);
    *(uint4*)(Wh + (size_t)n * HID + c8) = cvt8h(u, v);
}

__global__ __launch_bounds__(256) void prep_w_colperm(
    const float* __restrict__ W, __half* __restrict__ Wh)
{
    int idx = blockIdx.x * 256 + threadIdx.x;
    int n = idx >> 7;
    int k8 = (idx & 127) * 8;
    int orig = perm_orig(k8);
    float4 u = *(const float4*)(W + (size_t)n * HID + orig);
    float4 v = *(const float4*)(W + (size_t)n * HID + orig + 4);
    *(uint4*)(Wh + (size_t)n * HID + k8) = cvt8h(u, v);
}

__global__ void make_invf_kernel() {
    int j = threadIdx.x;
    if (j < HID / 2) {
        double e = exp(-((double)(2 * j) / (double)HID) * log(10000.0));
        g_invf[j] = (float)e;
    }
}
__global__ __launch_bounds__(256) void rope_table_kernel() {
    int idx = blockIdx.x * 256 + threadIdx.x;
    int s = idx >> 9;
    int j = idx & 511;
    float t = (float)s * g_invf[j];
    float st, ct;
    sincosf(t, &st, &ct);
    float s1, c1, s2, c2;
    sincosf(st, &s1, &c1);
    sincosf(ct, &s2, &c2);
    g_tab[idx] = make_float4(c1, s1, c2, s2);
}

// ============================================================================
// fused QKV projection, 1-term pure fp16: Y = X*W'^T (+bias +RoPE +scale).
// CTA 128x128, warp 64x32, K-chunk 32, 2-stage double buffer.
// NOTE: no min-blocks hint (R9 spill regression).
// ============================================================================
#define RSTRIDE 80
#define TILE_B (128 * RSTRIDE)      // 10240
#define STAGE1 (2 * TILE_B)         // 20480 (A, B)
#define GEMM_SMEM 67584             // epilogue fp32 tile 128x132
#define SROW 132

__global__ __launch_bounds__(256)
void gemm_qkv(const float* __restrict__ X, const __half* __restrict__ Bw,
              const float* __restrict__ bias,
              __half* __restrict__ outh, float scale)
{
    extern __shared__ __align__(128) char smem[];

    const int tid  = threadIdx.x;
    const int wid  = tid >> 5;
    const int lane = tid & 31;
    const int wm   = wid & 1;
    const int wn   = wid >> 1;
    const int brow = blockIdx.y * 128;
    const int bcol = blockIdx.x * 128;

    const uint32_t sbase = smem_u32(smem);
    const uint32_t aoff = (uint32_t)(((lane & 7) + ((lane >> 3) & 1) * 8) * RSTRIDE
                                     + ((lane >> 4) & 1) * 16);
    const uint32_t boff = (uint32_t)(((lane & 7) + ((lane >> 4) & 1) * 8) * RSTRIDE
                                     + ((lane >> 3) & 1) * 16);

    const int r0i = tid >> 2;          // rows r0i, r0i+64
    const int ch  = tid & 3;

    const float* Xp = X + (size_t)brow * HID;
    const __half* Bp = Bw + (size_t)bcol * HID;

    float acc[4][4][4];
#pragma unroll
    for (int i = 0; i < 4; i++)
#pragma unroll
        for (int j = 0; j < 4; j++)
#pragma unroll
            for (int r = 0; r < 4; r++) acc[i][j][r] = 0.0f;

    // prologue: chunk 0 -> stage 0
    {
        const size_t ke = (size_t)ch * 8;
        float4 a0 = *(const float4*)(Xp + (size_t)r0i * HID + ke);
        float4 a1 = *(const float4*)(Xp + (size_t)r0i * HID + ke + 4);
        float4 a2 = *(const float4*)(Xp + (size_t)(r0i + 64) * HID + ke);
        float4 a3 = *(const float4*)(Xp + (size_t)(r0i + 64) * HID + ke + 4);
        uint4 b0 = *(const uint4*)(Bp + (size_t)r0i * HID + ke);
        uint4 b1 = *(const uint4*)(Bp + (size_t)(r0i + 64) * HID + ke);
        *(uint4*)(smem + 0 * TILE_B + r0i * RSTRIDE + ch * 16)        = cvt8h(a0, a1);
        *(uint4*)(smem + 0 * TILE_B + (r0i + 64) * RSTRIDE + ch * 16) = cvt8h(a2, a3);
        *(uint4*)(smem + 1 * TILE_B + r0i * RSTRIDE + ch * 16)        = b0;
        *(uint4*)(smem + 1 * TILE_B + (r0i + 64) * RSTRIDE + ch * 16) = b1;
    }
    __syncthreads();

    for (int kc = 0; kc < 32; kc++) {
        const int s = kc & 1;
        const bool has = (kc + 1) < 32;

        float4 pa[4];
        uint4 pb[2];
        if (has) {
            const size_t ke = (size_t)(kc + 1) * 32 + (size_t)ch * 8;
            pa[0] = *(const float4*)(Xp + (size_t)r0i * HID + ke);
            pa[1] = *(const float4*)(Xp + (size_t)r0i * HID + ke + 4);
            pa[2] = *(const float4*)(Xp + (size_t)(r0i + 64) * HID + ke);
            pa[3] = *(const float4*)(Xp + (size_t)(r0i + 64) * HID + ke + 4);
            pb[0] = *(const uint4*)(Bp + (size_t)r0i * HID + ke);
            pb[1] = *(const uint4*)(Bp + (size_t)(r0i + 64) * HID + ke);
        }

        const uint32_t base = sbase + s * STAGE1;
#pragma unroll
        for (int ks = 0; ks < 2; ks++) {
            const uint32_t kb = ks * 32;
            uint32_t ah[4][4];
#pragma unroll
            for (int mf = 0; mf < 4; mf++) {
                uint32_t ro = (uint32_t)((wm * 64 + mf * 16) * RSTRIDE) + kb;
                ldm4(ah[mf], base + ro + aoff);
            }
            uint32_t bh[2][4];
#pragma unroll
            for (int p = 0; p < 2; p++) {
                uint32_t ro = (uint32_t)((wn * 32 + p * 16) * RSTRIDE) + kb;
                ldm4(bh[p], base + TILE_B + ro + boff);
            }
#pragma unroll
            for (int mf = 0; mf < 4; mf++) {
#pragma unroll
                for (int nf = 0; nf < 4; nf++) {
                    const int p = nf >> 1, q = nf & 1;
                    mma16816(acc[mf][nf], ah[mf], bh[p][2 * q], bh[p][2 * q + 1]);
                }
            }
        }

        if (has) {
            char* st = smem + (s ^ 1) * STAGE1;
            *(uint4*)(st + 0 * TILE_B + r0i * RSTRIDE + ch * 16)        = cvt8h(pa[0], pa[1]);
            *(uint4*)(st + 0 * TILE_B + (r0i + 64) * RSTRIDE + ch * 16) = cvt8h(pa[2], pa[3]);
            *(uint4*)(st + 1 * TILE_B + r0i * RSTRIDE + ch * 16)        = pb[0];
            *(uint4*)(st + 1 * TILE_B + (r0i + 64) * RSTRIDE + ch * 16) = pb[1];
        }
        __syncthreads();
    }

    // epilogue: stage fp32 tile, apply bias + RoPE + scale, write fp16
    float* sm = (float*)smem;
    const int g  = lane >> 2;
    const int t2 = (lane & 3) * 2;
#pragma unroll
    for (int mf = 0; mf < 4; mf++) {
        const int lr = wm * 64 + mf * 16 + g;
#pragma unroll
        for (int nf = 0; nf < 4; nf++) {
            const int lc = wn * 32 + nf * 8 + t2;
            *(float2*)(sm + lr * SROW + lc)       = make_float2(acc[mf][nf][0], acc[mf][nf][1]);
            *(float2*)(sm + (lr + 8) * SROW + lc) = make_float2(acc[mf][nf][2], acc[mf][nf][3]);
        }
    }
    __syncthreads();

    const int pblk = bcol >> 7;
#pragma unroll
    for (int it = 0; it < 16; it++) {
        int idx = it * 256 + tid;
        int r  = idx >> 5;
        int c0 = (idx & 31) * 2;
        int srow = (brow + r) & (SEQ - 1);
        int j0 = 64 * pblk + c0;
        float4 t0 = g_tab[(srow << 9) | j0];
        float4 t1 = g_tab[(srow << 9) | (j0 + 1)];
        float x1a = sm[r * SROW + c0]      + bias[j0];
        float x1b = sm[r * SROW + c0 + 1]  + bias[j0 + 1];
        float x2a = sm[r * SROW + c0 + 64] + bias[j0 + 512];
        float x2b = sm[r * SROW + c0 + 65] + bias[j0 + 513];
        float y1a = (x1a * t0.x + x2a * t0.y) * scale;
        float y2a = (x2a * t0.z - x1a * t0.w) * scale;
        float y1b = (x1b * t1.x + x2b * t1.y) * scale;
        float y2b = (x2b * t1.z - x1b * t1.w) * scale;
        size_t gb = (size_t)(brow + r) * HID + bcol;
        *(uint32_t*)(outh + gb + c0)      = pk2h(y1a, y1b);
        *(uint32_t*)(outh + gb + 64 + c0) = pk2h(y2a, y2b);
    }
}

// ============================================================================
// output projection, 1-term: out = Ctx*Wo'^T + bo (fp32). Ctx single fp16.
// ============================================================================
__global__ __launch_bounds__(256)
void gemm_out(const __half* __restrict__ Actx, const __half* __restrict__ Bw,
              const float* __restrict__ bias, float* __restrict__ Y)
{
    extern __shared__ __align__(128) char smem[];

    const int tid  = threadIdx.x;
    const int wid  = tid >> 5;
    const int lane = tid & 31;
    const int wm   = wid & 1;
    const int wn   = wid >> 1;
    const int brow = blockIdx.y * 128;
    const int bcol = blockIdx.x * 128;

    const uint32_t sbase = smem_u32(smem);
    const uint32_t aoff = (uint32_t)(((lane & 7) + ((lane >> 3) & 1) * 8) * RSTRIDE
                                     + ((lane >> 4) & 1) * 16);
    const uint32_t boff = (uint32_t)(((lane & 7) + ((lane >> 4) & 1) * 8) * RSTRIDE
                                     + ((lane >> 3) & 1) * 16);

    const int r0i = tid >> 2;
    const int ch  = tid & 3;

    const __half* Ap = Actx + (size_t)brow * HID;
    const __half* Bp = Bw + (size_t)bcol * HID;

    float acc[4][4][4];
#pragma unroll
    for (int i = 0; i < 4; i++)
#pragma unroll
        for (int j = 0; j < 4; j++)
#pragma unroll
            for (int r = 0; r < 4; r++) acc[i][j][r] = 0.0f;

    {
        const size_t ke = (size_t)ch * 8;
        *(uint4*)(smem + 0 * TILE_B + r0i * RSTRIDE + ch * 16) =
            *(const uint4*)(Ap + (size_t)r0i * HID + ke);
        *(uint4*)(smem + 0 * TILE_B + (r0i + 64) * RSTRIDE + ch * 16) =
            *(const uint4*)(Ap + (size_t)(r0i + 64) * HID + ke);
        *(uint4*)(smem + 1 * TILE_B + r0i * RSTRIDE + ch * 16) =
            *(const uint4*)(Bp + (size_t)r0i * HID + ke);
        *(uint4*)(smem + 1 * TILE_B + (r0i + 64) * RSTRIDE + ch * 16) =
            *(const uint4*)(Bp + (size_t)(r0i + 64) * HID + ke);
    }
    __syncthreads();

    for (int kc = 0; kc < 32; kc++) {
        const int s = kc & 1;
        const bool has = (kc + 1) < 32;

        uint4 pf[2][2];
        if (has) {
            const size_t ke = (size_t)(kc + 1) * 32 + (size_t)ch * 8;
            pf[0][0] = *(const uint4*)(Ap + (size_t)r0i * HID + ke);
            pf[0][1] = *(const uint4*)(Ap + (size_t)(r0i + 64) * HID + ke);
            pf[1][0] = *(const uint4*)(Bp + (size_t)r0i * HID + ke);
            pf[1][1] = *(const uint4*)(Bp + (size_t)(r0i + 64) * HID + ke);
        }

        const uint32_t base = sbase + s * STAGE1;
#pragma unroll
        for (int ks = 0; ks < 2; ks++) {
            const uint32_t kb = ks * 32;
            uint32_t ah[4][4];
#pragma unroll
            for (int mf = 0; mf < 4; mf++) {
                uint32_t ro = (uint32_t)((wm * 64 + mf * 16) * RSTRIDE) + kb;
                ldm4(ah[mf], base + ro + aoff);
            }
            uint32_t bh[2][4];
#pragma unroll
            for (int p = 0; p < 2; p++) {
                uint32_t ro = (uint32_t)((wn * 32 + p * 16) * RSTRIDE) + kb;
                ldm4(bh[p], base + TILE_B + ro + boff);
            }
#pragma unroll
            for (int mf = 0; mf < 4; mf++) {
#pragma unroll
                for (int nf = 0; nf < 4; nf++) {
                    const int p = nf >> 1, q = nf & 1;
                    mma16816(acc[mf][nf], ah[mf], bh[p][2 * q], bh[p][2 * q + 1]);
                }
            }
        }

        if (has) {
            char* st = smem + (s ^ 1) * STAGE1;
            *(uint4*)(st + 0 * TILE_B + r0i * RSTRIDE + ch * 16)        = pf[0][0];
            *(uint4*)(st + 0 * TILE_B + (r0i + 64) * RSTRIDE + ch * 16) = pf[0][1];
            *(uint4*)(st + 1 * TILE_B + r0i * RSTRIDE + ch * 16)        = pf[1][0];
            *(uint4*)(st + 1 * TILE_B + (r0i + 64) * RSTRIDE + ch * 16) = pf[1][1];
        }
        __syncthreads();
    }

    const int g = lane >> 2;
    const int t2 = (lane & 3) * 2;
#pragma unroll
    for (int mf = 0; mf < 4; mf++) {
        const int row0 = brow + wm * 64 + mf * 16 + g;
#pragma unroll
        for (int nf = 0; nf < 4; nf++) {
            const int col = bcol + wn * 32 + nf * 8 + t2;
            float2 bv = *(const float2*)(bias + col);
            *(float2*)(Y + (size_t)row0 * HID + col) =
                make_float2(acc[mf][nf][0] + bv.x, acc[mf][nf][1] + bv.y);
            *(float2*)(Y + (size_t)(row0 + 8) * HID + col) =
                make_float2(acc[mf][nf][2] + bv.x, acc[mf][nf][3] + bv.y);
        }
    }
}

// ============================================================================
// tensor-core flash attention, pure fp16 operands.
// cp.async double-buffered K/V stages. Ctx written as single fp16.
// ============================================================================
#define AST 144
#define AQ 0
#define AKV0 (128 * AST)              // 18432
#define KVSTG (2 * 64 * AST)          // 18432 (K, V)
#define ATTN_SMEM (AKV0 + 2 * KVSTG)  // 55296

__device__ __forceinline__ void attn_issue_kv(
    int krow0, size_t colbase, uint32_t kvbase, int tid)
{
#pragma unroll
    for (int i = 0; i < 4; i++) {
        const __half* g = (i < 2) ? g_Kh : g_Vh;
        const int arr = i >> 1;
        const int rem = ((i & 1) << 8) + tid;
        const int row = rem >> 3;
        const int c = rem & 7;
        cp16(kvbase + arr * (64 * AST) + row * AST + c * 16,
             g + (size_t)(krow0 + row) * HID + colbase + c * 8);
    }
}

__global__ __launch_bounds__(256, 2) void attn_mma() {
    extern __shared__ __align__(128) char smem[];

    const int tid  = threadIdx.x;
    const int wid  = tid >> 5;
    const int lane = tid & 31;
    const int qt   = blockIdx.x;
    const int bh   = blockIdx.y;
    const int b    = bh >> 4;
    const int h    = bh & 15;
    const int qbase = b * SEQ + qt * 128;
    const size_t colbase = (size_t)h * HD;
    const int krow_base = b * SEQ;

    const uint32_t sb = smem_u32(smem);

    const uint32_t aoff = (uint32_t)(((lane & 7) + ((lane >> 3) & 1) * 8) * AST
                                     + ((lane >> 4) & 1) * 16);
    const uint32_t boff = (uint32_t)(((lane & 7) + ((lane >> 4) & 1) * 8) * AST
                                     + ((lane >> 3) & 1) * 16);
    const uint32_t voff = (uint32_t)(((lane & 7) + ((lane >> 3) & 1) * 8) * AST
                                     + ((lane >> 4) & 1) * 16);

    // group 0: Q + KV stage 0
#pragma unroll
    for (int i = 0; i < 4; i++) {
        const int rem = (i << 8) + tid;
        const int row = rem >> 3;
        const int c = rem & 7;
        cp16(sb + AQ + row * AST + c * 16,
             g_Qh + (size_t)(qbase + row) * HID + colbase + c * 8);
    }
    attn_issue_kv(krow_base, colbase, sb + AKV0, tid);
    CP_COMMIT();
    attn_issue_kv(krow_base + 64, colbase, sb + AKV0 + KVSTG, tid);
    CP_COMMIT();

    float o[8][4];
#pragma unroll
    for (int nf = 0; nf < 8; nf++)
#pragma unroll
        for (int r = 0; r < 4; r++) o[nf][r] = 0.0f;
    float m0 = -1e30f, m1 = -1e30f, l0 = 0.0f, l1 = 0.0f;

    const uint32_t qrow_off = (uint32_t)(wid * 16 * AST);

    for (int kt = 0; kt < 16; kt++) {
        const int s = kt & 1;
        CP_WAIT1();
        __syncthreads();

        const uint32_t kvb = sb + AKV0 + s * KVSTG;
        const uint32_t akh = kvb;
        const uint32_t avh = kvb + 64 * AST;

        float sfr[8][4];
#pragma unroll
        for (int nf = 0; nf < 8; nf++)
#pragma unroll
            for (int r = 0; r < 4; r++) sfr[nf][r] = 0.0f;

#pragma unroll
        for (int kq = 0; kq < 4; kq++) {
            uint32_t qh[4];
            ldm4(qh, sb + AQ + qrow_off + kq * 32 + aoff);
            uint32_t kh[4][4];
#pragma unroll
            for (int p = 0; p < 4; p++)
                ldm4(kh[p], akh + (uint32_t)(p * 16 * AST) + kq * 32 + boff);
#pragma unroll
            for (int nf = 0; nf < 8; nf++) {
                const int p = nf >> 1, q = nf & 1;
                mma16816(sfr[nf], qh, kh[p][2 * q], kh[p][2 * q + 1]);
            }
        }

        float mx0 = -1e30f, mx1 = -1e30f;
#pragma unroll
        for (int nf = 0; nf < 8; nf++) {
            mx0 = fmaxf(mx0, fmaxf(sfr[nf][0], sfr[nf][1]));
            mx1 = fmaxf(mx1, fmaxf(sfr[nf][2], sfr[nf][3]));
        }
        mx0 = fmaxf(mx0, __shfl_xor_sync(0xFFFFFFFF, mx0, 1));
        mx0 = fmaxf(mx0, __shfl_xor_sync(0xFFFFFFFF, mx0, 2));
        mx1 = fmaxf(mx1, __shfl_xor_sync(0xFFFFFFFF, mx1, 1));
        mx1 = fmaxf(mx1, __shfl_xor_sync(0xFFFFFFFF, mx1, 2));

        float mn0 = fmaxf(m0, mx0), mn1 = fmaxf(m1, mx1);
        float c0 = __expf(m0 - mn0), c1 = __expf(m1 - mn1);
        l0 *= c0; l1 *= c1;
#pragma unroll
        for (int nf = 0; nf < 8; nf++) {
            o[nf][0] *= c0; o[nf][1] *= c0;
            o[nf][2] *= c1; o[nf][3] *= c1;
        }
#pragma unroll
        for (int nf = 0; nf < 8; nf++) {
            sfr[nf][0] = __expf(sfr[nf][0] - mn0);
            sfr[nf][1] = __expf(sfr[nf][1] - mn0);
            sfr[nf][2] = __expf(sfr[nf][2] - mn1);
            sfr[nf][3] = __expf(sfr[nf][3] - mn1);
            l0 += sfr[nf][0] + sfr[nf][1];
            l1 += sfr[nf][2] + sfr[nf][3];
        }
        m0 = mn0; m1 = mn1;

#pragma unroll
        for (int kk = 0; kk < 4; kk++) {
            uint32_t ah[4];
            ah[0] = pk2h(sfr[2 * kk][0],     sfr[2 * kk][1]);
            ah[1] = pk2h(sfr[2 * kk][2],     sfr[2 * kk][3]);
            ah[2] = pk2h(sfr[2 * kk + 1][0], sfr[2 * kk + 1][1]);
            ah[3] = pk2h(sfr[2 * kk + 1][2], sfr[2 * kk + 1][3]);

            uint32_t vh[4][4];
#pragma unroll
            for (int p = 0; p < 4; p++) {
                uint32_t ro = (uint32_t)(kk * 16 * AST) + (uint32_t)(p * 32);
                ldm4t(vh[p], avh + ro + voff);
            }
#pragma unroll
            for (int nf = 0; nf < 8; nf++) {
                const int p = nf >> 1, q = nf & 1;
                mma16816(o[nf], ah, vh[p][2 * q], vh[p][2 * q + 1]);
            }
        }

        __syncthreads();
        if (kt + 2 < 16)
            attn_issue_kv(krow_base + (kt + 2) * 64, colbase,
                          sb + AKV0 + s * KVSTG, tid);
        CP_COMMIT();
    }

    l0 += __shfl_xor_sync(0xFFFFFFFF, l0, 1);
    l0 += __shfl_xor_sync(0xFFFFFFFF, l0, 2);
    l1 += __shfl_xor_sync(0xFFFFFFFF, l1, 1);
    l1 += __shfl_xor_sync(0xFFFFFFFF, l1, 2);
    float inv0 = 1.0f / l0, inv1 = 1.0f / l1;

    const int g  = lane >> 2;
    const int t2 = (lane & 3) * 2;
    const int row0 = qbase + wid * 16 + g;
#pragma unroll
    for (int nf = 0; nf < 8; nf++) {
        size_t col = colbase + nf * 8 + t2;
        *(uint32_t*)(g_Ctx + (size_t)row0 * HID + col) =
            pk2h(o[nf][0] * inv0, o[nf][1] * inv0);
        *(uint32_t*)(g_Ctx + (size_t)(row0 + 8) * HID + col) =
            pk2h(o[nf][2] * inv1, o[nf][3] * inv1);
    }
}

// ============================================================================
// launch
// ============================================================================
extern "C" void kernel_launch(void* const* d_in, const int* in_sizes, int n_in,
                              void* d_out, int out_size) {
    (void)in_sizes; (void)n_in; (void)out_size;
    const float* query = (const float*)d_in[0];
    const float* key   = (const float*)d_in[1];
    const float* value = (const float*)d_in[2];
    const float* Wq    = (const float*)d_in[3];
    const float* bq    = (const float*)d_in[4];
    const float* Wk    = (const float*)d_in[5];
    const float* bk    = (const float*)d_in[6];
    const float* Wv    = (const float*)d_in[7];
    const float* bv    = (const float*)d_in[8];
    const float* Wo    = (const float*)d_in[9];
    const float* bo    = (const float*)d_in[10];
    float* out = (float*)d_out;

    __half *Qh, *Kh, *Vh, *Ctx, *Wqh, *Wkh, *Wvh, *Woh;
    cudaGetSymbolAddress((void**)&Qh, g_Qh);
    cudaGetSymbolAddress((void**)&Kh, g_Kh);   cudaGetSymbolAddress((void**)&Vh, g_Vh);
    cudaGetSymbolAddress((void**)&Ctx, g_Ctx);
    cudaGetSymbolAddress((void**)&Wqh, g_Wqh); cudaGetSymbolAddress((void**)&Wkh, g_Wkh);
    cudaGetSymbolAddress((void**)&Wvh, g_Wvh); cudaGetSymbolAddress((void**)&Woh, g_Woh);

    cudaFuncSetAttribute(gemm_qkv, cudaFuncAttributeMaxDynamicSharedMemorySize, GEMM_SMEM);
    cudaFuncSetAttribute(gemm_out, cudaFuncAttributeMaxDynamicSharedMemorySize, GEMM_SMEM);
    cudaFuncSetAttribute(attn_mma, cudaFuncAttributeMaxDynamicSharedMemorySize, ATTN_SMEM);

    dim3 ggrid(HID / 128, MROWS / 128);
    const int wblocks = (HID * HID / 8) / 256;   // 512

    make_invf_kernel<<<1, 512>>>();
    rope_table_kernel<<<(SEQ * 512) / 256, 256>>>();

    prep_w_qkv<<<dim3(wblocks, 3), 256>>>(Wq, Wk, Wv);
    prep_w_colperm<<<wblocks, 256>>>(Wo, Woh);

    gemm_qkv<<<ggrid, 256, GEMM_SMEM>>>(query, Wqh, bq, Qh, 0.125f);
    gemm_qkv<<<ggrid, 256, GEMM_SMEM>>>(key,   Wkh, bk, Kh, 1.0f);
    gemm_qkv<<<ggrid, 256, GEMM_SMEM>>>(value, Wvh, bv, Vh, 1.0f);

    attn_mma<<<dim3(8, 128), 256, ATTN_SMEM>>>();

    gemm_out<<<ggrid, 256, GEMM_SMEM>>>(Ctx, Woh, bo, out);
}

// round 13
// speedup vs baseline: 1.9868x; 1.0608x over previous
#include <cuda_runtime.h>
#include <cuda_fp16.h>
#include <cstdint>

#define HID 1024
#define HEADS 16
#define HD 64
#define BATCH 8
#define SEQ 1024
#define MROWS (BATCH * SEQ)
#define LOG2E 1.4426950408889634f

// ---------------- scratch (device globals; no allocation allowed) ----------
__device__ __half g_Qh[MROWS * HID];
__device__ __half g_Kh[MROWS * HID];
__device__ __half g_Vh[MROWS * HID];
__device__ __half g_Ctx[MROWS * HID];
__device__ __half g_Wqh[HID * HID];
__device__ __half g_Wkh[HID * HID];
__device__ __half g_Wvh[HID * HID];
__device__ __half g_Woh[HID * HID];
__device__ float g_invf[HID / 2];
__device__ float4 g_tab[SEQ * (HID / 2)];

// ---------------- helpers ----------------------------------------
__device__ __forceinline__ uint32_t smem_u32(const void* p) {
    uint32_t a;
    asm("{ .reg .u64 t; cvta.to.shared.u64 t, %1; cvt.u32.u64 %0, t; }"
        : "=r"(a) : "l"(p));
    return a;
}
__device__ __forceinline__ void cp16(uint32_t dst, const void* src) {
    asm volatile("cp.async.cg.shared.global [%0], [%1], 16;" :: "r"(dst), "l"(src));
}
#define CP_COMMIT() asm volatile("cp.async.commit_group;" ::: "memory")
#define CP_WAIT1()  asm volatile("cp.async.wait_group 1;" ::: "memory")

__device__ __forceinline__ void ldm4(uint32_t* r, uint32_t addr) {
    asm volatile("ldmatrix.sync.aligned.m8n8.x4.shared.b16 {%0,%1,%2,%3}, [%4];"
                 : "=r"(r[0]), "=r"(r[1]), "=r"(r[2]), "=r"(r[3]) : "r"(addr));
}
__device__ __forceinline__ void ldm4t(uint32_t* r, uint32_t addr) {
    asm volatile("ldmatrix.sync.aligned.m8n8.x4.trans.shared.b16 {%0,%1,%2,%3}, [%4];"
                 : "=r"(r[0]), "=r"(r[1]), "=r"(r[2]), "=r"(r[3]) : "r"(addr));
}
__device__ __forceinline__ void mma16816(float* d, const uint32_t* a,
                                         uint32_t b0, uint32_t b1) {
    asm volatile(
        "mma.sync.aligned.m16n8k16.row.col.f32.f16.f16.f32 "
        "{%0,%1,%2,%3}, {%4,%5,%6,%7}, {%8,%9}, {%0,%1,%2,%3};"
        : "+f"(d[0]), "+f"(d[1]), "+f"(d[2]), "+f"(d[3])
        : "r"(a[0]), "r"(a[1]), "r"(a[2]), "r"(a[3]), "r"(b0), "r"(b1));
}
// pack two floats into one half2 u32 (rn)
__device__ __forceinline__ uint32_t pk2h(float x, float y) {
    __half2 h = __floats2half2_rn(x, y);
    return *reinterpret_cast<uint32_t*>(&h);
}
// 8 fp32 -> uint4 of 8 rn-rounded fp16
__device__ __forceinline__ uint4 cvt8h(const float4& u, const float4& v) {
    __half2 h0 = __floats2half2_rn(u.x, u.y);
    __half2 h1 = __floats2half2_rn(u.z, u.w);
    __half2 h2 = __floats2half2_rn(v.x, v.y);
    __half2 h3 = __floats2half2_rn(v.z, v.w);
    return make_uint4(*(uint32_t*)&h0, *(uint32_t*)&h1, *(uint32_t*)&h2, *(uint32_t*)&h3);
}
// permutation: n' = 128p + 64s + i  ->  orig = 64p + 512s + i
__device__ __forceinline__ int perm_orig(int n) {
    int p = n >> 7, s = (n >> 6) & 1, i = n & 63;
    return 64 * p + 512 * s + i;
}

// ============================================================================
// weight prep: all four weights in ONE launch.
// blockIdx.y 0..2 -> row-permuted Wq/Wk/Wv; 3 -> col-permuted Wo.
// ============================================================================
__global__ __launch_bounds__(256) void prep_w_all(
    const float* __restrict__ Wq, const float* __restrict__ Wk,
    const float* __restrict__ Wv, const float* __restrict__ Wo)
{
    int idx = blockIdx.x * 256 + threadIdx.x;   // HID*HID/8
    int n = idx >> 7;
    int c8 = (idx & 127) * 8;
    if (blockIdx.y < 3) {
        const float* W = (blockIdx.y == 0) ? Wq : (blockIdx.y == 1) ? Wk : Wv;
        __half* Wh = (blockIdx.y == 0) ? g_Wqh : (blockIdx.y == 1) ? g_Wkh : g_Wvh;
        int orig = perm_orig(n);
        float4 u = *(const float4*)(W + (size_t)orig * HID + c8);
        float4 v = *(const float4*)(W + (size_t)orig * HID + c8 + 4);
        *(uint4*)(Wh + (size_t)n * HID + c8) = cvt8h(u, v);
    } else {
        int orig = perm_orig(c8);   // contiguous over the 8-run
        float4 u = *(const float4*)(Wo + (size_t)n * HID + orig);
        float4 v = *(const float4*)(Wo + (size_t)n * HID + orig + 4);
        *(uint4*)(g_Woh + (size_t)n * HID + c8) = cvt8h(u, v);
    }
}

__global__ void make_invf_kernel() {
    int j = threadIdx.x;
    if (j < HID / 2) {
        double e = exp(-((double)(2 * j) / (double)HID) * log(10000.0));
        g_invf[j] = (float)e;
    }
}
__global__ __launch_bounds__(256) void rope_table_kernel() {
    int idx = blockIdx.x * 256 + threadIdx.x;
    int s = idx >> 9;
    int j = idx & 511;
    float t = (float)s * g_invf[j];
    float st, ct;
    sincosf(t, &st, &ct);
    float s1, c1, s2, c2;
    sincosf(st, &s1, &c1);
    sincosf(ct, &s2, &c2);
    g_tab[idx] = make_float4(c1, s1, c2, s2);
}

// ============================================================================
// fused QKV projection, ALL THREE in one launch (blockIdx.z selects q/k/v).
// 1-term pure fp16: Y = X*W'^T (+bias +RoPE +scale) -> fp16.
// Q gets scale 0.125*log2(e) so attention runs exp2-domain softmax.
// CTA 128x128, warp 64x32, K-chunk 32, 2-stage double buffer.
// NOTE: no min-blocks hint (R9 spill regression).
// ============================================================================
#define RSTRIDE 80
#define TILE_B (128 * RSTRIDE)      // 10240
#define STAGE1 (2 * TILE_B)         // 20480 (A, B)
#define GEMM_SMEM 67584             // epilogue fp32 tile 128x132
#define SROW 132

__global__ __launch_bounds__(256)
void gemm_qkv(const float* __restrict__ Xq, const float* __restrict__ Xk,
              const float* __restrict__ Xv,
              const float* __restrict__ bq, const float* __restrict__ bk,
              const float* __restrict__ bv)
{
    extern __shared__ __align__(128) char smem[];

    const int z = blockIdx.z;
    const float* X    = (z == 0) ? Xq : (z == 1) ? Xk : Xv;
    const __half* Bw  = (z == 0) ? g_Wqh : (z == 1) ? g_Wkh : g_Wvh;
    const float* bias = (z == 0) ? bq : (z == 1) ? bk : bv;
    __half* outh      = (z == 0) ? g_Qh : (z == 1) ? g_Kh : g_Vh;
    const float scale = (z == 0) ? (0.125f * LOG2E) : 1.0f;

    const int tid  = threadIdx.x;
    const int wid  = tid >> 5;
    const int lane = tid & 31;
    const int wm   = wid & 1;
    const int wn   = wid >> 1;
    const int brow = blockIdx.y * 128;
    const int bcol = blockIdx.x * 128;

    const uint32_t sbase = smem_u32(smem);
    const uint32_t aoff = (uint32_t)(((lane & 7) + ((lane >> 3) & 1) * 8) * RSTRIDE
                                     + ((lane >> 4) & 1) * 16);
    const uint32_t boff = (uint32_t)(((lane & 7) + ((lane >> 4) & 1) * 8) * RSTRIDE
                                     + ((lane >> 3) & 1) * 16);

    const int r0i = tid >> 2;          // rows r0i, r0i+64
    const int ch  = tid & 3;

    const float* Xp = X + (size_t)brow * HID;
    const __half* Bp = Bw + (size_t)bcol * HID;

    float acc[4][4][4];
#pragma unroll
    for (int i = 0; i < 4; i++)
#pragma unroll
        for (int j = 0; j < 4; j++)
#pragma unroll
            for (int r = 0; r < 4; r++) acc[i][j][r] = 0.0f;

    // prologue: chunk 0 -> stage 0
    {
        const size_t ke = (size_t)ch * 8;
        float4 a0 = *(const float4*)(Xp + (size_t)r0i * HID + ke);
        float4 a1 = *(const float4*)(Xp + (size_t)r0i * HID + ke + 4);
        float4 a2 = *(const float4*)(Xp + (size_t)(r0i + 64) * HID + ke);
        float4 a3 = *(const float4*)(Xp + (size_t)(r0i + 64) * HID + ke + 4);
        uint4 b0 = *(const uint4*)(Bp + (size_t)r0i * HID + ke);
        uint4 b1 = *(const uint4*)(Bp + (size_t)(r0i + 64) * HID + ke);
        *(uint4*)(smem + 0 * TILE_B + r0i * RSTRIDE + ch * 16)        = cvt8h(a0, a1);
        *(uint4*)(smem + 0 * TILE_B + (r0i + 64) * RSTRIDE + ch * 16) = cvt8h(a2, a3);
        *(uint4*)(smem + 1 * TILE_B + r0i * RSTRIDE + ch * 16)        = b0;
        *(uint4*)(smem + 1 * TILE_B + (r0i + 64) * RSTRIDE + ch * 16) = b1;
    }
    __syncthreads();

    for (int kc = 0; kc < 32; kc++) {
        const int s = kc & 1;
        const bool has = (kc + 1) < 32;

        float4 pa[4];
        uint4 pb[2];
        if (has) {
            const size_t ke = (size_t)(kc + 1) * 32 + (size_t)ch * 8;
            pa[0] = *(const float4*)(Xp + (size_t)r0i * HID + ke);
            pa[1] = *(const float4*)(Xp + (size_t)r0i * HID + ke + 4);
            pa[2] = *(const float4*)(Xp + (size_t)(r0i + 64) * HID + ke);
            pa[3] = *(const float4*)(Xp + (size_t)(r0i + 64) * HID + ke + 4);
            pb[0] = *(const uint4*)(Bp + (size_t)r0i * HID + ke);
            pb[1] = *(const uint4*)(Bp + (size_t)(r0i + 64) * HID + ke);
        }

        const uint32_t base = sbase + s * STAGE1;
#pragma unroll
        for (int ks = 0; ks < 2; ks++) {
            const uint32_t kb = ks * 32;
            uint32_t ah[4][4];
#pragma unroll
            for (int mf = 0; mf < 4; mf++) {
                uint32_t ro = (uint32_t)((wm * 64 + mf * 16) * RSTRIDE) + kb;
                ldm4(ah[mf], base + ro + aoff);
            }
            uint32_t bh[2][4];
#pragma unroll
            for (int p = 0; p < 2; p++) {
                uint32_t ro = (uint32_t)((wn * 32 + p * 16) * RSTRIDE) + kb;
                ldm4(bh[p], base + TILE_B + ro + boff);
            }
#pragma unroll
            for (int mf = 0; mf < 4; mf++) {
#pragma unroll
                for (int nf = 0; nf < 4; nf++) {
                    const int p = nf >> 1, q = nf & 1;
                    mma16816(acc[mf][nf], ah[mf], bh[p][2 * q], bh[p][2 * q + 1]);
                }
            }
        }

        if (has) {
            char* st = smem + (s ^ 1) * STAGE1;
            *(uint4*)(st + 0 * TILE_B + r0i * RSTRIDE + ch * 16)        = cvt8h(pa[0], pa[1]);
            *(uint4*)(st + 0 * TILE_B + (r0i + 64) * RSTRIDE + ch * 16) = cvt8h(pa[2], pa[3]);
            *(uint4*)(st + 1 * TILE_B + r0i * RSTRIDE + ch * 16)        = pb[0];
            *(uint4*)(st + 1 * TILE_B + (r0i + 64) * RSTRIDE + ch * 16) = pb[1];
        }
        __syncthreads();
    }

    // epilogue: stage fp32 tile, apply bias + RoPE + scale, write fp16
    float* sm = (float*)smem;
    const int g  = lane >> 2;
    const int t2 = (lane & 3) * 2;
#pragma unroll
    for (int mf = 0; mf < 4; mf++) {
        const int lr = wm * 64 + mf * 16 + g;
#pragma unroll
        for (int nf = 0; nf < 4; nf++) {
            const int lc = wn * 32 + nf * 8 + t2;
            *(float2*)(sm + lr * SROW + lc)       = make_float2(acc[mf][nf][0], acc[mf][nf][1]);
            *(float2*)(sm + (lr + 8) * SROW + lc) = make_float2(acc[mf][nf][2], acc[mf][nf][3]);
        }
    }
    __syncthreads();

    const int pblk = bcol >> 7;
#pragma unroll
    for (int it = 0; it < 16; it++) {
        int idx = it * 256 + tid;
        int r  = idx >> 5;
        int c0 = (idx & 31) * 2;
        int srow = (brow + r) & (SEQ - 1);
        int j0 = 64 * pblk + c0;
        float4 t0 = g_tab[(srow << 9) | j0];
        float4 t1 = g_tab[(srow << 9) | (j0 + 1)];
        float x1a = sm[r * SROW + c0]      + bias[j0];
        float x1b = sm[r * SROW + c0 + 1]  + bias[j0 + 1];
        float x2a = sm[r * SROW + c0 + 64] + bias[j0 + 512];
        float x2b = sm[r * SROW + c0 + 65] + bias[j0 + 513];
        float y1a = (x1a * t0.x + x2a * t0.y) * scale;
        float y2a = (x2a * t0.z - x1a * t0.w) * scale;
        float y1b = (x1b * t1.x + x2b * t1.y) * scale;
        float y2b = (x2b * t1.z - x1b * t1.w) * scale;
        size_t gb = (size_t)(brow + r) * HID + bcol;
        *(uint32_t*)(outh + gb + c0)      = pk2h(y1a, y1b);
        *(uint32_t*)(outh + gb + 64 + c0) = pk2h(y2a, y2b);
    }
}

// ============================================================================
// output projection, 1-term: out = Ctx*Wo'^T + bo (fp32). Ctx single fp16.
// ============================================================================
__global__ __launch_bounds__(256)
void gemm_out(const __half* __restrict__ Actx, const __half* __restrict__ Bw,
              const float* __restrict__ bias, float* __restrict__ Y)
{
    extern __shared__ __align__(128) char smem[];

    const int tid  = threadIdx.x;
    const int wid  = tid >> 5;
    const int lane = tid & 31;
    const int wm   = wid & 1;
    const int wn   = wid >> 1;
    const int brow = blockIdx.y * 128;
    const int bcol = blockIdx.x * 128;

    const uint32_t sbase = smem_u32(smem);
    const uint32_t aoff = (uint32_t)(((lane & 7) + ((lane >> 3) & 1) * 8) * RSTRIDE
                                     + ((lane >> 4) & 1) * 16);
    const uint32_t boff = (uint32_t)(((lane & 7) + ((lane >> 4) & 1) * 8) * RSTRIDE
                                     + ((lane >> 3) & 1) * 16);

    const int r0i = tid >> 2;
    const int ch  = tid & 3;

    const __half* Ap = Actx + (size_t)brow * HID;
    const __half* Bp = Bw + (size_t)bcol * HID;

    float acc[4][4][4];
#pragma unroll
    for (int i = 0; i < 4; i++)
#pragma unroll
        for (int j = 0; j < 4; j++)
#pragma unroll
            for (int r = 0; r < 4; r++) acc[i][j][r] = 0.0f;

    {
        const size_t ke = (size_t)ch * 8;
        *(uint4*)(smem + 0 * TILE_B + r0i * RSTRIDE + ch * 16) =
            *(const uint4*)(Ap + (size_t)r0i * HID + ke);
        *(uint4*)(smem + 0 * TILE_B + (r0i + 64) * RSTRIDE + ch * 16) =
            *(const uint4*)(Ap + (size_t)(r0i + 64) * HID + ke);
        *(uint4*)(smem + 1 * TILE_B + r0i * RSTRIDE + ch * 16) =
            *(const uint4*)(Bp + (size_t)r0i * HID + ke);
        *(uint4*)(smem + 1 * TILE_B + (r0i + 64) * RSTRIDE + ch * 16) =
            *(const uint4*)(Bp + (size_t)(r0i + 64) * HID + ke);
    }
    __syncthreads();

    for (int kc = 0; kc < 32; kc++) {
        const int s = kc & 1;
        const bool has = (kc + 1) < 32;

        uint4 pf[2][2];
        if (has) {
            const size_t ke = (size_t)(kc + 1) * 32 + (size_t)ch * 8;
            pf[0][0] = *(const uint4*)(Ap + (size_t)r0i * HID + ke);
            pf[0][1] = *(const uint4*)(Ap + (size_t)(r0i + 64) * HID + ke);
            pf[1][0] = *(const uint4*)(Bp + (size_t)r0i * HID + ke);
            pf[1][1] = *(const uint4*)(Bp + (size_t)(r0i + 64) * HID + ke);
        }

        const uint32_t base = sbase + s * STAGE1;
#pragma unroll
        for (int ks = 0; ks < 2; ks++) {
            const uint32_t kb = ks * 32;
            uint32_t ah[4][4];
#pragma unroll
            for (int mf = 0; mf < 4; mf++) {
                uint32_t ro = (uint32_t)((wm * 64 + mf * 16) * RSTRIDE) + kb;
                ldm4(ah[mf], base + ro + aoff);
            }
            uint32_t bh[2][4];
#pragma unroll
            for (int p = 0; p < 2; p++) {
                uint32_t ro = (uint32_t)((wn * 32 + p * 16) * RSTRIDE) + kb;
                ldm4(bh[p], base + TILE_B + ro + boff);
            }
#pragma unroll
            for (int mf = 0; mf < 4; mf++) {
#pragma unroll
                for (int nf = 0; nf < 4; nf++) {
                    const int p = nf >> 1, q = nf & 1;
                    mma16816(acc[mf][nf], ah[mf], bh[p][2 * q], bh[p][2 * q + 1]);
                }
            }
        }

        if (has) {
            char* st = smem + (s ^ 1) * STAGE1;
            *(uint4*)(st + 0 * TILE_B + r0i * RSTRIDE + ch * 16)        = pf[0][0];
            *(uint4*)(st + 0 * TILE_B + (r0i + 64) * RSTRIDE + ch * 16) = pf[0][1];
            *(uint4*)(st + 1 * TILE_B + r0i * RSTRIDE + ch * 16)        = pf[1][0];
            *(uint4*)(st + 1 * TILE_B + (r0i + 64) * RSTRIDE + ch * 16) = pf[1][1];
        }
        __syncthreads();
    }

    const int g = lane >> 2;
    const int t2 = (lane & 3) * 2;
#pragma unroll
    for (int mf = 0; mf < 4; mf++) {
        const int row0 = brow + wm * 64 + mf * 16 + g;
#pragma unroll
        for (int nf = 0; nf < 4; nf++) {
            const int col = bcol + wn * 32 + nf * 8 + t2;
            float2 bv = *(const float2*)(bias + col);
            *(float2*)(Y + (size_t)row0 * HID + col) =
                make_float2(acc[mf][nf][0] + bv.x, acc[mf][nf][1] + bv.y);
            *(float2*)(Y + (size_t)(row0 + 8) * HID + col) =
                make_float2(acc[mf][nf][2] + bv.x, acc[mf][nf][3] + bv.y);
        }
    }
}

// ============================================================================
// tensor-core flash attention, pure fp16 operands, exp2-domain softmax
// (scores arrive pre-multiplied by log2(e) via the Q scale).
// cp.async double-buffered K/V stages. Ctx written as single fp16.
// ============================================================================
#define AST 144
#define AQ 0
#define AKV0 (128 * AST)              // 18432
#define KVSTG (2 * 64 * AST)          // 18432 (K, V)
#define ATTN_SMEM (AKV0 + 2 * KVSTG)  // 55296

__device__ __forceinline__ void attn_issue_kv(
    int krow0, size_t colbase, uint32_t kvbase, int tid)
{
#pragma unroll
    for (int i = 0; i < 4; i++) {
        const __half* g = (i < 2) ? g_Kh : g_Vh;
        const int arr = i >> 1;
        const int rem = ((i & 1) << 8) + tid;
        const int row = rem >> 3;
        const int c = rem & 7;
        cp16(kvbase + arr * (64 * AST) + row * AST + c * 16,
             g + (size_t)(krow0 + row) * HID + colbase + c * 8);
    }
}

__global__ __launch_bounds__(256, 2) void attn_mma() {
    extern __shared__ __align__(128) char smem[];

    const int tid  = threadIdx.x;
    const int wid  = tid >> 5;
    const int lane = tid & 31;
    const int qt   = blockIdx.x;
    const int bh   = blockIdx.y;
    const int b    = bh >> 4;
    const int h    = bh & 15;
    const int qbase = b * SEQ + qt * 128;
    const size_t colbase = (size_t)h * HD;
    const int krow_base = b * SEQ;

    const uint32_t sb = smem_u32(smem);

    const uint32_t aoff = (uint32_t)(((lane & 7) + ((lane >> 3) & 1) * 8) * AST
                                     + ((lane >> 4) & 1) * 16);
    const uint32_t boff = (uint32_t)(((lane & 7) + ((lane >> 4) & 1) * 8) * AST
                                     + ((lane >> 3) & 1) * 16);
    const uint32_t voff = (uint32_t)(((lane & 7) + ((lane >> 3) & 1) * 8) * AST
                                     + ((lane >> 4) & 1) * 16);

    // group 0: Q + KV stage 0
#pragma unroll
    for (int i = 0; i < 4; i++) {
        const int rem = (i << 8) + tid;
        const int row = rem >> 3;
        const int c = rem & 7;
        cp16(sb + AQ + row * AST + c * 16,
             g_Qh + (size_t)(qbase + row) * HID + colbase + c * 8);
    }
    attn_issue_kv(krow_base, colbase, sb + AKV0, tid);
    CP_COMMIT();
    attn_issue_kv(krow_base + 64, colbase, sb + AKV0 + KVSTG, tid);
    CP_COMMIT();

    float o[8][4];
#pragma unroll
    for (int nf = 0; nf < 8; nf++)
#pragma unroll
        for (int r = 0; r < 4; r++) o[nf][r] = 0.0f;
    float m0 = -1e30f, m1 = -1e30f, l0 = 0.0f, l1 = 0.0f;

    const uint32_t qrow_off = (uint32_t)(wid * 16 * AST);

    for (int kt = 0; kt < 16; kt++) {
        const int s = kt & 1;
        CP_WAIT1();
        __syncthreads();

        const uint32_t kvb = sb + AKV0 + s * KVSTG;
        const uint32_t akh = kvb;
        const uint32_t avh = kvb + 64 * AST;

        float sfr[8][4];
#pragma unroll
        for (int nf = 0; nf < 8; nf++)
#pragma unroll
            for (int r = 0; r < 4; r++) sfr[nf][r] = 0.0f;

#pragma unroll
        for (int kq = 0; kq < 4; kq++) {
            uint32_t qh[4];
            ldm4(qh, sb + AQ + qrow_off + kq * 32 + aoff);
            uint32_t kh[4][4];
#pragma unroll
            for (int p = 0; p < 4; p++)
                ldm4(kh[p], akh + (uint32_t)(p * 16 * AST) + kq * 32 + boff);
#pragma unroll
            for (int nf = 0; nf < 8; nf++) {
                const int p = nf >> 1, q = nf & 1;
                mma16816(sfr[nf], qh, kh[p][2 * q], kh[p][2 * q + 1]);
            }
        }

        // scores are in log2-e units; softmax entirely in exp2 domain
        float mx0 = -1e30f, mx1 = -1e30f;
#pragma unroll
        for (int nf = 0; nf < 8; nf++) {
            mx0 = fmaxf(mx0, fmaxf(sfr[nf][0], sfr[nf][1]));
            mx1 = fmaxf(mx1, fmaxf(sfr[nf][2], sfr[nf][3]));
        }
        mx0 = fmaxf(mx0, __shfl_xor_sync(0xFFFFFFFF, mx0, 1));
        mx0 = fmaxf(mx0, __shfl_xor_sync(0xFFFFFFFF, mx0, 2));
        mx1 = fmaxf(mx1, __shfl_xor_sync(0xFFFFFFFF, mx1, 1));
        mx1 = fmaxf(mx1, __shfl_xor_sync(0xFFFFFFFF, mx1, 2));

        float mn0 = fmaxf(m0, mx0), mn1 = fmaxf(m1, mx1);
        float c0 = exp2f(m0 - mn0), c1 = exp2f(m1 - mn1);
        l0 *= c0; l1 *= c1;
#pragma unroll
        for (int nf = 0; nf < 8; nf++) {
            o[nf][0] *= c0; o[nf][1] *= c0;
            o[nf][2] *= c1; o[nf][3] *= c1;
        }
#pragma unroll
        for (int nf = 0; nf < 8; nf++) {
            sfr[nf][0] = exp2f(sfr[nf][0] - mn0);
            sfr[nf][1] = exp2f(sfr[nf][1] - mn0);
            sfr[nf][2] = exp2f(sfr[nf][2] - mn1);
            sfr[nf][3] = exp2f(sfr[nf][3] - mn1);
            l0 += sfr[nf][0] + sfr[nf][1];
            l1 += sfr[nf][2] + sfr[nf][3];
        }
        m0 = mn0; m1 = mn1;

#pragma unroll
        for (int kk = 0; kk < 4; kk++) {
            uint32_t ah[4];
            ah[0] = pk2h(sfr[2 * kk][0],     sfr[2 * kk][1]);
            ah[1] = pk2h(sfr[2 * kk][2],     sfr[2 * kk][3]);
            ah[2] = pk2h(sfr[2 * kk + 1][0], sfr[2 * kk + 1][1]);
            ah[3] = pk2h(sfr[2 * kk + 1][2], sfr[2 * kk + 1][3]);

            uint32_t vh[4][4];
#pragma unroll
            for (int p = 0; p < 4; p++) {
                uint32_t ro = (uint32_t)(kk * 16 * AST) + (uint32_t)(p * 32);
                ldm4t(vh[p], avh + ro + voff);
            }
#pragma unroll
            for (int nf = 0; nf < 8; nf++) {
                const int p = nf >> 1, q = nf & 1;
                mma16816(o[nf], ah, vh[p][2 * q], vh[p][2 * q + 1]);
            }
        }

        __syncthreads();
        if (kt + 2 < 16)
            attn_issue_kv(krow_base + (kt + 2) * 64, colbase,
                          sb + AKV0 + s * KVSTG, tid);
        CP_COMMIT();
    }

    l0 += __shfl_xor_sync(0xFFFFFFFF, l0, 1);
    l0 += __shfl_xor_sync(0xFFFFFFFF, l0, 2);
    l1 += __shfl_xor_sync(0xFFFFFFFF, l1, 1);
    l1 += __shfl_xor_sync(0xFFFFFFFF, l1, 2);
    float inv0 = 1.0f / l0, inv1 = 1.0f / l1;

    const int g  = lane >> 2;
    const int t2 = (lane & 3) * 2;
    const int row0 = qbase + wid * 16 + g;
#pragma unroll
    for (int nf = 0; nf < 8; nf++) {
        size_t col = colbase + nf * 8 + t2;
        *(uint32_t*)(g_Ctx + (size_t)row0 * HID + col) =
            pk2h(o[nf][0] * inv0, o[nf][1] * inv0);
        *(uint32_t*)(g_Ctx + (size_t)(row0 + 8) * HID + col) =
            pk2h(o[nf][2] * inv1, o[nf][3] * inv1);
    }
}

// ============================================================================
// launch
// ============================================================================
extern "C" void kernel_launch(void* const* d_in, const int* in_sizes, int n_in,
                              void* d_out, int out_size) {
    (void)in_sizes; (void)n_in; (void)out_size;
    const float* query = (const float*)d_in[0];
    const float* key   = (const float*)d_in[1];
    const float* value = (const float*)d_in[2];
    const float* Wq    = (const float*)d_in[3];
    const float* bq    = (const float*)d_in[4];
    const float* Wk    = (const float*)d_in[5];
    const float* bk    = (const float*)d_in[6];
    const float* Wv    = (const float*)d_in[7];
    const float* bv    = (const float*)d_in[8];
    const float* Wo    = (const float*)d_in[9];
    const float* bo    = (const float*)d_in[10];
    float* out = (float*)d_out;

    __half *Ctx, *Woh;
    cudaGetSymbolAddress((void**)&Ctx, g_Ctx);
    cudaGetSymbolAddress((void**)&Woh, g_Woh);

    cudaFuncSetAttribute(gemm_qkv, cudaFuncAttributeMaxDynamicSharedMemorySize, GEMM_SMEM);
    cudaFuncSetAttribute(gemm_out, cudaFuncAttributeMaxDynamicSharedMemorySize, GEMM_SMEM);
    cudaFuncSetAttribute(attn_mma, cudaFuncAttributeMaxDynamicSharedMemorySize, ATTN_SMEM);

    const int wblocks = (HID * HID / 8) / 256;   // 512

    make_invf_kernel<<<1, 512>>>();
    rope_table_kernel<<<(SEQ * 512) / 256, 256>>>();

    prep_w_all<<<dim3(wblocks, 4), 256>>>(Wq, Wk, Wv, Wo);

    gemm_qkv<<<dim3(HID / 128, MROWS / 128, 3), 256, GEMM_SMEM>>>(
        query, key, value, bq, bk, bv);

    attn_mma<<<dim3(8, 128), 256, ATTN_SMEM>>>();

    gemm_out<<<dim3(HID / 128, MROWS / 128), 256, GEMM_SMEM>>>(Ctx, Woh, bo, out);
}

// round 14
// speedup vs baseline: 2.1127x; 1.0634x over previous
#include <cuda_runtime.h>
#include <cuda_fp16.h>
#include <cstdint>

#define HID 1024
#define HEADS 16
#define HD 64
#define BATCH 8
#define SEQ 1024
#define MROWS (BATCH * SEQ)
#define LOG2E 1.4426950408889634f

// ---------------- scratch (device globals; no allocation allowed) ----------
__device__ __half g_Xq[MROWS * HID];
__device__ __half g_Xk[MROWS * HID];
__device__ __half g_Xv[MROWS * HID];
__device__ __half g_Qh[MROWS * HID];
__device__ __half g_Kh[MROWS * HID];
__device__ __half g_Vh[MROWS * HID];
__device__ __half g_Ctx[MROWS * HID];
__device__ __half g_Wqh[HID * HID];
__device__ __half g_Wkh[HID * HID];
__device__ __half g_Wvh[HID * HID];
__device__ __half g_Woh[HID * HID];
__device__ float g_invf[HID / 2];
__device__ float4 g_tab[SEQ * (HID / 2)];

// ---------------- helpers ----------------------------------------
__device__ __forceinline__ uint32_t smem_u32(const void* p) {
    uint32_t a;
    asm("{ .reg .u64 t; cvta.to.shared.u64 t, %1; cvt.u32.u64 %0, t; }"
        : "=r"(a) : "l"(p));
    return a;
}
__device__ __forceinline__ void cp16(uint32_t dst, const void* src) {
    asm volatile("cp.async.cg.shared.global [%0], [%1], 16;" :: "r"(dst), "l"(src));
}
#define CP_COMMIT() asm volatile("cp.async.commit_group;" ::: "memory")
#define CP_WAIT1()  asm volatile("cp.async.wait_group 1;" ::: "memory")

__device__ __forceinline__ void ldm4(uint32_t* r, uint32_t addr) {
    asm volatile("ldmatrix.sync.aligned.m8n8.x4.shared.b16 {%0,%1,%2,%3}, [%4];"
                 : "=r"(r[0]), "=r"(r[1]), "=r"(r[2]), "=r"(r[3]) : "r"(addr));
}
__device__ __forceinline__ void ldm4t(uint32_t* r, uint32_t addr) {
    asm volatile("ldmatrix.sync.aligned.m8n8.x4.trans.shared.b16 {%0,%1,%2,%3}, [%4];"
                 : "=r"(r[0]), "=r"(r[1]), "=r"(r[2]), "=r"(r[3]) : "r"(addr));
}
__device__ __forceinline__ void mma16816(float* d, const uint32_t* a,
                                         uint32_t b0, uint32_t b1) {
    asm volatile(
        "mma.sync.aligned.m16n8k16.row.col.f32.f16.f16.f32 "
        "{%0,%1,%2,%3}, {%4,%5,%6,%7}, {%8,%9}, {%0,%1,%2,%3};"
        : "+f"(d[0]), "+f"(d[1]), "+f"(d[2]), "+f"(d[3])
        : "r"(a[0]), "r"(a[1]), "r"(a[2]), "r"(a[3]), "r"(b0), "r"(b1));
}
// pack two floats into one half2 u32 (rn)
__device__ __forceinline__ uint32_t pk2h(float x, float y) {
    __half2 h = __floats2half2_rn(x, y);
    return *reinterpret_cast<uint32_t*>(&h);
}
// 8 fp32 -> uint4 of 8 rn-rounded fp16
__device__ __forceinline__ uint4 cvt8h(const float4& u, const float4& v) {
    __half2 h0 = __floats2half2_rn(u.x, u.y);
    __half2 h1 = __floats2half2_rn(u.z, u.w);
    __half2 h2 = __floats2half2_rn(v.x, v.y);
    __half2 h3 = __floats2half2_rn(v.z, v.w);
    return make_uint4(*(uint32_t*)&h0, *(uint32_t*)&h1, *(uint32_t*)&h2, *(uint32_t*)&h3);
}
// permutation: n' = 128p + 64s + i  ->  orig = 64p + 512s + i
__device__ __forceinline__ int perm_orig(int n) {
    int p = n >> 7, s = (n >> 6) & 1, i = n & 63;
    return 64 * p + 512 * s + i;
}

// ============================================================================
// prep: activations -> fp16 (identical rounding to former inline cvt8h)
// ============================================================================
__global__ __launch_bounds__(256) void prep_act(
    const float* __restrict__ Xq, const float* __restrict__ Xk,
    const float* __restrict__ Xv)
{
    const float* X = (blockIdx.y == 0) ? Xq : (blockIdx.y == 1) ? Xk : Xv;
    __half* O = (blockIdx.y == 0) ? g_Xq : (blockIdx.y == 1) ? g_Xk : g_Xv;
    int idx = blockIdx.x * 256 + threadIdx.x;   // MROWS*HID/8
    float4 u = ((const float4*)X)[2 * idx];
    float4 v = ((const float4*)X)[2 * idx + 1];
    ((uint4*)O)[idx] = cvt8h(u, v);
}

// ============================================================================
// weight prep: all four weights in ONE launch.
// ============================================================================
__global__ __launch_bounds__(256) void prep_w_all(
    const float* __restrict__ Wq, const float* __restrict__ Wk,
    const float* __restrict__ Wv, const float* __restrict__ Wo)
{
    int idx = blockIdx.x * 256 + threadIdx.x;   // HID*HID/8
    int n = idx >> 7;
    int c8 = (idx & 127) * 8;
    if (blockIdx.y < 3) {
        const float* W = (blockIdx.y == 0) ? Wq : (blockIdx.y == 1) ? Wk : Wv;
        __half* Wh = (blockIdx.y == 0) ? g_Wqh : (blockIdx.y == 1) ? g_Wkh : g_Wvh;
        int orig = perm_orig(n);
        float4 u = *(const float4*)(W + (size_t)orig * HID + c8);
        float4 v = *(const float4*)(W + (size_t)orig * HID + c8 + 4);
        *(uint4*)(Wh + (size_t)n * HID + c8) = cvt8h(u, v);
    } else {
        int orig = perm_orig(c8);
        float4 u = *(const float4*)(Wo + (size_t)n * HID + orig);
        float4 v = *(const float4*)(Wo + (size_t)n * HID + orig + 4);
        *(uint4*)(g_Woh + (size_t)n * HID + c8) = cvt8h(u, v);
    }
}

__global__ void make_invf_kernel() {
    int j = threadIdx.x;
    if (j < HID / 2) {
        double e = exp(-((double)(2 * j) / (double)HID) * log(10000.0));
        g_invf[j] = (float)e;
    }
}
__global__ __launch_bounds__(256) void rope_table_kernel() {
    int idx = blockIdx.x * 256 + threadIdx.x;
    int s = idx >> 9;
    int j = idx & 511;
    float t = (float)s * g_invf[j];
    float st, ct;
    sincosf(t, &st, &ct);
    float s1, c1, s2, c2;
    sincosf(st, &s1, &c1);
    sincosf(ct, &s2, &c2);
    g_tab[idx] = make_float4(c1, s1, c2, s2);
}

// ============================================================================
// shared GEMM machinery: fp16 NT, CTA 128x128, warp 64x32, K-chunk 32,
// 3-stage cp.async ring (16KB/stage). One __syncthreads per kc.
// ============================================================================
#define RSTRIDE 80
#define TILE_B (128 * RSTRIDE)      // 10240
#define STG (2 * TILE_B)            // 20480 (A, B)
#define GEMM_SMEM 67584             // >= 3*STG (61440) and epilogue 128x132 f32
#define SROW 132

__device__ __forceinline__ void issue_stage(
    const __half* A, const __half* B, int kc, uint32_t st, int tid)
{
    const size_t ko = (size_t)kc * 32;
#pragma unroll
    for (int t = 0; t < 4; t++) {
        const __half* g = (t < 2) ? A : B;
        const int tile = t >> 1;
        const int rem = ((t & 1) << 8) + tid;
        const int row = rem >> 2;
        const int c = rem & 3;
        cp16(st + tile * TILE_B + row * RSTRIDE + c * 16,
             g + (size_t)row * HID + ko + c * 8);
    }
}

// mainloop body shared by both GEMMs (acc[4][4][4] by ref)
__device__ __forceinline__ void gemm_mainloop(
    const __half* Ap, const __half* Bp, uint32_t sbase,
    uint32_t aoff, uint32_t boff, int wm, int wn, int tid,
    float acc[4][4][4])
{
    issue_stage(Ap, Bp, 0, sbase, tid);
    CP_COMMIT();
    issue_stage(Ap, Bp, 1, sbase + STG, tid);
    CP_COMMIT();

    for (int kc = 0; kc < 32; kc++) {
        CP_WAIT1();
        __syncthreads();
        if (kc + 2 < 32)
            issue_stage(Ap, Bp, kc + 2, sbase + ((kc + 2) % 3) * STG, tid);
        CP_COMMIT();

        const uint32_t base = sbase + (kc % 3) * STG;
#pragma unroll
        for (int ks = 0; ks < 2; ks++) {
            const uint32_t kb = ks * 32;
            uint32_t ah[4][4];
#pragma unroll
            for (int mf = 0; mf < 4; mf++) {
                uint32_t ro = (uint32_t)((wm * 64 + mf * 16) * RSTRIDE) + kb;
                ldm4(ah[mf], base + ro + aoff);
            }
            uint32_t bh[2][4];
#pragma unroll
            for (int p = 0; p < 2; p++) {
                uint32_t ro = (uint32_t)((wn * 32 + p * 16) * RSTRIDE) + kb;
                ldm4(bh[p], base + TILE_B + ro + boff);
            }
#pragma unroll
            for (int mf = 0; mf < 4; mf++) {
#pragma unroll
                for (int nf = 0; nf < 4; nf++) {
                    const int p = nf >> 1, q = nf & 1;
                    mma16816(acc[mf][nf], ah[mf], bh[p][2 * q], bh[p][2 * q + 1]);
                }
            }
        }
    }
    __syncthreads();   // all reads done before smem reuse
}

// ============================================================================
// fused QKV projection, ALL THREE in one launch (blockIdx.z selects q/k/v).
// Y = Xh*W'^T (+bias +RoPE +scale) -> fp16. Q scale folds 0.125*log2e.
// ============================================================================
__global__ __launch_bounds__(256)
void gemm_qkv(const float* __restrict__ bq, const float* __restrict__ bk,
              const float* __restrict__ bv)
{
    extern __shared__ __align__(128) char smem[];

    const int z = blockIdx.z;
    const __half* X   = (z == 0) ? g_Xq : (z == 1) ? g_Xk : g_Xv;
    const __half* Bw  = (z == 0) ? g_Wqh : (z == 1) ? g_Wkh : g_Wvh;
    const float* bias = (z == 0) ? bq : (z == 1) ? bk : bv;
    __half* outh      = (z == 0) ? g_Qh : (z == 1) ? g_Kh : g_Vh;
    const float scale = (z == 0) ? (0.125f * LOG2E) : 1.0f;

    const int tid  = threadIdx.x;
    const int wid  = tid >> 5;
    const int lane = tid & 31;
    const int wm   = wid & 1;
    const int wn   = wid >> 1;
    const int brow = blockIdx.y * 128;
    const int bcol = blockIdx.x * 128;

    const uint32_t sbase = smem_u32(smem);
    const uint32_t aoff = (uint32_t)(((lane & 7) + ((lane >> 3) & 1) * 8) * RSTRIDE
                                     + ((lane >> 4) & 1) * 16);
    const uint32_t boff = (uint32_t)(((lane & 7) + ((lane >> 4) & 1) * 8) * RSTRIDE
                                     + ((lane >> 3) & 1) * 16);

    float acc[4][4][4];
#pragma unroll
    for (int i = 0; i < 4; i++)
#pragma unroll
        for (int j = 0; j < 4; j++)
#pragma unroll
            for (int r = 0; r < 4; r++) acc[i][j][r] = 0.0f;

    gemm_mainloop(X + (size_t)brow * HID, Bw + (size_t)bcol * HID,
                  sbase, aoff, boff, wm, wn, tid, acc);

    // epilogue: stage fp32 tile, apply bias + RoPE + scale, write fp16
    float* sm = (float*)smem;
    const int g  = lane >> 2;
    const int t2 = (lane & 3) * 2;
#pragma unroll
    for (int mf = 0; mf < 4; mf++) {
        const int lr = wm * 64 + mf * 16 + g;
#pragma unroll
        for (int nf = 0; nf < 4; nf++) {
            const int lc = wn * 32 + nf * 8 + t2;
            *(float2*)(sm + lr * SROW + lc)       = make_float2(acc[mf][nf][0], acc[mf][nf][1]);
            *(float2*)(sm + (lr + 8) * SROW + lc) = make_float2(acc[mf][nf][2], acc[mf][nf][3]);
        }
    }
    __syncthreads();

    const int pblk = bcol >> 7;
#pragma unroll
    for (int it = 0; it < 16; it++) {
        int idx = it * 256 + tid;
        int r  = idx >> 5;
        int c0 = (idx & 31) * 2;
        int srow = (brow + r) & (SEQ - 1);
        int j0 = 64 * pblk + c0;
        float4 t0 = g_tab[(srow << 9) | j0];
        float4 t1 = g_tab[(srow << 9) | (j0 + 1)];
        float x1a = sm[r * SROW + c0]      + bias[j0];
        float x1b = sm[r * SROW + c0 + 1]  + bias[j0 + 1];
        float x2a = sm[r * SROW + c0 + 64] + bias[j0 + 512];
        float x2b = sm[r * SROW + c0 + 65] + bias[j0 + 513];
        float y1a = (x1a * t0.x + x2a * t0.y) * scale;
        float y2a = (x2a * t0.z - x1a * t0.w) * scale;
        float y1b = (x1b * t1.x + x2b * t1.y) * scale;
        float y2b = (x2b * t1.z - x1b * t1.w) * scale;
        size_t gb = (size_t)(brow + r) * HID + bcol;
        *(uint32_t*)(outh + gb + c0)      = pk2h(y1a, y1b);
        *(uint32_t*)(outh + gb + 64 + c0) = pk2h(y2a, y2b);
    }
}

// ============================================================================
// output projection: out = Ctx*Wo'^T + bo (fp32).
// ============================================================================
__global__ __launch_bounds__(256)
void gemm_out(const __half* __restrict__ Actx, const __half* __restrict__ Bw,
              const float* __restrict__ bias, float* __restrict__ Y)
{
    extern __shared__ __align__(128) char smem[];

    const int tid  = threadIdx.x;
    const int wid  = tid >> 5;
    const int lane = tid & 31;
    const int wm   = wid & 1;
    const int wn   = wid >> 1;
    const int brow = blockIdx.y * 128;
    const int bcol = blockIdx.x * 128;

    const uint32_t sbase = smem_u32(smem);
    const uint32_t aoff = (uint32_t)(((lane & 7) + ((lane >> 3) & 1) * 8) * RSTRIDE
                                     + ((lane >> 4) & 1) * 16);
    const uint32_t boff = (uint32_t)(((lane & 7) + ((lane >> 4) & 1) * 8) * RSTRIDE
                                     + ((lane >> 3) & 1) * 16);

    float acc[4][4][4];
#pragma unroll
    for (int i = 0; i < 4; i++)
#pragma unroll
        for (int j = 0; j < 4; j++)
#pragma unroll
            for (int r = 0; r < 4; r++) acc[i][j][r] = 0.0f;

    gemm_mainloop(Actx + (size_t)brow * HID, Bw + (size_t)bcol * HID,
                  sbase, aoff, boff, wm, wn, tid, acc);

    const int g = lane >> 2;
    const int t2 = (lane & 3) * 2;
#pragma unroll
    for (int mf = 0; mf < 4; mf++) {
        const int row0 = brow + wm * 64 + mf * 16 + g;
#pragma unroll
        for (int nf = 0; nf < 4; nf++) {
            const int col = bcol + wn * 32 + nf * 8 + t2;
            float2 bv = *(const float2*)(bias + col);
            *(float2*)(Y + (size_t)row0 * HID + col) =
                make_float2(acc[mf][nf][0] + bv.x, acc[mf][nf][1] + bv.y);
            *(float2*)(Y + (size_t)(row0 + 8) * HID + col) =
                make_float2(acc[mf][nf][2] + bv.x, acc[mf][nf][3] + bv.y);
        }
    }
}

// ============================================================================
// tensor-core flash attention, pure fp16 operands, exp2-domain softmax.
// cp.async double-buffered K/V stages. Ctx written as single fp16.
// ============================================================================
#define AST 144
#define AQ 0
#define AKV0 (128 * AST)              // 18432
#define KVSTG (2 * 64 * AST)          // 18432 (K, V)
#define ATTN_SMEM (AKV0 + 2 * KVSTG)  // 55296

__device__ __forceinline__ void attn_issue_kv(
    int krow0, size_t colbase, uint32_t kvbase, int tid)
{
#pragma unroll
    for (int i = 0; i < 4; i++) {
        const __half* g = (i < 2) ? g_Kh : g_Vh;
        const int arr = i >> 1;
        const int rem = ((i & 1) << 8) + tid;
        const int row = rem >> 3;
        const int c = rem & 7;
        cp16(kvbase + arr * (64 * AST) + row * AST + c * 16,
             g + (size_t)(krow0 + row) * HID + colbase + c * 8);
    }
}

__global__ __launch_bounds__(256, 2) void attn_mma() {
    extern __shared__ __align__(128) char smem[];

    const int tid  = threadIdx.x;
    const int wid  = tid >> 5;
    const int lane = tid & 31;
    const int qt   = blockIdx.x;
    const int bh   = blockIdx.y;
    const int b    = bh >> 4;
    const int h    = bh & 15;
    const int qbase = b * SEQ + qt * 128;
    const size_t colbase = (size_t)h * HD;
    const int krow_base = b * SEQ;

    const uint32_t sb = smem_u32(smem);

    const uint32_t aoff = (uint32_t)(((lane & 7) + ((lane >> 3) & 1) * 8) * AST
                                     + ((lane >> 4) & 1) * 16);
    const uint32_t boff = (uint32_t)(((lane & 7) + ((lane >> 4) & 1) * 8) * AST
                                     + ((lane >> 3) & 1) * 16);
    const uint32_t voff = (uint32_t)(((lane & 7) + ((lane >> 3) & 1) * 8) * AST
                                     + ((lane >> 4) & 1) * 16);

#pragma unroll
    for (int i = 0; i < 4; i++) {
        const int rem = (i << 8) + tid;
        const int row = rem >> 3;
        const int c = rem & 7;
        cp16(sb + AQ + row * AST + c * 16,
             g_Qh + (size_t)(qbase + row) * HID + colbase + c * 8);
    }
    attn_issue_kv(krow_base, colbase, sb + AKV0, tid);
    CP_COMMIT();
    attn_issue_kv(krow_base + 64, colbase, sb + AKV0 + KVSTG, tid);
    CP_COMMIT();

    float o[8][4];
#pragma unroll
    for (int nf = 0; nf < 8; nf++)
#pragma unroll
        for (int r = 0; r < 4; r++) o[nf][r] = 0.0f;
    float m0 = -1e30f, m1 = -1e30f, l0 = 0.0f, l1 = 0.0f;

    const uint32_t qrow_off = (uint32_t)(wid * 16 * AST);

    for (int kt = 0; kt < 16; kt++) {
        const int s = kt & 1;
        CP_WAIT1();
        __syncthreads();

        const uint32_t kvb = sb + AKV0 + s * KVSTG;
        const uint32_t akh = kvb;
        const uint32_t avh = kvb + 64 * AST;

        float sfr[8][4];
#pragma unroll
        for (int nf = 0; nf < 8; nf++)
#pragma unroll
            for (int r = 0; r < 4; r++) sfr[nf][r] = 0.0f;

#pragma unroll
        for (int kq = 0; kq < 4; kq++) {
            uint32_t qh[4];
            ldm4(qh, sb + AQ + qrow_off + kq * 32 + aoff);
            uint32_t kh[4][4];
#pragma unroll
            for (int p = 0; p < 4; p++)
                ldm4(kh[p], akh + (uint32_t)(p * 16 * AST) + kq * 32 + boff);
#pragma unroll
            for (int nf = 0; nf < 8; nf++) {
                const int p = nf >> 1, q = nf & 1;
                mma16816(sfr[nf], qh, kh[p][2 * q], kh[p][2 * q + 1]);
            }
        }

        float mx0 = -1e30f, mx1 = -1e30f;
#pragma unroll
        for (int nf = 0; nf < 8; nf++) {
            mx0 = fmaxf(mx0, fmaxf(sfr[nf][0], sfr[nf][1]));
            mx1 = fmaxf(mx1, fmaxf(sfr[nf][2], sfr[nf][3]));
        }
        mx0 = fmaxf(mx0, __shfl_xor_sync(0xFFFFFFFF, mx0, 1));
        mx0 = fmaxf(mx0, __shfl_xor_sync(0xFFFFFFFF, mx0, 2));
        mx1 = fmaxf(mx1, __shfl_xor_sync(0xFFFFFFFF, mx1, 1));
        mx1 = fmaxf(mx1, __shfl_xor_sync(0xFFFFFFFF, mx1, 2));

        float mn0 = fmaxf(m0, mx0), mn1 = fmaxf(m1, mx1);
        float c0 = exp2f(m0 - mn0), c1 = exp2f(m1 - mn1);
        l0 *= c0; l1 *= c1;
#pragma unroll
        for (int nf = 0; nf < 8; nf++) {
            o[nf][0] *= c0; o[nf][1] *= c0;
            o[nf][2] *= c1; o[nf][3] *= c1;
        }
#pragma unroll
        for (int nf = 0; nf < 8; nf++) {
            sfr[nf][0] = exp2f(sfr[nf][0] - mn0);
            sfr[nf][1] = exp2f(sfr[nf][1] - mn0);
            sfr[nf][2] = exp2f(sfr[nf][2] - mn1);
            sfr[nf][3] = exp2f(sfr[nf][3] - mn1);
            l0 += sfr[nf][0] + sfr[nf][1];
            l1 += sfr[nf][2] + sfr[nf][3];
        }
        m0 = mn0; m1 = mn1;

#pragma unroll
        for (int kk = 0; kk < 4; kk++) {
            uint32_t ah[4];
            ah[0] = pk2h(sfr[2 * kk][0],     sfr[2 * kk][1]);
            ah[1] = pk2h(sfr[2 * kk][2],     sfr[2 * kk][3]);
            ah[2] = pk2h(sfr[2 * kk + 1][0], sfr[2 * kk + 1][1]);
            ah[3] = pk2h(sfr[2 * kk + 1][2], sfr[2 * kk + 1][3]);

            uint32_t vh[4][4];
#pragma unroll
            for (int p = 0; p < 4; p++) {
                uint32_t ro = (uint32_t)(kk * 16 * AST) + (uint32_t)(p * 32);
                ldm4t(vh[p], avh + ro + voff);
            }
#pragma unroll
            for (int nf = 0; nf < 8; nf++) {
                const int p = nf >> 1, q = nf & 1;
                mma16816(o[nf], ah, vh[p][2 * q], vh[p][2 * q + 1]);
            }
        }

        __syncthreads();
        if (kt + 2 < 16)
            attn_issue_kv(krow_base + (kt + 2) * 64, colbase,
                          sb + AKV0 + s * KVSTG, tid);
        CP_COMMIT();
    }

    l0 += __shfl_xor_sync(0xFFFFFFFF, l0, 1);
    l0 += __shfl_xor_sync(0xFFFFFFFF, l0, 2);
    l1 += __shfl_xor_sync(0xFFFFFFFF, l1, 1);
    l1 += __shfl_xor_sync(0xFFFFFFFF, l1, 2);
    float inv0 = 1.0f / l0, inv1 = 1.0f / l1;

    const int g  = lane >> 2;
    const int t2 = (lane & 3) * 2;
    const int row0 = qbase + wid * 16 + g;
#pragma unroll
    for (int nf = 0; nf < 8; nf++) {
        size_t col = colbase + nf * 8 + t2;
        *(uint32_t*)(g_Ctx + (size_t)row0 * HID + col) =
            pk2h(o[nf][0] * inv0, o[nf][1] * inv0);
        *(uint32_t*)(g_Ctx + (size_t)(row0 + 8) * HID + col) =
            pk2h(o[nf][2] * inv1, o[nf][3] * inv1);
    }
}

// ============================================================================
// launch
// ============================================================================
extern "C" void kernel_launch(void* const* d_in, const int* in_sizes, int n_in,
                              void* d_out, int out_size) {
    (void)in_sizes; (void)n_in; (void)out_size;
    const float* query = (const float*)d_in[0];
    const float* key   = (const float*)d_in[1];
    const float* value = (const float*)d_in[2];
    const float* Wq    = (const float*)d_in[3];
    const float* bq    = (const float*)d_in[4];
    const float* Wk    = (const float*)d_in[5];
    const float* bk    = (const float*)d_in[6];
    const float* Wv    = (const float*)d_in[7];
    const float* bv    = (const float*)d_in[8];
    const float* Wo    = (const float*)d_in[9];
    const float* bo    = (const float*)d_in[10];
    float* out = (float*)d_out;

    __half *Ctx, *Woh;
    cudaGetSymbolAddress((void**)&Ctx, g_Ctx);
    cudaGetSymbolAddress((void**)&Woh, g_Woh);

    cudaFuncSetAttribute(gemm_qkv, cudaFuncAttributeMaxDynamicSharedMemorySize, GEMM_SMEM);
    cudaFuncSetAttribute(gemm_out, cudaFuncAttributeMaxDynamicSharedMemorySize, GEMM_SMEM);
    cudaFuncSetAttribute(attn_mma, cudaFuncAttributeMaxDynamicSharedMemorySize, ATTN_SMEM);

    const int wblocks = (HID * HID / 8) / 256;      // 512
    const int ablocks = (MROWS * HID / 8) / 256;    // 4096

    make_invf_kernel<<<1, 512>>>();
    rope_table_kernel<<<(SEQ * 512) / 256, 256>>>();

    prep_w_all<<<dim3(wblocks, 4), 256>>>(Wq, Wk, Wv, Wo);
    prep_act<<<dim3(ablocks, 3), 256>>>(query, key, value);

    gemm_qkv<<<dim3(HID / 128, MROWS / 128, 3), 256, GEMM_SMEM>>>(bq, bk, bv);

    attn_mma<<<dim3(8, 128), 256, ATTN_SMEM>>>();

    gemm_out<<<dim3(HID / 128, MROWS / 128), 256, GEMM_SMEM>>>(Ctx, Woh, bo, out);
}

// round 15
// speedup vs baseline: 2.2566x; 1.0681x over previous
#include <cuda_runtime.h>
#include <cuda_fp16.h>
#include <cstdint>

#define HID 1024
#define HEADS 16
#define HD 64
#define BATCH 8
#define SEQ 1024
#define MROWS (BATCH * SEQ)
#define LOG2E 1.4426950408889634f

// ---------------- scratch (device globals; no allocation allowed) ----------
__device__ __half g_Xq[MROWS * HID];
__device__ __half g_Xk[MROWS * HID];
__device__ __half g_Xv[MROWS * HID];
__device__ __half g_Qh[MROWS * HID];
__device__ __half g_Kh[MROWS * HID];
__device__ __half g_Vh[MROWS * HID];
__device__ __half g_Ctx[MROWS * HID];
__device__ __half g_Wqh[HID * HID];
__device__ __half g_Wkh[HID * HID];
__device__ __half g_Wvh[HID * HID];
__device__ __half g_Woh[HID * HID];
__device__ float g_invf[HID / 2];
__device__ float4 g_tab[SEQ * (HID / 2)];

// ---------------- helpers ----------------------------------------
__device__ __forceinline__ uint32_t smem_u32(const void* p) {
    uint32_t a;
    asm("{ .reg .u64 t; cvta.to.shared.u64 t, %1; cvt.u32.u64 %0, t; }"
        : "=r"(a) : "l"(p));
    return a;
}
__device__ __forceinline__ void cp16(uint32_t dst, const void* src) {
    asm volatile("cp.async.cg.shared.global [%0], [%1], 16;" :: "r"(dst), "l"(src));
}
#define CP_COMMIT() asm volatile("cp.async.commit_group;" ::: "memory")
#define CP_WAIT1()  asm volatile("cp.async.wait_group 1;" ::: "memory")

__device__ __forceinline__ void ldm4(uint32_t* r, uint32_t addr) {
    asm volatile("ldmatrix.sync.aligned.m8n8.x4.shared.b16 {%0,%1,%2,%3}, [%4];"
                 : "=r"(r[0]), "=r"(r[1]), "=r"(r[2]), "=r"(r[3]) : "r"(addr));
}
__device__ __forceinline__ void ldm4t(uint32_t* r, uint32_t addr) {
    asm volatile("ldmatrix.sync.aligned.m8n8.x4.trans.shared.b16 {%0,%1,%2,%3}, [%4];"
                 : "=r"(r[0]), "=r"(r[1]), "=r"(r[2]), "=r"(r[3]) : "r"(addr));
}
__device__ __forceinline__ void mma16816(float* d, const uint32_t* a,
                                         uint32_t b0, uint32_t b1) {
    asm volatile(
        "mma.sync.aligned.m16n8k16.row.col.f32.f16.f16.f32 "
        "{%0,%1,%2,%3}, {%4,%5,%6,%7}, {%8,%9}, {%0,%1,%2,%3};"
        : "+f"(d[0]), "+f"(d[1]), "+f"(d[2]), "+f"(d[3])
        : "r"(a[0]), "r"(a[1]), "r"(a[2]), "r"(a[3]), "r"(b0), "r"(b1));
}
// packed f32x2 multiply (two independent fp32 muls, bit-identical semantics)
__device__ __forceinline__ void f2mul(unsigned long long& d, unsigned long long a,
                                      unsigned long long b) {
    asm("mul.rn.f32x2 %0, %1, %2;" : "+l"(d) : "l"(a), "l"(b));
}
__device__ __forceinline__ uint32_t pk2h(float x, float y) {
    __half2 h = __floats2half2_rn(x, y);
    return *reinterpret_cast<uint32_t*>(&h);
}
__device__ __forceinline__ uint4 cvt8h(const float4& u, const float4& v) {
    __half2 h0 = __floats2half2_rn(u.x, u.y);
    __half2 h1 = __floats2half2_rn(u.z, u.w);
    __half2 h2 = __floats2half2_rn(v.x, v.y);
    __half2 h3 = __floats2half2_rn(v.z, v.w);
    return make_uint4(*(uint32_t*)&h0, *(uint32_t*)&h1, *(uint32_t*)&h2, *(uint32_t*)&h3);
}
// permutation: n' = 128p + 64s + i  ->  orig = 64p + 512s + i
__device__ __forceinline__ int perm_orig(int n) {
    int p = n >> 7, s = (n >> 6) & 1, i = n & 63;
    return 64 * p + 512 * s + i;
}

// ============================================================================
// prep kernels
// ============================================================================
__global__ __launch_bounds__(256) void prep_act(
    const float* __restrict__ Xq, const float* __restrict__ Xk,
    const float* __restrict__ Xv)
{
    const float* X = (blockIdx.y == 0) ? Xq : (blockIdx.y == 1) ? Xk : Xv;
    __half* O = (blockIdx.y == 0) ? g_Xq : (blockIdx.y == 1) ? g_Xk : g_Xv;
    int idx = blockIdx.x * 256 + threadIdx.x;
    float4 u = ((const float4*)X)[2 * idx];
    float4 v = ((const float4*)X)[2 * idx + 1];
    ((uint4*)O)[idx] = cvt8h(u, v);
}

__global__ __launch_bounds__(256) void prep_w_all(
    const float* __restrict__ Wq, const float* __restrict__ Wk,
    const float* __restrict__ Wv, const float* __restrict__ Wo)
{
    int idx = blockIdx.x * 256 + threadIdx.x;
    int n = idx >> 7;
    int c8 = (idx & 127) * 8;
    if (blockIdx.y < 3) {
        const float* W = (blockIdx.y == 0) ? Wq : (blockIdx.y == 1) ? Wk : Wv;
        __half* Wh = (blockIdx.y == 0) ? g_Wqh : (blockIdx.y == 1) ? g_Wkh : g_Wvh;
        int orig = perm_orig(n);
        float4 u = *(const float4*)(W + (size_t)orig * HID + c8);
        float4 v = *(const float4*)(W + (size_t)orig * HID + c8 + 4);
        *(uint4*)(Wh + (size_t)n * HID + c8) = cvt8h(u, v);
    } else {
        int orig = perm_orig(c8);
        float4 u = *(const float4*)(Wo + (size_t)n * HID + orig);
        float4 v = *(const float4*)(Wo + (size_t)n * HID + orig + 4);
        *(uint4*)(g_Woh + (size_t)n * HID + c8) = cvt8h(u, v);
    }
}

__global__ void make_invf_kernel() {
    int j = threadIdx.x;
    if (j < HID / 2) {
        double e = exp(-((double)(2 * j) / (double)HID) * log(10000.0));
        g_invf[j] = (float)e;
    }
}
__global__ __launch_bounds__(256) void rope_table_kernel() {
    int idx = blockIdx.x * 256 + threadIdx.x;
    int s = idx >> 9;
    int j = idx & 511;
    float t = (float)s * g_invf[j];
    float st, ct;
    sincosf(t, &st, &ct);
    float s1, c1, s2, c2;
    sincosf(st, &s1, &c1);
    sincosf(ct, &s2, &c2);
    g_tab[idx] = make_float4(c1, s1, c2, s2);
}

// ============================================================================
// shared GEMM machinery: fp16 NT, CTA 128x128, warp 64x32, K-chunk 64,
// 3-stage cp.async ring (36KB/stage). One __syncthreads per kc (16 total).
// Accumulation order identical to K-chunk-32 version (bit-identical output).
// ============================================================================
#define RSTRIDE 144
#define TILE_B (128 * RSTRIDE)      // 18432
#define STG (2 * TILE_B)            // 36864 (A, B)
#define GEMM_SMEM (3 * STG)         // 110592 (>= epilogue 128x132 f32 = 67584)
#define SROW 132

__device__ __forceinline__ void issue_stage(
    const __half* A, const __half* B, int kc, uint32_t st, int tid)
{
    const size_t ko = (size_t)kc * 64;
#pragma unroll
    for (int t = 0; t < 8; t++) {
        const __half* g = (t < 4) ? A : B;
        const int tile = t >> 2;
        const int rem = ((t & 3) << 8) + tid;
        const int row = rem >> 3;
        const int c = rem & 7;
        cp16(st + tile * TILE_B + row * RSTRIDE + c * 16,
             g + (size_t)row * HID + ko + c * 8);
    }
}

__device__ __forceinline__ void gemm_mainloop(
    const __half* Ap, const __half* Bp, uint32_t sbase,
    uint32_t aoff, uint32_t boff, int wm, int wn, int tid,
    float acc[4][4][4])
{
    issue_stage(Ap, Bp, 0, sbase, tid);
    CP_COMMIT();
    issue_stage(Ap, Bp, 1, sbase + STG, tid);
    CP_COMMIT();

    for (int kc = 0; kc < 16; kc++) {
        CP_WAIT1();
        __syncthreads();
        if (kc + 2 < 16)
            issue_stage(Ap, Bp, kc + 2, sbase + ((kc + 2) % 3) * STG, tid);
        CP_COMMIT();

        const uint32_t base = sbase + (kc % 3) * STG;
#pragma unroll
        for (int ks = 0; ks < 4; ks++) {
            const uint32_t kb = ks * 32;
            uint32_t ah[4][4];
#pragma unroll
            for (int mf = 0; mf < 4; mf++) {
                uint32_t ro = (uint32_t)((wm * 64 + mf * 16) * RSTRIDE) + kb;
                ldm4(ah[mf], base + ro + aoff);
            }
            uint32_t bh[2][4];
#pragma unroll
            for (int p = 0; p < 2; p++) {
                uint32_t ro = (uint32_t)((wn * 32 + p * 16) * RSTRIDE) + kb;
                ldm4(bh[p], base + TILE_B + ro + boff);
            }
#pragma unroll
            for (int mf = 0; mf < 4; mf++) {
#pragma unroll
                for (int nf = 0; nf < 4; nf++) {
                    const int p = nf >> 1, q = nf & 1;
                    mma16816(acc[mf][nf], ah[mf], bh[p][2 * q], bh[p][2 * q + 1]);
                }
            }
        }
    }
    __syncthreads();
}

// ============================================================================
// fused QKV projection, ALL THREE in one launch (blockIdx.z selects q/k/v).
// ============================================================================
__global__ __launch_bounds__(256)
void gemm_qkv(const float* __restrict__ bq, const float* __restrict__ bk,
              const float* __restrict__ bv)
{
    extern __shared__ __align__(128) char smem[];

    const int z = blockIdx.z;
    const __half* X   = (z == 0) ? g_Xq : (z == 1) ? g_Xk : g_Xv;
    const __half* Bw  = (z == 0) ? g_Wqh : (z == 1) ? g_Wkh : g_Wvh;
    const float* bias = (z == 0) ? bq : (z == 1) ? bk : bv;
    __half* outh      = (z == 0) ? g_Qh : (z == 1) ? g_Kh : g_Vh;
    const float scale = (z == 0) ? (0.125f * LOG2E) : 1.0f;

    const int tid  = threadIdx.x;
    const int wid  = tid >> 5;
    const int lane = tid & 31;
    const int wm   = wid & 1;
    const int wn   = wid >> 1;
    const int brow = blockIdx.y * 128;
    const int bcol = blockIdx.x * 128;

    const uint32_t sbase = smem_u32(smem);
    const uint32_t aoff = (uint32_t)(((lane & 7) + ((lane >> 3) & 1) * 8) * RSTRIDE
                                     + ((lane >> 4) & 1) * 16);
    const uint32_t boff = (uint32_t)(((lane & 7) + ((lane >> 4) & 1) * 8) * RSTRIDE
                                     + ((lane >> 3) & 1) * 16);

    float acc[4][4][4];
#pragma unroll
    for (int i = 0; i < 4; i++)
#pragma unroll
        for (int j = 0; j < 4; j++)
#pragma unroll
            for (int r = 0; r < 4; r++) acc[i][j][r] = 0.0f;

    gemm_mainloop(X + (size_t)brow * HID, Bw + (size_t)bcol * HID,
                  sbase, aoff, boff, wm, wn, tid, acc);

    float* sm = (float*)smem;
    const int g  = lane >> 2;
    const int t2 = (lane & 3) * 2;
#pragma unroll
    for (int mf = 0; mf < 4; mf++) {
        const int lr = wm * 64 + mf * 16 + g;
#pragma unroll
        for (int nf = 0; nf < 4; nf++) {
            const int lc = wn * 32 + nf * 8 + t2;
            *(float2*)(sm + lr * SROW + lc)       = make_float2(acc[mf][nf][0], acc[mf][nf][1]);
            *(float2*)(sm + (lr + 8) * SROW + lc) = make_float2(acc[mf][nf][2], acc[mf][nf][3]);
        }
    }
    __syncthreads();

    const int pblk = bcol >> 7;
#pragma unroll
    for (int it = 0; it < 16; it++) {
        int idx = it * 256 + tid;
        int r  = idx >> 5;
        int c0 = (idx & 31) * 2;
        int srow = (brow + r) & (SEQ - 1);
        int j0 = 64 * pblk + c0;
        float4 t0 = g_tab[(srow << 9) | j0];
        float4 t1 = g_tab[(srow << 9) | (j0 + 1)];
        float x1a = sm[r * SROW + c0]      + bias[j0];
        float x1b = sm[r * SROW + c0 + 1]  + bias[j0 + 1];
        float x2a = sm[r * SROW + c0 + 64] + bias[j0 + 512];
        float x2b = sm[r * SROW + c0 + 65] + bias[j0 + 513];
        float y1a = (x1a * t0.x + x2a * t0.y) * scale;
        float y2a = (x2a * t0.z - x1a * t0.w) * scale;
        float y1b = (x1b * t1.x + x2b * t1.y) * scale;
        float y2b = (x2b * t1.z - x1b * t1.w) * scale;
        size_t gb = (size_t)(brow + r) * HID + bcol;
        *(uint32_t*)(outh + gb + c0)      = pk2h(y1a, y1b);
        *(uint32_t*)(outh + gb + 64 + c0) = pk2h(y2a, y2b);
    }
}

// ============================================================================
// output projection: out = Ctx*Wo'^T + bo (fp32).
// ============================================================================
__global__ __launch_bounds__(256)
void gemm_out(const __half* __restrict__ Actx, const __half* __restrict__ Bw,
              const float* __restrict__ bias, float* __restrict__ Y)
{
    extern __shared__ __align__(128) char smem[];

    const int tid  = threadIdx.x;
    const int wid  = tid >> 5;
    const int lane = tid & 31;
    const int wm   = wid & 1;
    const int wn   = wid >> 1;
    const int brow = blockIdx.y * 128;
    const int bcol = blockIdx.x * 128;

    const uint32_t sbase = smem_u32(smem);
    const uint32_t aoff = (uint32_t)(((lane & 7) + ((lane >> 3) & 1) * 8) * RSTRIDE
                                     + ((lane >> 4) & 1) * 16);
    const uint32_t boff = (uint32_t)(((lane & 7) + ((lane >> 4) & 1) * 8) * RSTRIDE
                                     + ((lane >> 3) & 1) * 16);

    float acc[4][4][4];
#pragma unroll
    for (int i = 0; i < 4; i++)
#pragma unroll
        for (int j = 0; j < 4; j++)
#pragma unroll
            for (int r = 0; r < 4; r++) acc[i][j][r] = 0.0f;

    gemm_mainloop(Actx + (size_t)brow * HID, Bw + (size_t)bcol * HID,
                  sbase, aoff, boff, wm, wn, tid, acc);

    const int g = lane >> 2;
    const int t2 = (lane & 3) * 2;
#pragma unroll
    for (int mf = 0; mf < 4; mf++) {
        const int row0 = brow + wm * 64 + mf * 16 + g;
#pragma unroll
        for (int nf = 0; nf < 4; nf++) {
            const int col = bcol + wn * 32 + nf * 8 + t2;
            float2 bv = *(const float2*)(bias + col);
            *(float2*)(Y + (size_t)row0 * HID + col) =
                make_float2(acc[mf][nf][0] + bv.x, acc[mf][nf][1] + bv.y);
            *(float2*)(Y + (size_t)(row0 + 8) * HID + col) =
                make_float2(acc[mf][nf][2] + bv.x, acc[mf][nf][3] + bv.y);
        }
    }
}

// ============================================================================
// tensor-core flash attention, pure fp16 operands, exp2-domain softmax.
// ============================================================================
#define AST 144
#define AQ 0
#define AKV0 (128 * AST)              // 18432
#define KVSTG (2 * 64 * AST)          // 18432 (K, V)
#define ATTN_SMEM (AKV0 + 2 * KVSTG)  // 55296

__device__ __forceinline__ void attn_issue_kv(
    int krow0, size_t colbase, uint32_t kvbase, int tid)
{
#pragma unroll
    for (int i = 0; i < 4; i++) {
        const __half* g = (i < 2) ? g_Kh : g_Vh;
        const int arr = i >> 1;
        const int rem = ((i & 1) << 8) + tid;
        const int row = rem >> 3;
        const int c = rem & 7;
        cp16(kvbase + arr * (64 * AST) + row * AST + c * 16,
             g + (size_t)(krow0 + row) * HID + colbase + c * 8);
    }
}

__global__ __launch_bounds__(256, 2) void attn_mma() {
    extern __shared__ __align__(128) char smem[];

    const int tid  = threadIdx.x;
    const int wid  = tid >> 5;
    const int lane = tid & 31;
    const int qt   = blockIdx.x;
    const int bh   = blockIdx.y;
    const int b    = bh >> 4;
    const int h    = bh & 15;
    const int qbase = b * SEQ + qt * 128;
    const size_t colbase = (size_t)h * HD;
    const int krow_base = b * SEQ;

    const uint32_t sb = smem_u32(smem);

    const uint32_t aoff = (uint32_t)(((lane & 7) + ((lane >> 3) & 1) * 8) * AST
                                     + ((lane >> 4) & 1) * 16);
    const uint32_t boff = (uint32_t)(((lane & 7) + ((lane >> 4) & 1) * 8) * AST
                                     + ((lane >> 3) & 1) * 16);
    const uint32_t voff = (uint32_t)(((lane & 7) + ((lane >> 3) & 1) * 8) * AST
                                     + ((lane >> 4) & 1) * 16);

#pragma unroll
    for (int i = 0; i < 4; i++) {
        const int rem = (i << 8) + tid;
        const int row = rem >> 3;
        const int c = rem & 7;
        cp16(sb + AQ + row * AST + c * 16,
             g_Qh + (size_t)(qbase + row) * HID + colbase + c * 8);
    }
    attn_issue_kv(krow_base, colbase, sb + AKV0, tid);
    CP_COMMIT();
    attn_issue_kv(krow_base + 64, colbase, sb + AKV0 + KVSTG, tid);
    CP_COMMIT();

    // o accumulators as packed f32x2 pairs for cheap rescale
    unsigned long long o2[8][2];
#pragma unroll
    for (int nf = 0; nf < 8; nf++) { o2[nf][0] = 0ULL; o2[nf][1] = 0ULL; }
    float m0 = -1e30f, m1 = -1e30f, l0 = 0.0f, l1 = 0.0f;

    const uint32_t qrow_off = (uint32_t)(wid * 16 * AST);

    for (int kt = 0; kt < 16; kt++) {
        const int s = kt & 1;
        CP_WAIT1();
        __syncthreads();

        const uint32_t kvb = sb + AKV0 + s * KVSTG;
        const uint32_t akh = kvb;
        const uint32_t avh = kvb + 64 * AST;

        float sfr[8][4];
#pragma unroll
        for (int nf = 0; nf < 8; nf++)
#pragma unroll
            for (int r = 0; r < 4; r++) sfr[nf][r] = 0.0f;

#pragma unroll
        for (int kq = 0; kq < 4; kq++) {
            uint32_t qh[4];
            ldm4(qh, sb + AQ + qrow_off + kq * 32 + aoff);
            uint32_t kh[4][4];
#pragma unroll
            for (int p = 0; p < 4; p++)
                ldm4(kh[p], akh + (uint32_t)(p * 16 * AST) + kq * 32 + boff);
#pragma unroll
            for (int nf = 0; nf < 8; nf++) {
                const int p = nf >> 1, q = nf & 1;
                mma16816(sfr[nf], qh, kh[p][2 * q], kh[p][2 * q + 1]);
            }
        }

        float mx0 = -1e30f, mx1 = -1e30f;
#pragma unroll
        for (int nf = 0; nf < 8; nf++) {
            mx0 = fmaxf(mx0, fmaxf(sfr[nf][0], sfr[nf][1]));
            mx1 = fmaxf(mx1, fmaxf(sfr[nf][2], sfr[nf][3]));
        }
        mx0 = fmaxf(mx0, __shfl_xor_sync(0xFFFFFFFF, mx0, 1));
        mx0 = fmaxf(mx0, __shfl_xor_sync(0xFFFFFFFF, mx0, 2));
        mx1 = fmaxf(mx1, __shfl_xor_sync(0xFFFFFFFF, mx1, 1));
        mx1 = fmaxf(mx1, __shfl_xor_sync(0xFFFFFFFF, mx1, 2));

        float mn0 = fmaxf(m0, mx0), mn1 = fmaxf(m1, mx1);
        float c0 = exp2f(m0 - mn0), c1 = exp2f(m1 - mn1);
        l0 *= c0; l1 *= c1;
        unsigned long long c0p, c1p;
        asm("mov.b64 %0, {%1, %1};" : "=l"(c0p) : "f"(c0));
        asm("mov.b64 %0, {%1, %1};" : "=l"(c1p) : "f"(c1));
#pragma unroll
        for (int nf = 0; nf < 8; nf++) {
            f2mul(o2[nf][0], o2[nf][0], c0p);
            f2mul(o2[nf][1], o2[nf][1], c1p);
        }
#pragma unroll
        for (int nf = 0; nf < 8; nf++) {
            sfr[nf][0] = exp2f(sfr[nf][0] - mn0);
            sfr[nf][1] = exp2f(sfr[nf][1] - mn0);
            sfr[nf][2] = exp2f(sfr[nf][2] - mn1);
            sfr[nf][3] = exp2f(sfr[nf][3] - mn1);
            l0 += sfr[nf][0] + sfr[nf][1];
            l1 += sfr[nf][2] + sfr[nf][3];
        }
        m0 = mn0; m1 = mn1;

#pragma unroll
        for (int kk = 0; kk < 4; kk++) {
            uint32_t ah[4];
            ah[0] = pk2h(sfr[2 * kk][0],     sfr[2 * kk][1]);
            ah[1] = pk2h(sfr[2 * kk][2],     sfr[2 * kk][3]);
            ah[2] = pk2h(sfr[2 * kk + 1][0], sfr[2 * kk + 1][1]);
            ah[3] = pk2h(sfr[2 * kk + 1][2], sfr[2 * kk + 1][3]);

            uint32_t vh[4][4];
#pragma unroll
            for (int p = 0; p < 4; p++) {
                uint32_t ro = (uint32_t)(kk * 16 * AST) + (uint32_t)(p * 32);
                ldm4t(vh[p], avh + ro + voff);
            }
#pragma unroll
            for (int nf = 0; nf < 8; nf++) {
                const int p = nf >> 1, q = nf & 1;
                mma16816((float*)o2[nf], ah, vh[p][2 * q], vh[p][2 * q + 1]);
            }
        }

        __syncthreads();
        if (kt + 2 < 16)
            attn_issue_kv(krow_base + (kt + 2) * 64, colbase,
                          sb + AKV0 + s * KVSTG, tid);
        CP_COMMIT();
    }

    l0 += __shfl_xor_sync(0xFFFFFFFF, l0, 1);
    l0 += __shfl_xor_sync(0xFFFFFFFF, l0, 2);
    l1 += __shfl_xor_sync(0xFFFFFFFF, l1, 1);
    l1 += __shfl_xor_sync(0xFFFFFFFF, l1, 2);
    float inv0 = 1.0f / l0, inv1 = 1.0f / l1;

    const int g  = lane >> 2;
    const int t2 = (lane & 3) * 2;
    const int row0 = qbase + wid * 16 + g;
#pragma unroll
    for (int nf = 0; nf < 8; nf++) {
        size_t col = colbase + nf * 8 + t2;
        const float* of = (const float*)o2[nf];
        *(uint32_t*)(g_Ctx + (size_t)row0 * HID + col) =
            pk2h(of[0] * inv0, of[1] * inv0);
        *(uint32_t*)(g_Ctx + (size_t)(row0 + 8) * HID + col) =
            pk2h(of[2] * inv1, of[3] * inv1);
    }
}

// ============================================================================
// launch
// ============================================================================
extern "C" void kernel_launch(void* const* d_in, const int* in_sizes, int n_in,
                              void* d_out, int out_size) {
    (void)in_sizes; (void)n_in; (void)out_size;
    const float* query = (const float*)d_in[0];
    const float* key   = (const float*)d_in[1];
    const float* value = (const float*)d_in[2];
    const float* Wq    = (const float*)d_in[3];
    const float* bq    = (const float*)d_in[4];
    const float* Wk    = (const float*)d_in[5];
    const float* bk    = (const float*)d_in[6];
    const float* Wv    = (const float*)d_in[7];
    const float* bv    = (const float*)d_in[8];
    const float* Wo    = (const float*)d_in[9];
    const float* bo    = (const float*)d_in[10];
    float* out = (float*)d_out;

    __half *Ctx, *Woh;
    cudaGetSymbolAddress((void**)&Ctx, g_Ctx);
    cudaGetSymbolAddress((void**)&Woh, g_Woh);

    cudaFuncSetAttribute(gemm_qkv, cudaFuncAttributeMaxDynamicSharedMemorySize, GEMM_SMEM);
    cudaFuncSetAttribute(gemm_out, cudaFuncAttributeMaxDynamicSharedMemorySize, GEMM_SMEM);
    cudaFuncSetAttribute(attn_mma, cudaFuncAttributeMaxDynamicSharedMemorySize, ATTN_SMEM);

    const int wblocks = (HID * HID / 8) / 256;      // 512
    const int ablocks = (MROWS * HID / 8) / 256;    // 4096

    make_invf_kernel<<<1, 512>>>();
    rope_table_kernel<<<(SEQ * 512) / 256, 256>>>();

    prep_w_all<<<dim3(wblocks, 4), 256>>>(Wq, Wk, Wv, Wo);
    prep_act<<<dim3(ablocks, 3), 256>>>(query, key, value);

    gemm_qkv<<<dim3(HID / 128, MROWS / 128, 3), 256, GEMM_SMEM>>>(bq, bk, bv);

    attn_mma<<<dim3(8, 128), 256, ATTN_SMEM>>>();

    gemm_out<<<dim3(HID / 128, MROWS / 128), 256, GEMM_SMEM>>>(Ctx, Woh, bo, out);
}

// round 16
// speedup vs baseline: 2.2848x; 1.0125x over previous
#include <cuda_runtime.h>
#include <cuda_fp16.h>
#include <cstdint>

#define HID 1024
#define HEADS 16
#define HD 64
#define BATCH 8
#define SEQ 1024
#define MROWS (BATCH * SEQ)
#define LOG2E 1.4426950408889634f

// ---------------- scratch (device globals; no allocation allowed) ----------
__device__ __half g_Xq[MROWS * HID];
__device__ __half g_Xk[MROWS * HID];
__device__ __half g_Xv[MROWS * HID];
__device__ __half g_Qh[MROWS * HID];
__device__ __half g_Kh[MROWS * HID];
__device__ __half g_Vh[MROWS * HID];
__device__ __half g_Ctx[MROWS * HID];
__device__ __half g_Wqh[HID * HID];
__device__ __half g_Wkh[HID * HID];
__device__ __half g_Wvh[HID * HID];
__device__ __half g_Woh[HID * HID];
__device__ float g_invf[HID / 2];
__device__ float4 g_tab[SEQ * (HID / 2)];

// ---------------- helpers ----------------------------------------
__device__ __forceinline__ uint32_t smem_u32(const void* p) {
    uint32_t a;
    asm("{ .reg .u64 t; cvta.to.shared.u64 t, %1; cvt.u32.u64 %0, t; }"
        : "=r"(a) : "l"(p));
    return a;
}
__device__ __forceinline__ void cp16(uint32_t dst, const void* src) {
    asm volatile("cp.async.cg.shared.global [%0], [%1], 16;" :: "r"(dst), "l"(src));
}
#define CP_COMMIT() asm volatile("cp.async.commit_group;" ::: "memory")
#define CP_WAIT1()  asm volatile("cp.async.wait_group 1;" ::: "memory")

__device__ __forceinline__ void ldm4(uint32_t* r, uint32_t addr) {
    asm volatile("ldmatrix.sync.aligned.m8n8.x4.shared.b16 {%0,%1,%2,%3}, [%4];"
                 : "=r"(r[0]), "=r"(r[1]), "=r"(r[2]), "=r"(r[3]) : "r"(addr));
}
__device__ __forceinline__ void ldm4t(uint32_t* r, uint32_t addr) {
    asm volatile("ldmatrix.sync.aligned.m8n8.x4.trans.shared.b16 {%0,%1,%2,%3}, [%4];"
                 : "=r"(r[0]), "=r"(r[1]), "=r"(r[2]), "=r"(r[3]) : "r"(addr));
}
__device__ __forceinline__ void mma16816(float* d, const uint32_t* a,
                                         uint32_t b0, uint32_t b1) {
    asm volatile(
        "mma.sync.aligned.m16n8k16.row.col.f32.f16.f16.f32 "
        "{%0,%1,%2,%3}, {%4,%5,%6,%7}, {%8,%9}, {%0,%1,%2,%3};"
        : "+f"(d[0]), "+f"(d[1]), "+f"(d[2]), "+f"(d[3])
        : "r"(a[0]), "r"(a[1]), "r"(a[2]), "r"(a[3]), "r"(b0), "r"(b1));
}
// packed f32x2 multiply (two independent fp32 muls, bit-identical semantics)
__device__ __forceinline__ void f2mul(unsigned long long& d, unsigned long long a,
                                      unsigned long long b) {
    asm("mul.rn.f32x2 %0, %1, %2;" : "+l"(d) : "l"(a), "l"(b));
}
__device__ __forceinline__ uint32_t pk2h(float x, float y) {
    __half2 h = __floats2half2_rn(x, y);
    return *reinterpret_cast<uint32_t*>(&h);
}
// fp16x2 exp2 (single MUFU op for two values)
__device__ __forceinline__ uint32_t h2exp2(uint32_t x) {
    uint32_t r;
    asm("ex2.approx.f16x2 %0, %1;" : "=r"(r) : "r"(x));
    return r;
}
__device__ __forceinline__ float2 h2f2(uint32_t x) {
    __half2 h = *reinterpret_cast<__half2*>(&x);
    return __half22float2(h);
}
__device__ __forceinline__ uint4 cvt8h(const float4& u, const float4& v) {
    __half2 h0 = __floats2half2_rn(u.x, u.y);
    __half2 h1 = __floats2half2_rn(u.z, u.w);
    __half2 h2 = __floats2half2_rn(v.x, v.y);
    __half2 h3 = __floats2half2_rn(v.z, v.w);
    return make_uint4(*(uint32_t*)&h0, *(uint32_t*)&h1, *(uint32_t*)&h2, *(uint32_t*)&h3);
}
// permutation: n' = 128p + 64s + i  ->  orig = 64p + 512s + i
__device__ __forceinline__ int perm_orig(int n) {
    int p = n >> 7, s = (n >> 6) & 1, i = n & 63;
    return 64 * p + 512 * s + i;
}

// ============================================================================
// prep kernels
// ============================================================================
__global__ __launch_bounds__(256) void prep_act(
    const float* __restrict__ Xq, const float* __restrict__ Xk,
    const float* __restrict__ Xv)
{
    const float* X = (blockIdx.y == 0) ? Xq : (blockIdx.y == 1) ? Xk : Xv;
    __half* O = (blockIdx.y == 0) ? g_Xq : (blockIdx.y == 1) ? g_Xk : g_Xv;
    int idx = blockIdx.x * 256 + threadIdx.x;
    float4 u = ((const float4*)X)[2 * idx];
    float4 v = ((const float4*)X)[2 * idx + 1];
    ((uint4*)O)[idx] = cvt8h(u, v);
}

__global__ __launch_bounds__(256) void prep_w_all(
    const float* __restrict__ Wq, const float* __restrict__ Wk,
    const float* __restrict__ Wv, const float* __restrict__ Wo)
{
    int idx = blockIdx.x * 256 + threadIdx.x;
    int n = idx >> 7;
    int c8 = (idx & 127) * 8;
    if (blockIdx.y < 3) {
        const float* W = (blockIdx.y == 0) ? Wq : (blockIdx.y == 1) ? Wk : Wv;
        __half* Wh = (blockIdx.y == 0) ? g_Wqh : (blockIdx.y == 1) ? g_Wkh : g_Wvh;
        int orig = perm_orig(n);
        float4 u = *(const float4*)(W + (size_t)orig * HID + c8);
        float4 v = *(const float4*)(W + (size_t)orig * HID + c8 + 4);
        *(uint4*)(Wh + (size_t)n * HID + c8) = cvt8h(u, v);
    } else {
        int orig = perm_orig(c8);
        float4 u = *(const float4*)(Wo + (size_t)n * HID + orig);
        float4 v = *(const float4*)(Wo + (size_t)n * HID + orig + 4);
        *(uint4*)(g_Woh + (size_t)n * HID + c8) = cvt8h(u, v);
    }
}

__global__ void make_invf_kernel() {
    int j = threadIdx.x;
    if (j < HID / 2) {
        double e = exp(-((double)(2 * j) / (double)HID) * log(10000.0));
        g_invf[j] = (float)e;
    }
}
__global__ __launch_bounds__(256) void rope_table_kernel() {
    int idx = blockIdx.x * 256 + threadIdx.x;
    int s = idx >> 9;
    int j = idx & 511;
    float t = (float)s * g_invf[j];
    float st, ct;
    sincosf(t, &st, &ct);
    float s1, c1, s2, c2;
    sincosf(st, &s1, &c1);
    sincosf(ct, &s2, &c2);
    g_tab[idx] = make_float4(c1, s1, c2, s2);
}

// ============================================================================
// shared GEMM machinery: fp16 NT, CTA 128x128, warp 64x32, K-chunk 64,
// 3-stage cp.async ring (36KB/stage). One __syncthreads per kc (16 total).
// ============================================================================
#define RSTRIDE 144
#define TILE_B (128 * RSTRIDE)      // 18432
#define STG (2 * TILE_B)            // 36864 (A, B)
#define GEMM_SMEM (3 * STG)         // 110592
#define SROW 132

__device__ __forceinline__ void issue_stage(
    const __half* A, const __half* B, int kc, uint32_t st, int tid)
{
    const size_t ko = (size_t)kc * 64;
#pragma unroll
    for (int t = 0; t < 8; t++) {
        const __half* g = (t < 4) ? A : B;
        const int tile = t >> 2;
        const int rem = ((t & 3) << 8) + tid;
        const int row = rem >> 3;
        const int c = rem & 7;
        cp16(st + tile * TILE_B + row * RSTRIDE + c * 16,
             g + (size_t)row * HID + ko + c * 8);
    }
}

__device__ __forceinline__ void gemm_mainloop(
    const __half* Ap, const __half* Bp, uint32_t sbase,
    uint32_t aoff, uint32_t boff, int wm, int wn, int tid,
    float acc[4][4][4])
{
    issue_stage(Ap, Bp, 0, sbase, tid);
    CP_COMMIT();
    issue_stage(Ap, Bp, 1, sbase + STG, tid);
    CP_COMMIT();

    for (int kc = 0; kc < 16; kc++) {
        CP_WAIT1();
        __syncthreads();
        if (kc + 2 < 16)
            issue_stage(Ap, Bp, kc + 2, sbase + ((kc + 2) % 3) * STG, tid);
        CP_COMMIT();

        const uint32_t base = sbase + (kc % 3) * STG;
#pragma unroll
        for (int ks = 0; ks < 4; ks++) {
            const uint32_t kb = ks * 32;
            uint32_t ah[4][4];
#pragma unroll
            for (int mf = 0; mf < 4; mf++) {
                uint32_t ro = (uint32_t)((wm * 64 + mf * 16) * RSTRIDE) + kb;
                ldm4(ah[mf], base + ro + aoff);
            }
            uint32_t bh[2][4];
#pragma unroll
            for (int p = 0; p < 2; p++) {
                uint32_t ro = (uint32_t)((wn * 32 + p * 16) * RSTRIDE) + kb;
                ldm4(bh[p], base + TILE_B + ro + boff);
            }
#pragma unroll
            for (int mf = 0; mf < 4; mf++) {
#pragma unroll
                for (int nf = 0; nf < 4; nf++) {
                    const int p = nf >> 1, q = nf & 1;
                    mma16816(acc[mf][nf], ah[mf], bh[p][2 * q], bh[p][2 * q + 1]);
                }
            }
        }
    }
    __syncthreads();
}

// ============================================================================
// fused QKV projection, ALL THREE in one launch (blockIdx.z selects q/k/v).
// ============================================================================
__global__ __launch_bounds__(256)
void gemm_qkv(const float* __restrict__ bq, const float* __restrict__ bk,
              const float* __restrict__ bv)
{
    extern __shared__ __align__(128) char smem[];

    const int z = blockIdx.z;
    const __half* X   = (z == 0) ? g_Xq : (z == 1) ? g_Xk : g_Xv;
    const __half* Bw  = (z == 0) ? g_Wqh : (z == 1) ? g_Wkh : g_Wvh;
    const float* bias = (z == 0) ? bq : (z == 1) ? bk : bv;
    __half* outh      = (z == 0) ? g_Qh : (z == 1) ? g_Kh : g_Vh;
    const float scale = (z == 0) ? (0.125f * LOG2E) : 1.0f;

    const int tid  = threadIdx.x;
    const int wid  = tid >> 5;
    const int lane = tid & 31;
    const int wm   = wid & 1;
    const int wn   = wid >> 1;
    const int brow = blockIdx.y * 128;
    const int bcol = blockIdx.x * 128;

    const uint32_t sbase = smem_u32(smem);
    const uint32_t aoff = (uint32_t)(((lane & 7) + ((lane >> 3) & 1) * 8) * RSTRIDE
                                     + ((lane >> 4) & 1) * 16);
    const uint32_t boff = (uint32_t)(((lane & 7) + ((lane >> 4) & 1) * 8) * RSTRIDE
                                     + ((lane >> 3) & 1) * 16);

    float acc[4][4][4];
#pragma unroll
    for (int i = 0; i < 4; i++)
#pragma unroll
        for (int j = 0; j < 4; j++)
#pragma unroll
            for (int r = 0; r < 4; r++) acc[i][j][r] = 0.0f;

    gemm_mainloop(X + (size_t)brow * HID, Bw + (size_t)bcol * HID,
                  sbase, aoff, boff, wm, wn, tid, acc);

    float* sm = (float*)smem;
    const int g  = lane >> 2;
    const int t2 = (lane & 3) * 2;
#pragma unroll
    for (int mf = 0; mf < 4; mf++) {
        const int lr = wm * 64 + mf * 16 + g;
#pragma unroll
        for (int nf = 0; nf < 4; nf++) {
            const int lc = wn * 32 + nf * 8 + t2;
            *(float2*)(sm + lr * SROW + lc)       = make_float2(acc[mf][nf][0], acc[mf][nf][1]);
            *(float2*)(sm + (lr + 8) * SROW + lc) = make_float2(acc[mf][nf][2], acc[mf][nf][3]);
        }
    }
    __syncthreads();

    const int pblk = bcol >> 7;
#pragma unroll
    for (int it = 0; it < 16; it++) {
        int idx = it * 256 + tid;
        int r  = idx >> 5;
        int c0 = (idx & 31) * 2;
        int srow = (brow + r) & (SEQ - 1);
        int j0 = 64 * pblk + c0;
        float4 t0 = g_tab[(srow << 9) | j0];
        float4 t1 = g_tab[(srow << 9) | (j0 + 1)];
        float x1a = sm[r * SROW + c0]      + bias[j0];
        float x1b = sm[r * SROW + c0 + 1]  + bias[j0 + 1];
        float x2a = sm[r * SROW + c0 + 64] + bias[j0 + 512];
        float x2b = sm[r * SROW + c0 + 65] + bias[j0 + 513];
        float y1a = (x1a * t0.x + x2a * t0.y) * scale;
        float y2a = (x2a * t0.z - x1a * t0.w) * scale;
        float y1b = (x1b * t1.x + x2b * t1.y) * scale;
        float y2b = (x2b * t1.z - x1b * t1.w) * scale;
        size_t gb = (size_t)(brow + r) * HID + bcol;
        *(uint32_t*)(outh + gb + c0)      = pk2h(y1a, y1b);
        *(uint32_t*)(outh + gb + 64 + c0) = pk2h(y2a, y2b);
    }
}

// ============================================================================
// output projection: out = Ctx*Wo'^T + bo (fp32).
// ============================================================================
__global__ __launch_bounds__(256)
void gemm_out(const __half* __restrict__ Actx, const __half* __restrict__ Bw,
              const float* __restrict__ bias, float* __restrict__ Y)
{
    extern __shared__ __align__(128) char smem[];

    const int tid  = threadIdx.x;
    const int wid  = tid >> 5;
    const int lane = tid & 31;
    const int wm   = wid & 1;
    const int wn   = wid >> 1;
    const int brow = blockIdx.y * 128;
    const int bcol = blockIdx.x * 128;

    const uint32_t sbase = smem_u32(smem);
    const uint32_t aoff = (uint32_t)(((lane & 7) + ((lane >> 3) & 1) * 8) * RSTRIDE
                                     + ((lane >> 4) & 1) * 16);
    const uint32_t boff = (uint32_t)(((lane & 7) + ((lane >> 4) & 1) * 8) * RSTRIDE
                                     + ((lane >> 3) & 1) * 16);

    float acc[4][4][4];
#pragma unroll
    for (int i = 0; i < 4; i++)
#pragma unroll
        for (int j = 0; j < 4; j++)
#pragma unroll
            for (int r = 0; r < 4; r++) acc[i][j][r] = 0.0f;

    gemm_mainloop(Actx + (size_t)brow * HID, Bw + (size_t)bcol * HID,
                  sbase, aoff, boff, wm, wn, tid, acc);

    const int g = lane >> 2;
    const int t2 = (lane & 3) * 2;
#pragma unroll
    for (int mf = 0; mf < 4; mf++) {
        const int row0 = brow + wm * 64 + mf * 16 + g;
#pragma unroll
        for (int nf = 0; nf < 4; nf++) {
            const int col = bcol + wn * 32 + nf * 8 + t2;
            float2 bv = *(const float2*)(bias + col);
            *(float2*)(Y + (size_t)row0 * HID + col) =
                make_float2(acc[mf][nf][0] + bv.x, acc[mf][nf][1] + bv.y);
            *(float2*)(Y + (size_t)(row0 + 8) * HID + col) =
                make_float2(acc[mf][nf][2] + bv.x, acc[mf][nf][3] + bv.y);
        }
    }
}

// ============================================================================
// tensor-core flash attention: pure fp16 operands, exp2-domain softmax with
// ex2.approx.f16x2 (P computed directly as fp16 pairs), 3-stage KV ring
// (one __syncthreads per kt). Ctx written as single fp16.
// ============================================================================
#define AST 144
#define AQ 0
#define AKV0 (128 * AST)              // 18432
#define KVSTG (2 * 64 * AST)          // 18432 (K, V)
#define ATTN_SMEM (AKV0 + 3 * KVSTG)  // 73728

__device__ __forceinline__ void attn_issue_kv(
    int krow0, size_t colbase, uint32_t kvbase, int tid)
{
#pragma unroll
    for (int i = 0; i < 4; i++) {
        const __half* g = (i < 2) ? g_Kh : g_Vh;
        const int arr = i >> 1;
        const int rem = ((i & 1) << 8) + tid;
        const int row = rem >> 3;
        const int c = rem & 7;
        cp16(kvbase + arr * (64 * AST) + row * AST + c * 16,
             g + (size_t)(krow0 + row) * HID + colbase + c * 8);
    }
}

__global__ __launch_bounds__(256, 2) void attn_mma() {
    extern __shared__ __align__(128) char smem[];

    const int tid  = threadIdx.x;
    const int wid  = tid >> 5;
    const int lane = tid & 31;
    const int qt   = blockIdx.x;
    const int bh   = blockIdx.y;
    const int b    = bh >> 4;
    const int h    = bh & 15;
    const int qbase = b * SEQ + qt * 128;
    const size_t colbase = (size_t)h * HD;
    const int krow_base = b * SEQ;

    const uint32_t sb = smem_u32(smem);

    const uint32_t aoff = (uint32_t)(((lane & 7) + ((lane >> 3) & 1) * 8) * AST
                                     + ((lane >> 4) & 1) * 16);
    const uint32_t boff = (uint32_t)(((lane & 7) + ((lane >> 4) & 1) * 8) * AST
                                     + ((lane >> 3) & 1) * 16);
    const uint32_t voff = (uint32_t)(((lane & 7) + ((lane >> 3) & 1) * 8) * AST
                                     + ((lane >> 4) & 1) * 16);

#pragma unroll
    for (int i = 0; i < 4; i++) {
        const int rem = (i << 8) + tid;
        const int row = rem >> 3;
        const int c = rem & 7;
        cp16(sb + AQ + row * AST + c * 16,
             g_Qh + (size_t)(qbase + row) * HID + colbase + c * 8);
    }
    attn_issue_kv(krow_base, colbase, sb + AKV0, tid);
    CP_COMMIT();
    attn_issue_kv(krow_base + 64, colbase, sb + AKV0 + KVSTG, tid);
    CP_COMMIT();

    unsigned long long o2[8][2];
#pragma unroll
    for (int nf = 0; nf < 8; nf++) { o2[nf][0] = 0ULL; o2[nf][1] = 0ULL; }
    float m0 = -1e30f, m1 = -1e30f, l0 = 0.0f, l1 = 0.0f;

    const uint32_t qrow_off = (uint32_t)(wid * 16 * AST);

    for (int kt = 0; kt < 16; kt++) {
        CP_WAIT1();
        __syncthreads();
        if (kt + 2 < 16)
            attn_issue_kv(krow_base + (kt + 2) * 64, colbase,
                          sb + AKV0 + ((kt + 2) % 3) * KVSTG, tid);
        CP_COMMIT();

        const uint32_t kvb = sb + AKV0 + (kt % 3) * KVSTG;
        const uint32_t akh = kvb;
        const uint32_t avh = kvb + 64 * AST;

        float sfr[8][4];
#pragma unroll
        for (int nf = 0; nf < 8; nf++)
#pragma unroll
            for (int r = 0; r < 4; r++) sfr[nf][r] = 0.0f;

#pragma unroll
        for (int kq = 0; kq < 4; kq++) {
            uint32_t qh[4];
            ldm4(qh, sb + AQ + qrow_off + kq * 32 + aoff);
            uint32_t kh[4][4];
#pragma unroll
            for (int p = 0; p < 4; p++)
                ldm4(kh[p], akh + (uint32_t)(p * 16 * AST) + kq * 32 + boff);
#pragma unroll
            for (int nf = 0; nf < 8; nf++) {
                const int p = nf >> 1, q = nf & 1;
                mma16816(sfr[nf], qh, kh[p][2 * q], kh[p][2 * q + 1]);
            }
        }

        float mx0 = -1e30f, mx1 = -1e30f;
#pragma unroll
        for (int nf = 0; nf < 8; nf++) {
            mx0 = fmaxf(mx0, fmaxf(sfr[nf][0], sfr[nf][1]));
            mx1 = fmaxf(mx1, fmaxf(sfr[nf][2], sfr[nf][3]));
        }
        mx0 = fmaxf(mx0, __shfl_xor_sync(0xFFFFFFFF, mx0, 1));
        mx0 = fmaxf(mx0, __shfl_xor_sync(0xFFFFFFFF, mx0, 2));
        mx1 = fmaxf(mx1, __shfl_xor_sync(0xFFFFFFFF, mx1, 1));
        mx1 = fmaxf(mx1, __shfl_xor_sync(0xFFFFFFFF, mx1, 2));

        float mn0 = fmaxf(m0, mx0), mn1 = fmaxf(m1, mx1);
        float c0 = exp2f(m0 - mn0), c1 = exp2f(m1 - mn1);
        l0 *= c0; l1 *= c1;
        unsigned long long c0p, c1p;
        asm("mov.b64 %0, {%1, %1};" : "=l"(c0p) : "f"(c0));
        asm("mov.b64 %0, {%1, %1};" : "=l"(c1p) : "f"(c1));
#pragma unroll
        for (int nf = 0; nf < 8; nf++) {
            f2mul(o2[nf][0], o2[nf][0], c0p);
            f2mul(o2[nf][1], o2[nf][1], c1p);
        }

        // P = exp2(s - mn) via fp16x2 MUFU; result IS the PV A-fragment.
        uint32_t pex[8][2];
#pragma unroll
        for (int nf = 0; nf < 8; nf++) {
            pex[nf][0] = h2exp2(pk2h(sfr[nf][0] - mn0, sfr[nf][1] - mn0));
            pex[nf][1] = h2exp2(pk2h(sfr[nf][2] - mn1, sfr[nf][3] - mn1));
            float2 f0 = h2f2(pex[nf][0]);
            float2 f1 = h2f2(pex[nf][1]);
            l0 += f0.x + f0.y;
            l1 += f1.x + f1.y;
        }
        m0 = mn0; m1 = mn1;

#pragma unroll
        for (int kk = 0; kk < 4; kk++) {
            uint32_t ah[4];
            ah[0] = pex[2 * kk][0];
            ah[1] = pex[2 * kk][1];
            ah[2] = pex[2 * kk + 1][0];
            ah[3] = pex[2 * kk + 1][1];

            uint32_t vh[4][4];
#pragma unroll
            for (int p = 0; p < 4; p++) {
                uint32_t ro = (uint32_t)(kk * 16 * AST) + (uint32_t)(p * 32);
                ldm4t(vh[p], avh + ro + voff);
            }
#pragma unroll
            for (int nf = 0; nf < 8; nf++) {
                const int p = nf >> 1, q = nf & 1;
                mma16816((float*)o2[nf], ah, vh[p][2 * q], vh[p][2 * q + 1]);
            }
        }
    }

    l0 += __shfl_xor_sync(0xFFFFFFFF, l0, 1);
    l0 += __shfl_xor_sync(0xFFFFFFFF, l0, 2);
    l1 += __shfl_xor_sync(0xFFFFFFFF, l1, 1);
    l1 += __shfl_xor_sync(0xFFFFFFFF, l1, 2);
    float inv0 = 1.0f / l0, inv1 = 1.0f / l1;

    const int g  = lane >> 2;
    const int t2 = (lane & 3) * 2;
    const int row0 = qbase + wid * 16 + g;
#pragma unroll
    for (int nf = 0; nf < 8; nf++) {
        size_t col = colbase + nf * 8 + t2;
        const float* of = (const float*)o2[nf];
        *(uint32_t*)(g_Ctx + (size_t)row0 * HID + col) =
            pk2h(of[0] * inv0, of[1] * inv0);
        *(uint32_t*)(g_Ctx + (size_t)(row0 + 8) * HID + col) =
            pk2h(of[2] * inv1, of[3] * inv1);
    }
}

// ============================================================================
// launch
// ============================================================================
extern "C" void kernel_launch(void* const* d_in, const int* in_sizes, int n_in,
                              void* d_out, int out_size) {
    (void)in_sizes; (void)n_in; (void)out_size;
    const float* query = (const float*)d_in[0];
    const float* key   = (const float*)d_in[1];
    const float* value = (const float*)d_in[2];
    const float* Wq    = (const float*)d_in[3];
    const float* bq    = (const float*)d_in[4];
    const float* Wk    = (const float*)d_in[5];
    const float* bk    = (const float*)d_in[6];
    const float* Wv    = (const float*)d_in[7];
    const float* bv    = (const float*)d_in[8];
    const float* Wo    = (const float*)d_in[9];
    const float* bo    = (const float*)d_in[10];
    float* out = (float*)d_out;

    __half *Ctx, *Woh;
    cudaGetSymbolAddress((void**)&Ctx, g_Ctx);
    cudaGetSymbolAddress((void**)&Woh, g_Woh);

    cudaFuncSetAttribute(gemm_qkv, cudaFuncAttributeMaxDynamicSharedMemorySize, GEMM_SMEM);
    cudaFuncSetAttribute(gemm_out, cudaFuncAttributeMaxDynamicSharedMemorySize, GEMM_SMEM);
    cudaFuncSetAttribute(attn_mma, cudaFuncAttributeMaxDynamicSharedMemorySize, ATTN_SMEM);

    const int wblocks = (HID * HID / 8) / 256;      // 512
    const int ablocks = (MROWS * HID / 8) / 256;    // 4096

    make_invf_kernel<<<1, 512>>>();
    rope_table_kernel<<<(SEQ * 512) / 256, 256>>>();

    prep_w_all<<<dim3(wblocks, 4), 256>>>(Wq, Wk, Wv, Wo);
    prep_act<<<dim3(ablocks, 3), 256>>>(query, key, value);

    gemm_qkv<<<dim3(HID / 128, MROWS / 128, 3), 256, GEMM_SMEM>>>(bq, bk, bv);

    attn_mma<<<dim3(8, 128), 256, ATTN_SMEM>>>();

    gemm_out<<<dim3(HID / 128, MROWS / 128), 256, GEMM_SMEM>>>(Ctx, Woh, bo, out);
}

// round 17
// speedup vs baseline: 2.3079x; 1.0101x over previous
#include <cuda_runtime.h>
#include <cuda_fp16.h>
#include <cstdint>

#define HID 1024
#define HEADS 16
#define HD 64
#define BATCH 8
#define SEQ 1024
#define MROWS (BATCH * SEQ)
#define LOG2E 1.4426950408889634f

// ---------------- scratch (device globals; no allocation allowed) ----------
__device__ __half g_Xq[MROWS * HID];
__device__ __half g_Xk[MROWS * HID];
__device__ __half g_Xv[MROWS * HID];
__device__ __half g_Qh[MROWS * HID];
__device__ __half g_Kh[MROWS * HID];
__device__ __half g_Vh[MROWS * HID];
__device__ __half g_Ctx[MROWS * HID];
__device__ __half g_Wqh[HID * HID];
__device__ __half g_Wkh[HID * HID];
__device__ __half g_Wvh[HID * HID];
__device__ __half g_Woh[HID * HID];
__device__ float g_invf[HID / 2];
__device__ float4 g_tab[SEQ * (HID / 2)];

// ---------------- helpers ----------------------------------------
__device__ __forceinline__ uint32_t smem_u32(const void* p) {
    uint32_t a;
    asm("{ .reg .u64 t; cvta.to.shared.u64 t, %1; cvt.u32.u64 %0, t; }"
        : "=r"(a) : "l"(p));
    return a;
}
__device__ __forceinline__ void cp16(uint32_t dst, const void* src) {
    asm volatile("cp.async.cg.shared.global [%0], [%1], 16;" :: "r"(dst), "l"(src));
}
#define CP_COMMIT() asm volatile("cp.async.commit_group;" ::: "memory")
#define CP_WAIT1()  asm volatile("cp.async.wait_group 1;" ::: "memory")

__device__ __forceinline__ void ldm4(uint32_t* r, uint32_t addr) {
    asm volatile("ldmatrix.sync.aligned.m8n8.x4.shared.b16 {%0,%1,%2,%3}, [%4];"
                 : "=r"(r[0]), "=r"(r[1]), "=r"(r[2]), "=r"(r[3]) : "r"(addr));
}
__device__ __forceinline__ void ldm4t(uint32_t* r, uint32_t addr) {
    asm volatile("ldmatrix.sync.aligned.m8n8.x4.trans.shared.b16 {%0,%1,%2,%3}, [%4];"
                 : "=r"(r[0]), "=r"(r[1]), "=r"(r[2]), "=r"(r[3]) : "r"(addr));
}
__device__ __forceinline__ void mma16816(float* d, const uint32_t* a,
                                         uint32_t b0, uint32_t b1) {
    asm volatile(
        "mma.sync.aligned.m16n8k16.row.col.f32.f16.f16.f32 "
        "{%0,%1,%2,%3}, {%4,%5,%6,%7}, {%8,%9}, {%0,%1,%2,%3};"
        : "+f"(d[0]), "+f"(d[1]), "+f"(d[2]), "+f"(d[3])
        : "r"(a[0]), "r"(a[1]), "r"(a[2]), "r"(a[3]), "r"(b0), "r"(b1));
}
// packed f32x2 multiply (two independent fp32 muls, bit-identical semantics)
__device__ __forceinline__ void f2mul(unsigned long long& d, unsigned long long a,
                                      unsigned long long b) {
    asm("mul.rn.f32x2 %0, %1, %2;" : "+l"(d) : "l"(a), "l"(b));
}
__device__ __forceinline__ uint32_t pk2h(float x, float y) {
    __half2 h = __floats2half2_rn(x, y);
    return *reinterpret_cast<uint32_t*>(&h);
}
// fp16x2 exp2 (single MUFU op for two values)
__device__ __forceinline__ uint32_t h2exp2(uint32_t x) {
    uint32_t r;
    asm("ex2.approx.f16x2 %0, %1;" : "=r"(r) : "r"(x));
    return r;
}
__device__ __forceinline__ uint4 cvt8h(const float4& u, const float4& v) {
    __half2 h0 = __floats2half2_rn(u.x, u.y);
    __half2 h1 = __floats2half2_rn(u.z, u.w);
    __half2 h2 = __floats2half2_rn(v.x, v.y);
    __half2 h3 = __floats2half2_rn(v.z, v.w);
    return make_uint4(*(uint32_t*)&h0, *(uint32_t*)&h1, *(uint32_t*)&h2, *(uint32_t*)&h3);
}
// permutation: n' = 128p + 64s + i  ->  orig = 64p + 512s + i
__device__ __forceinline__ int perm_orig(int n) {
    int p = n >> 7, s = (n >> 6) & 1, i = n & 63;
    return 64 * p + 512 * s + i;
}

// ============================================================================
// merged prep: blockIdx.y 0..2 -> activation fp16 convert; y==3 -> weights.
// ============================================================================
__global__ __launch_bounds__(256) void prep_all(
    const float* __restrict__ Xq, const float* __restrict__ Xk,
    const float* __restrict__ Xv,
    const float* __restrict__ Wq, const float* __restrict__ Wk,
    const float* __restrict__ Wv, const float* __restrict__ Wo)
{
    if (blockIdx.y < 3) {
        const float* X = (blockIdx.y == 0) ? Xq : (blockIdx.y == 1) ? Xk : Xv;
        __half* O = (blockIdx.y == 0) ? g_Xq : (blockIdx.y == 1) ? g_Xk : g_Xv;
        int idx = blockIdx.x * 256 + threadIdx.x;
        float4 u = ((const float4*)X)[2 * idx];
        float4 v = ((const float4*)X)[2 * idx + 1];
        ((uint4*)O)[idx] = cvt8h(u, v);
        return;
    }
    // weights: 4 x 512 blocks of work within blockIdx.x in [0, 2048)
    if (blockIdx.x >= 2048) return;
    const int w = blockIdx.x >> 9;              // 0..3
    int idx = (blockIdx.x & 511) * 256 + threadIdx.x;   // HID*HID/8
    int n = idx >> 7;
    int c8 = (idx & 127) * 8;
    if (w < 3) {
        const float* W = (w == 0) ? Wq : (w == 1) ? Wk : Wv;
        __half* Wh = (w == 0) ? g_Wqh : (w == 1) ? g_Wkh : g_Wvh;
        int orig = perm_orig(n);
        float4 u = *(const float4*)(W + (size_t)orig * HID + c8);
        float4 v = *(const float4*)(W + (size_t)orig * HID + c8 + 4);
        *(uint4*)(Wh + (size_t)n * HID + c8) = cvt8h(u, v);
    } else {
        int orig = perm_orig(c8);
        float4 u = *(const float4*)(Wo + (size_t)n * HID + orig);
        float4 v = *(const float4*)(Wo + (size_t)n * HID + orig + 4);
        *(uint4*)(g_Woh + (size_t)n * HID + c8) = cvt8h(u, v);
    }
}

__global__ void make_invf_kernel() {
    int j = threadIdx.x;
    if (j < HID / 2) {
        double e = exp(-((double)(2 * j) / (double)HID) * log(10000.0));
        g_invf[j] = (float)e;
    }
}
__global__ __launch_bounds__(256) void rope_table_kernel() {
    int idx = blockIdx.x * 256 + threadIdx.x;
    int s = idx >> 9;
    int j = idx & 511;
    float t = (float)s * g_invf[j];
    float st, ct;
    sincosf(t, &st, &ct);
    float s1, c1, s2, c2;
    sincosf(st, &s1, &c1);
    sincosf(ct, &s2, &c2);
    g_tab[idx] = make_float4(c1, s1, c2, s2);
}

// ============================================================================
// shared GEMM machinery: fp16 NT, CTA 128x128, warp 64x32, K-chunk 64,
// 3-stage cp.async ring (36KB/stage). One __syncthreads per kc (16 total).
// ============================================================================
#define RSTRIDE 144
#define TILE_B (128 * RSTRIDE)      // 18432
#define STG (2 * TILE_B)            // 36864 (A, B)
#define GEMM_SMEM (3 * STG)         // 110592
#define SROW 132

__device__ __forceinline__ void issue_stage(
    const __half* A, const __half* B, int kc, uint32_t st, int tid)
{
    const size_t ko = (size_t)kc * 64;
#pragma unroll
    for (int t = 0; t < 8; t++) {
        const __half* g = (t < 4) ? A : B;
        const int tile = t >> 2;
        const int rem = ((t & 3) << 8) + tid;
        const int row = rem >> 3;
        const int c = rem & 7;
        cp16(st + tile * TILE_B + row * RSTRIDE + c * 16,
             g + (size_t)row * HID + ko + c * 8);
    }
}

__device__ __forceinline__ void gemm_mainloop(
    const __half* Ap, const __half* Bp, uint32_t sbase,
    uint32_t aoff, uint32_t boff, int wm, int wn, int tid,
    float acc[4][4][4])
{
    issue_stage(Ap, Bp, 0, sbase, tid);
    CP_COMMIT();
    issue_stage(Ap, Bp, 1, sbase + STG, tid);
    CP_COMMIT();

    for (int kc = 0; kc < 16; kc++) {
        CP_WAIT1();
        __syncthreads();
        if (kc + 2 < 16)
            issue_stage(Ap, Bp, kc + 2, sbase + ((kc + 2) % 3) * STG, tid);
        CP_COMMIT();

        const uint32_t base = sbase + (kc % 3) * STG;
#pragma unroll
        for (int ks = 0; ks < 4; ks++) {
            const uint32_t kb = ks * 32;
            uint32_t ah[4][4];
#pragma unroll
            for (int mf = 0; mf < 4; mf++) {
                uint32_t ro = (uint32_t)((wm * 64 + mf * 16) * RSTRIDE) + kb;
                ldm4(ah[mf], base + ro + aoff);
            }
            uint32_t bh[2][4];
#pragma unroll
            for (int p = 0; p < 2; p++) {
                uint32_t ro = (uint32_t)((wn * 32 + p * 16) * RSTRIDE) + kb;
                ldm4(bh[p], base + TILE_B + ro + boff);
            }
#pragma unroll
            for (int mf = 0; mf < 4; mf++) {
#pragma unroll
                for (int nf = 0; nf < 4; nf++) {
                    const int p = nf >> 1, q = nf & 1;
                    mma16816(acc[mf][nf], ah[mf], bh[p][2 * q], bh[p][2 * q + 1]);
                }
            }
        }
    }
    __syncthreads();
}

// ============================================================================
// fused QKV projection, ALL THREE in one launch (blockIdx.z selects q/k/v).
// ============================================================================
__global__ __launch_bounds__(256)
void gemm_qkv(const float* __restrict__ bq, const float* __restrict__ bk,
              const float* __restrict__ bv)
{
    extern __shared__ __align__(128) char smem[];

    const int z = blockIdx.z;
    const __half* X   = (z == 0) ? g_Xq : (z == 1) ? g_Xk : g_Xv;
    const __half* Bw  = (z == 0) ? g_Wqh : (z == 1) ? g_Wkh : g_Wvh;
    const float* bias = (z == 0) ? bq : (z == 1) ? bk : bv;
    __half* outh      = (z == 0) ? g_Qh : (z == 1) ? g_Kh : g_Vh;
    const float scale = (z == 0) ? (0.125f * LOG2E) : 1.0f;

    const int tid  = threadIdx.x;
    const int wid  = tid >> 5;
    const int lane = tid & 31;
    const int wm   = wid & 1;
    const int wn   = wid >> 1;
    const int brow = blockIdx.y * 128;
    const int bcol = blockIdx.x * 128;

    const uint32_t sbase = smem_u32(smem);
    const uint32_t aoff = (uint32_t)(((lane & 7) + ((lane >> 3) & 1) * 8) * RSTRIDE
                                     + ((lane >> 4) & 1) * 16);
    const uint32_t boff = (uint32_t)(((lane & 7) + ((lane >> 4) & 1) * 8) * RSTRIDE
                                     + ((lane >> 3) & 1) * 16);

    float acc[4][4][4];
#pragma unroll
    for (int i = 0; i < 4; i++)
#pragma unroll
        for (int j = 0; j < 4; j++)
#pragma unroll
            for (int r = 0; r < 4; r++) acc[i][j][r] = 0.0f;

    gemm_mainloop(X + (size_t)brow * HID, Bw + (size_t)bcol * HID,
                  sbase, aoff, boff, wm, wn, tid, acc);

    float* sm = (float*)smem;
    const int g  = lane >> 2;
    const int t2 = (lane & 3) * 2;
#pragma unroll
    for (int mf = 0; mf < 4; mf++) {
        const int lr = wm * 64 + mf * 16 + g;
#pragma unroll
        for (int nf = 0; nf < 4; nf++) {
            const int lc = wn * 32 + nf * 8 + t2;
            *(float2*)(sm + lr * SROW + lc)       = make_float2(acc[mf][nf][0], acc[mf][nf][1]);
            *(float2*)(sm + (lr + 8) * SROW + lc) = make_float2(acc[mf][nf][2], acc[mf][nf][3]);
        }
    }
    __syncthreads();

    const int pblk = bcol >> 7;
#pragma unroll
    for (int it = 0; it < 16; it++) {
        int idx = it * 256 + tid;
        int r  = idx >> 5;
        int c0 = (idx & 31) * 2;
        int srow = (brow + r) & (SEQ - 1);
        int j0 = 64 * pblk + c0;
        float4 t0 = g_tab[(srow << 9) | j0];
        float4 t1 = g_tab[(srow << 9) | (j0 + 1)];
        float x1a = sm[r * SROW + c0]      + bias[j0];
        float x1b = sm[r * SROW + c0 + 1]  + bias[j0 + 1];
        float x2a = sm[r * SROW + c0 + 64] + bias[j0 + 512];
        float x2b = sm[r * SROW + c0 + 65] + bias[j0 + 513];
        float y1a = (x1a * t0.x + x2a * t0.y) * scale;
        float y2a = (x2a * t0.z - x1a * t0.w) * scale;
        float y1b = (x1b * t1.x + x2b * t1.y) * scale;
        float y2b = (x2b * t1.z - x1b * t1.w) * scale;
        size_t gb = (size_t)(brow + r) * HID + bcol;
        *(uint32_t*)(outh + gb + c0)      = pk2h(y1a, y1b);
        *(uint32_t*)(outh + gb + 64 + c0) = pk2h(y2a, y2b);
    }
}

// ============================================================================
// output projection: out = Ctx*Wo'^T + bo (fp32).
// ============================================================================
__global__ __launch_bounds__(256)
void gemm_out(const __half* __restrict__ Actx, const __half* __restrict__ Bw,
              const float* __restrict__ bias, float* __restrict__ Y)
{
    extern __shared__ __align__(128) char smem[];

    const int tid  = threadIdx.x;
    const int wid  = tid >> 5;
    const int lane = tid & 31;
    const int wm   = wid & 1;
    const int wn   = wid >> 1;
    const int brow = blockIdx.y * 128;
    const int bcol = blockIdx.x * 128;

    const uint32_t sbase = smem_u32(smem);
    const uint32_t aoff = (uint32_t)(((lane & 7) + ((lane >> 3) & 1) * 8) * RSTRIDE
                                     + ((lane >> 4) & 1) * 16);
    const uint32_t boff = (uint32_t)(((lane & 7) + ((lane >> 4) & 1) * 8) * RSTRIDE
                                     + ((lane >> 3) & 1) * 16);

    float acc[4][4][4];
#pragma unroll
    for (int i = 0; i < 4; i++)
#pragma unroll
        for (int j = 0; j < 4; j++)
#pragma unroll
            for (int r = 0; r < 4; r++) acc[i][j][r] = 0.0f;

    gemm_mainloop(Actx + (size_t)brow * HID, Bw + (size_t)bcol * HID,
                  sbase, aoff, boff, wm, wn, tid, acc);

    const int g = lane >> 2;
    const int t2 = (lane & 3) * 2;
#pragma unroll
    for (int mf = 0; mf < 4; mf++) {
        const int row0 = brow + wm * 64 + mf * 16 + g;
#pragma unroll
        for (int nf = 0; nf < 4; nf++) {
            const int col = bcol + wn * 32 + nf * 8 + t2;
            float2 bv = *(const float2*)(bias + col);
            *(float2*)(Y + (size_t)row0 * HID + col) =
                make_float2(acc[mf][nf][0] + bv.x, acc[mf][nf][1] + bv.y);
            *(float2*)(Y + (size_t)(row0 + 8) * HID + col) =
                make_float2(acc[mf][nf][2] + bv.x, acc[mf][nf][3] + bv.y);
        }
    }
}

// ============================================================================
// tensor-core flash attention: fp16 operands, exp2-domain softmax via
// ex2.approx.f16x2; l computed by an all-ones MMA row-sum (no scalar adds,
// no final shfl reduce). 3-stage KV cp.async ring, one sync per kt.
// ============================================================================
#define AST 144
#define AQ 0
#define AKV0 (128 * AST)              // 18432
#define KVSTG (2 * 64 * AST)          // 18432 (K, V)
#define ATTN_SMEM (AKV0 + 3 * KVSTG)  // 73728
#define ONE2 0x3C003C00u              // half2(1.0, 1.0)

__device__ __forceinline__ void attn_issue_kv(
    int krow0, size_t colbase, uint32_t kvbase, int tid)
{
#pragma unroll
    for (int i = 0; i < 4; i++) {
        const __half* g = (i < 2) ? g_Kh : g_Vh;
        const int arr = i >> 1;
        const int rem = ((i & 1) << 8) + tid;
        const int row = rem >> 3;
        const int c = rem & 7;
        cp16(kvbase + arr * (64 * AST) + row * AST + c * 16,
             g + (size_t)(krow0 + row) * HID + colbase + c * 8);
    }
}

__global__ __launch_bounds__(256, 2) void attn_mma() {
    extern __shared__ __align__(128) char smem[];

    const int tid  = threadIdx.x;
    const int wid  = tid >> 5;
    const int lane = tid & 31;
    const int qt   = blockIdx.x;
    const int bh   = blockIdx.y;
    const int b    = bh >> 4;
    const int h    = bh & 15;
    const int qbase = b * SEQ + qt * 128;
    const size_t colbase = (size_t)h * HD;
    const int krow_base = b * SEQ;

    const uint32_t sb = smem_u32(smem);

    const uint32_t aoff = (uint32_t)(((lane & 7) + ((lane >> 3) & 1) * 8) * AST
                                     + ((lane >> 4) & 1) * 16);
    const uint32_t boff = (uint32_t)(((lane & 7) + ((lane >> 4) & 1) * 8) * AST
                                     + ((lane >> 3) & 1) * 16);
    const uint32_t voff = (uint32_t)(((lane & 7) + ((lane >> 3) & 1) * 8) * AST
                                     + ((lane >> 4) & 1) * 16);

#pragma unroll
    for (int i = 0; i < 4; i++) {
        const int rem = (i << 8) + tid;
        const int row = rem >> 3;
        const int c = rem & 7;
        cp16(sb + AQ + row * AST + c * 16,
             g_Qh + (size_t)(qbase + row) * HID + colbase + c * 8);
    }
    attn_issue_kv(krow_base, colbase, sb + AKV0, tid);
    CP_COMMIT();
    attn_issue_kv(krow_base + 64, colbase, sb + AKV0 + KVSTG, tid);
    CP_COMMIT();

    unsigned long long o2[8][2];
#pragma unroll
    for (int nf = 0; nf < 8; nf++) { o2[nf][0] = 0ULL; o2[nf][1] = 0ULL; }
    unsigned long long ls2[2];    // l row-sum accumulator fragment (fp32 x4)
    ls2[0] = 0ULL; ls2[1] = 0ULL;
    float m0 = -1e30f, m1 = -1e30f;

    const uint32_t qrow_off = (uint32_t)(wid * 16 * AST);

    for (int kt = 0; kt < 16; kt++) {
        CP_WAIT1();
        __syncthreads();
        if (kt + 2 < 16)
            attn_issue_kv(krow_base + (kt + 2) * 64, colbase,
                          sb + AKV0 + ((kt + 2) % 3) * KVSTG, tid);
        CP_COMMIT();

        const uint32_t kvb = sb + AKV0 + (kt % 3) * KVSTG;
        const uint32_t akh = kvb;
        const uint32_t avh = kvb + 64 * AST;

        float sfr[8][4];
#pragma unroll
        for (int nf = 0; nf < 8; nf++)
#pragma unroll
            for (int r = 0; r < 4; r++) sfr[nf][r] = 0.0f;

#pragma unroll
        for (int kq = 0; kq < 4; kq++) {
            uint32_t qh[4];
            ldm4(qh, sb + AQ + qrow_off + kq * 32 + aoff);
            uint32_t kh[4][4];
#pragma unroll
            for (int p = 0; p < 4; p++)
                ldm4(kh[p], akh + (uint32_t)(p * 16 * AST) + kq * 32 + boff);
#pragma unroll
            for (int nf = 0; nf < 8; nf++) {
                const int p = nf >> 1, q = nf & 1;
                mma16816(sfr[nf], qh, kh[p][2 * q], kh[p][2 * q + 1]);
            }
        }

        float mx0 = -1e30f, mx1 = -1e30f;
#pragma unroll
        for (int nf = 0; nf < 8; nf++) {
            mx0 = fmaxf(mx0, fmaxf(sfr[nf][0], sfr[nf][1]));
            mx1 = fmaxf(mx1, fmaxf(sfr[nf][2], sfr[nf][3]));
        }
        mx0 = fmaxf(mx0, __shfl_xor_sync(0xFFFFFFFF, mx0, 1));
        mx0 = fmaxf(mx0, __shfl_xor_sync(0xFFFFFFFF, mx0, 2));
        mx1 = fmaxf(mx1, __shfl_xor_sync(0xFFFFFFFF, mx1, 1));
        mx1 = fmaxf(mx1, __shfl_xor_sync(0xFFFFFFFF, mx1, 2));

        float mn0 = fmaxf(m0, mx0), mn1 = fmaxf(m1, mx1);
        float c0 = exp2f(m0 - mn0), c1 = exp2f(m1 - mn1);
        unsigned long long c0p, c1p;
        asm("mov.b64 %0, {%1, %1};" : "=l"(c0p) : "f"(c0));
        asm("mov.b64 %0, {%1, %1};" : "=l"(c1p) : "f"(c1));
#pragma unroll
        for (int nf = 0; nf < 8; nf++) {
            f2mul(o2[nf][0], o2[nf][0], c0p);
            f2mul(o2[nf][1], o2[nf][1], c1p);
        }
        f2mul(ls2[0], ls2[0], c0p);
        f2mul(ls2[1], ls2[1], c1p);

        // P = exp2(s - mn) via fp16x2 MUFU; result IS the PV A-fragment.
        uint32_t pex[8][2];
#pragma unroll
        for (int nf = 0; nf < 8; nf++) {
            pex[nf][0] = h2exp2(pk2h(sfr[nf][0] - mn0, sfr[nf][1] - mn0));
            pex[nf][1] = h2exp2(pk2h(sfr[nf][2] - mn1, sfr[nf][3] - mn1));
        }
        m0 = mn0; m1 = mn1;

#pragma unroll
        for (int kk = 0; kk < 4; kk++) {
            uint32_t ah[4];
            ah[0] = pex[2 * kk][0];
            ah[1] = pex[2 * kk][1];
            ah[2] = pex[2 * kk + 1][0];
            ah[3] = pex[2 * kk + 1][1];

            // l row-sum: one MMA with B = ones
            mma16816((float*)ls2, ah, ONE2, ONE2);

            uint32_t vh[4][4];
#pragma unroll
            for (int p = 0; p < 4; p++) {
                uint32_t ro = (uint32_t)(kk * 16 * AST) + (uint32_t)(p * 32);
                ldm4t(vh[p], avh + ro + voff);
            }
#pragma unroll
            for (int nf = 0; nf < 8; nf++) {
                const int p = nf >> 1, q = nf & 1;
                mma16816((float*)o2[nf], ah, vh[p][2 * q], vh[p][2 * q + 1]);
            }
        }
    }

    const float* ls = (const float*)ls2;
    float inv0 = 1.0f / ls[0], inv1 = 1.0f / ls[2];

    const int g  = lane >> 2;
    const int t2 = (lane & 3) * 2;
    const int row0 = qbase + wid * 16 + g;
#pragma unroll
    for (int nf = 0; nf < 8; nf++) {
        size_t col = colbase + nf * 8 + t2;
        const float* of = (const float*)o2[nf];
        *(uint32_t*)(g_Ctx + (size_t)row0 * HID + col) =
            pk2h(of[0] * inv0, of[1] * inv0);
        *(uint32_t*)(g_Ctx + (size_t)(row0 + 8) * HID + col) =
            pk2h(of[2] * inv1, of[3] * inv1);
    }
}

// ============================================================================
// launch
// ============================================================================
extern "C" void kernel_launch(void* const* d_in, const int* in_sizes, int n_in,
                              void* d_out, int out_size) {
    (void)in_sizes; (void)n_in; (void)out_size;
    const float* query = (const float*)d_in[0];
    const float* key   = (const float*)d_in[1];
    const float* value = (const float*)d_in[2];
    const float* Wq    = (const float*)d_in[3];
    const float* bq    = (const float*)d_in[4];
    const float* Wk    = (const float*)d_in[5];
    const float* bk    = (const float*)d_in[6];
    const float* Wv    = (const float*)d_in[7];
    const float* bv    = (const float*)d_in[8];
    const float* Wo    = (const float*)d_in[9];
    const float* bo    = (const float*)d_in[10];
    float* out = (float*)d_out;

    __half *Ctx, *Woh;
    cudaGetSymbolAddress((void**)&Ctx, g_Ctx);
    cudaGetSymbolAddress((void**)&Woh, g_Woh);

    cudaFuncSetAttribute(gemm_qkv, cudaFuncAttributeMaxDynamicSharedMemorySize, GEMM_SMEM);
    cudaFuncSetAttribute(gemm_out, cudaFuncAttributeMaxDynamicSharedMemorySize, GEMM_SMEM);
    cudaFuncSetAttribute(attn_mma, cudaFuncAttributeMaxDynamicSharedMemorySize, ATTN_SMEM);

    const int ablocks = (MROWS * HID / 8) / 256;    // 4096

    make_invf_kernel<<<1, 512>>>();
    rope_table_kernel<<<(SEQ * 512) / 256, 256>>>();

    prep_all<<<dim3(ablocks, 4), 256>>>(query, key, value, Wq, Wk, Wv, Wo);

    gemm_qkv<<<dim3(HID / 128, MROWS / 128, 3), 256, GEMM_SMEM>>>(bq, bk, bv);

    attn_mma<<<dim3(8, 128), 256, ATTN_SMEM>>>();

    gemm_out<<<dim3(HID / 128, MROWS / 128), 256, GEMM_SMEM>>>(Ctx, Woh, bo, out);
}